// round 6
// baseline (speedup 1.0000x reference)
#include <cuda_runtime.h>
#include <cuda_bf16.h>
#include <cstdint>
#include <cstddef>

// Problem constants
#define BB 2
#define TT 2048
#define DD 2048
#define HQ 16
#define HKV 8
#define HD 128
#define MROWS (BB*TT)   // 4096

typedef __nv_bfloat16 bf16;

// log2(e)/sqrt(128)
#define QSCALE 0.12752551164384637f
// cross-term descale: 1/2^22
#define XSCALE 2.38418579101562e-7f

// quantization scales
#define SA_FULL 16.0f        // activations (x, ctx)
#define SA_LO   4096.0f      // activation lo residual
#define SB_FULL 1024.0f      // weights
#define SB_LO   262144.0f    // weight lo residual

// ---------------- scratch (static device globals) ---------------------------
__device__ float g_Qraw[(size_t)MROWS * (HQ*HD)];
__device__ float g_Kraw[(size_t)MROWS * (HKV*HD)];
__device__ float g_Vraw[(size_t)MROWS * (HKV*HD)];

__device__ bf16   g_xh [(size_t)MROWS*DD];
__device__ int8_t g_x8 [(size_t)MROWS*DD],  g_x8l [(size_t)MROWS*DD];
__device__ bf16   g_Wqh[(size_t)HQ*HD*DD];
__device__ int8_t g_Wq8[(size_t)HQ*HD*DD], g_Wq8l[(size_t)HQ*HD*DD];
__device__ bf16   g_Wkh[(size_t)HKV*HD*DD];
__device__ int8_t g_Wk8[(size_t)HKV*HD*DD], g_Wk8l[(size_t)HKV*HD*DD];
__device__ bf16   g_Wvh[(size_t)HKV*HD*DD];
__device__ int8_t g_Wv8[(size_t)HKV*HD*DD], g_Wv8l[(size_t)HKV*HD*DD];
__device__ bf16   g_Woh[(size_t)DD*HQ*HD];
__device__ int8_t g_Wo8[(size_t)DD*HQ*HD], g_Wo8l[(size_t)DD*HQ*HD];

__device__ bf16 g_Qh [(size_t)BB*HQ*TT*HD],  g_Ql [(size_t)BB*HQ*TT*HD];
__device__ bf16 g_Kh [(size_t)BB*HKV*TT*HD], g_Kl [(size_t)BB*HKV*TT*HD];
__device__ bf16 g_Vh [(size_t)MROWS*HKV*HD], g_Vl [(size_t)MROWS*HKV*HD];
__device__ bf16   g_ctxh[(size_t)MROWS*HQ*HD];
__device__ int8_t g_ctx8[(size_t)MROWS*HQ*HD], g_ctx8l[(size_t)MROWS*HQ*HD];

// ---------------- PTX helpers ------------------------------------------------
__device__ __forceinline__ void ldsm4(uint32_t* r, uint32_t a) {
    asm volatile("ldmatrix.sync.aligned.m8n8.x4.shared.b16 {%0,%1,%2,%3}, [%4];\n"
        : "=r"(r[0]), "=r"(r[1]), "=r"(r[2]), "=r"(r[3]) : "r"(a));
}
__device__ __forceinline__ void ldsm4t(uint32_t* r, uint32_t a) {
    asm volatile("ldmatrix.sync.aligned.m8n8.x4.trans.shared.b16 {%0,%1,%2,%3}, [%4];\n"
        : "=r"(r[0]), "=r"(r[1]), "=r"(r[2]), "=r"(r[3]) : "r"(a));
}
__device__ __forceinline__ void mma16816(float* c, const uint32_t* a, const uint32_t* b) {
    asm volatile("mma.sync.aligned.m16n8k16.row.col.f32.bf16.bf16.f32 "
        "{%0,%1,%2,%3}, {%4,%5,%6,%7}, {%8,%9}, {%0,%1,%2,%3};\n"
        : "+f"(c[0]), "+f"(c[1]), "+f"(c[2]), "+f"(c[3])
        : "r"(a[0]), "r"(a[1]), "r"(a[2]), "r"(a[3]), "r"(b[0]), "r"(b[1]));
}
__device__ __forceinline__ void mma_s8(int* c, const uint32_t* a, const uint32_t* b) {
    asm volatile("mma.sync.aligned.m16n8k32.row.col.s32.s8.s8.s32 "
        "{%0,%1,%2,%3}, {%4,%5,%6,%7}, {%8,%9}, {%0,%1,%2,%3};\n"
        : "+r"(c[0]), "+r"(c[1]), "+r"(c[2]), "+r"(c[3])
        : "r"(a[0]), "r"(a[1]), "r"(a[2]), "r"(a[3]), "r"(b[0]), "r"(b[1]));
}
__device__ __forceinline__ void cp_async16(uint32_t dst, const void* src) {
    asm volatile("cp.async.ca.shared.global [%0], [%1], 16;\n" :: "r"(dst), "l"(src));
}
__device__ __forceinline__ void cp_commit() {
    asm volatile("cp.async.commit_group;\n" ::: "memory");
}
__device__ __forceinline__ uint32_t packbf(float a, float b) {
    __nv_bfloat162 t = __floats2bfloat162_rn(a, b);
    return *(uint32_t*)&t;
}
__device__ __forceinline__ void split2(float a, float b, uint32_t& h, uint32_t& l) {
    bf16 ha = __float2bfloat16(a), hb = __float2bfloat16(b);
    h = ((uint32_t)__bfloat16_as_ushort(hb) << 16) | (uint32_t)__bfloat16_as_ushort(ha);
    l = packbf(a - __bfloat162float(ha), b - __bfloat162float(hb));
}
__device__ __forceinline__ int q8(float v, float s) {
    int x = __float2int_rn(v * s);
    return max(-127, min(127, x));
}

// ---------------- fp32 -> (bf16 hi, s8 full, s8 lo) 3-plane split -----------
__global__ __launch_bounds__(256) void split3_kernel(
    const float4* __restrict__ in, bf16* __restrict__ hi,
    int8_t* __restrict__ q, int8_t* __restrict__ ql,
    int n4, float sfull, float slo)
{
    int i = blockIdx.x * 256 + threadIdx.x;
    if (i >= n4) return;
    float4 v = in[i];
    bf16 h0 = __float2bfloat16(v.x), h1 = __float2bfloat16(v.y);
    bf16 h2 = __float2bfloat16(v.z), h3 = __float2bfloat16(v.w);
    float l0 = v.x - __bfloat162float(h0), l1 = v.y - __bfloat162float(h1);
    float l2 = v.z - __bfloat162float(h2), l3 = v.w - __bfloat162float(h3);
    uint2* H = (uint2*)(hi + (size_t)i*4);
    *H = make_uint2(
        ((uint32_t)__bfloat16_as_ushort(h1) << 16) | (uint32_t)__bfloat16_as_ushort(h0),
        ((uint32_t)__bfloat16_as_ushort(h3) << 16) | (uint32_t)__bfloat16_as_ushort(h2));
    uint32_t qa = (uint32_t)(q8(v.x,sfull)&255) | ((uint32_t)(q8(v.y,sfull)&255)<<8)
                | ((uint32_t)(q8(v.z,sfull)&255)<<16) | ((uint32_t)(q8(v.w,sfull)&255)<<24);
    uint32_t qb = (uint32_t)(q8(l0,slo)&255) | ((uint32_t)(q8(l1,slo)&255)<<8)
                | ((uint32_t)(q8(l2,slo)&255)<<16) | ((uint32_t)(q8(l3,slo)&255)<<24);
    *(uint32_t*)(q  + (size_t)i*4) = qa;
    *(uint32_t*)(ql + (size_t)i*4) = qb;
}

// ---------------- plain fp32 -> bf16 hi/lo split (for V) --------------------
__global__ __launch_bounds__(256) void split_kernel(
    const float4* __restrict__ in, bf16* __restrict__ hi, bf16* __restrict__ lo, int n4)
{
    int i = blockIdx.x * 256 + threadIdx.x;
    if (i >= n4) return;
    float4 v = in[i];
    uint32_t h0, l0, h1, l1;
    split2(v.x, v.y, h0, l0);
    split2(v.z, v.w, h1, l1);
    *(uint2*)(hi + (size_t)i*4) = make_uint2(h0, h1);
    *(uint2*)(lo + (size_t)i*4) = make_uint2(l0, l1);
}

// ---------------- hybrid GEMM: C[M,N] = A[M,K]*B[N,K]^T ---------------------
// main term bf16 (Ah*Bh), cross terms int8 (qAl*qB + qA*qBl) scaled 2^-22.
// 128x128 CTA tile, BK=32, 256 threads (8 warps, 32x64 warp tiles),
// cp.async double-buffered.
#define OFF_AH  0u
#define OFF_A8  10240u
#define OFF_A8L 16384u
#define OFF_BH  22528u
#define OFF_B8  32768u
#define OFF_B8L 38912u
#define GSTAGE  45056u
#define GEMM_SMEM (2*GSTAGE)

__global__ __launch_bounds__(256) void gemm_hyb(
    const bf16* __restrict__ Ah, const int8_t* __restrict__ A8, const int8_t* __restrict__ A8l,
    const bf16* __restrict__ Bh, const int8_t* __restrict__ B8, const int8_t* __restrict__ B8l,
    float* __restrict__ C, int M, int N, int K)
{
    extern __shared__ char smc[];
    const uint32_t sb = (uint32_t)__cvta_generic_to_shared(smc);
    const int tid = threadIdx.x, lane = tid & 31, wid = tid >> 5;
    const int row0 = blockIdx.y * 128, col0 = blockIdx.x * 128;

    const int wm = (wid >> 1) * 32;
    const int wn = (wid & 1) * 64;

    const int r   = lane & 7, blk = lane >> 3;
    const int a_row = ((blk & 1) << 3) + r;
    const int a_col = (blk >> 1) << 3;          // b16 units
    const int b_row = ((blk >> 1) << 3) + r;
    const int b_col = (blk & 1) << 3;

    // load coords
    const int lrow = tid >> 1;          // 0..127
    const int lc   = tid & 1;           // chunk half

    float accm[2][8][4];
    int   accx[2][8][4];
#pragma unroll
    for (int i = 0; i < 2; i++)
#pragma unroll
        for (int j = 0; j < 8; j++)
#pragma unroll
            for (int k = 0; k < 4; k++) { accm[i][j][k] = 0.f; accx[i][j][k] = 0; }

    const int niter = K / 32;

#define GISSUE(it, stg) do {                                                       \
    const int k0_ = (it) * 32;                                                     \
    const uint32_t st_ = sb + (uint32_t)(stg)*GSTAGE;                              \
    /* Ah: 2 chunks */                                                             \
    cp_async16(st_ + OFF_AH + lrow*80u + (uint32_t)lc*32u,                         \
               Ah + (size_t)(row0+lrow)*K + k0_ + lc*16);                          \
    cp_async16(st_ + OFF_AH + lrow*80u + (uint32_t)lc*32u + 16u,                   \
               Ah + (size_t)(row0+lrow)*K + k0_ + lc*16 + 8);                      \
    /* Bh: 2 chunks */                                                             \
    cp_async16(st_ + OFF_BH + lrow*80u + (uint32_t)lc*32u,                         \
               Bh + (size_t)(col0+lrow)*K + k0_ + lc*16);                          \
    cp_async16(st_ + OFF_BH + lrow*80u + (uint32_t)lc*32u + 16u,                   \
               Bh + (size_t)(col0+lrow)*K + k0_ + lc*16 + 8);                      \
    /* s8 planes: 1 chunk each */                                                  \
    cp_async16(st_ + OFF_A8  + lrow*48u + (uint32_t)lc*16u,                        \
               A8  + (size_t)(row0+lrow)*K + k0_ + lc*16);                         \
    cp_async16(st_ + OFF_A8L + lrow*48u + (uint32_t)lc*16u,                        \
               A8l + (size_t)(row0+lrow)*K + k0_ + lc*16);                         \
    cp_async16(st_ + OFF_B8  + lrow*48u + (uint32_t)lc*16u,                        \
               B8  + (size_t)(col0+lrow)*K + k0_ + lc*16);                         \
    cp_async16(st_ + OFF_B8L + lrow*48u + (uint32_t)lc*16u,                        \
               B8l + (size_t)(col0+lrow)*K + k0_ + lc*16);                         \
} while (0)

    GISSUE(0, 0);
    cp_commit();

    for (int it = 0; it < niter; it++) {
        if (it + 1 < niter) {
            GISSUE(it + 1, (it + 1) & 1);
            cp_commit();
            asm volatile("cp.async.wait_group 1;\n" ::: "memory");
        } else {
            asm volatile("cp.async.wait_group 0;\n" ::: "memory");
        }
        __syncthreads();

        const uint32_t st = sb + (uint32_t)(it & 1)*GSTAGE;

        // ---- main bf16 term ----
#pragma unroll
        for (int ks = 0; ks < 2; ks++) {
            uint32_t ah[2][4], bh[4][4];
#pragma unroll
            for (int mt = 0; mt < 2; mt++)
                ldsm4(ah[mt], st + OFF_AH + (uint32_t)((wm + mt*16 + a_row)*80 + (ks*16 + a_col)*2));
#pragma unroll
            for (int p = 0; p < 4; p++)
                ldsm4(bh[p], st + OFF_BH + (uint32_t)((wn + p*16 + b_row)*80 + (ks*16 + b_col)*2));
#pragma unroll
            for (int mt = 0; mt < 2; mt++)
#pragma unroll
                for (int p = 0; p < 4; p++) {
                    mma16816(accm[mt][2*p],   ah[mt], &bh[p][0]);
                    mma16816(accm[mt][2*p+1], ah[mt], &bh[p][2]);
                }
        }

        // ---- cross int8 terms (k32) ----
        {
            uint32_t a8[2][4], a8l[2][4], b8[4][4], b8l[4][4];
#pragma unroll
            for (int mt = 0; mt < 2; mt++) {
                uint32_t base = st + (uint32_t)((wm + mt*16 + a_row)*48 + a_col*2);
                ldsm4(a8[mt],  base + OFF_A8);
                ldsm4(a8l[mt], base + OFF_A8L);
            }
#pragma unroll
            for (int p = 0; p < 4; p++) {
                uint32_t base = st + (uint32_t)((wn + p*16 + b_row)*48 + b_col*2);
                ldsm4(b8[p],  base + OFF_B8);
                ldsm4(b8l[p], base + OFF_B8L);
            }
#pragma unroll
            for (int mt = 0; mt < 2; mt++)
#pragma unroll
                for (int p = 0; p < 4; p++) {
                    mma_s8(accx[mt][2*p],   a8l[mt], &b8[p][0]);
                    mma_s8(accx[mt][2*p+1], a8l[mt], &b8[p][2]);
                    mma_s8(accx[mt][2*p],   a8[mt],  &b8l[p][0]);
                    mma_s8(accx[mt][2*p+1], a8[mt],  &b8l[p][2]);
                }
        }
        __syncthreads();
    }
#undef GISSUE

    const int gr = lane >> 2, gc = (lane & 3) * 2;
#pragma unroll
    for (int mt = 0; mt < 2; mt++)
#pragma unroll
        for (int nt = 0; nt < 8; nt++) {
            int row = row0 + wm + mt*16 + gr;
            int col = col0 + wn + nt*8 + gc;
            float2 v0 = make_float2(accm[mt][nt][0] + (float)accx[mt][nt][0]*XSCALE,
                                    accm[mt][nt][1] + (float)accx[mt][nt][1]*XSCALE);
            float2 v1 = make_float2(accm[mt][nt][2] + (float)accx[mt][nt][2]*XSCALE,
                                    accm[mt][nt][3] + (float)accx[mt][nt][3]*XSCALE);
            *(float2*)&C[(size_t)row*N + col]       = v0;
            *(float2*)&C[(size_t)(row+8)*N + col]   = v1;
        }
}

// ---------------- RMSNorm + RoPE -> bf16 hi/lo in [B,H,T,HD] ----------------
__global__ __launch_bounds__(128) void norm_rope_split_kernel(
    const float* __restrict__ raw, bf16* __restrict__ outh, bf16* __restrict__ outl,
    const float* __restrict__ scale,
    const float* __restrict__ cosT, const float* __restrict__ sinT,
    int H, float scale_mul)
{
    const int blk = blockIdx.x;
    const int h  = blk % H;
    const int bt = blk / H;
    const int t  = bt & (TT-1);
    const int b  = bt >> 11;
    const int d  = threadIdx.x;

    __shared__ float red[HD];
    float v = raw[(size_t)bt * (H*HD) + h*HD + d];
    red[d] = v*v;
    __syncthreads();
#pragma unroll
    for (int s = 64; s > 0; s >>= 1) {
        if (d < s) red[d] += red[d+s];
        __syncthreads();
    }
    float inv = rsqrtf(red[0]*(1.0f/HD) + 1e-6f);
    __syncthreads();
    float xn = v * inv * scale[d];
    red[d] = xn;
    __syncthreads();
    float rot = (d < 64) ? -red[d+64] : red[d-64];
    float o = (xn * cosT[t*HD + d] + rot * sinT[t*HD + d]) * scale_mul;
    size_t off = (((size_t)(b*H + h))*TT + t)*HD + d;
    bf16 hi = __float2bfloat16(o);
    outh[off] = hi;
    outl[off] = __float2bfloat16(o - __bfloat162float(hi));
}

// ---------------- fused flash attention (bf16x3 QK^T and PV) ----------------
#define BQ 128
#define BK 64
#define FP 136
#define QELE (BQ*FP)
#define KELE (BK*FP)
#define QAREA (2*QELE)
#define STGKV (4*KELE)
#define FLASH_SMEM ((QAREA + 2*STGKV) * 2)

__global__ __launch_bounds__(256) void flash_kernel(
    const bf16* __restrict__ Qh, const bf16* __restrict__ Ql,
    const bf16* __restrict__ Kh, const bf16* __restrict__ Kl,
    const bf16* __restrict__ Vh, const bf16* __restrict__ Vl,
    bf16* __restrict__ ctxh, int8_t* __restrict__ ctx8, int8_t* __restrict__ ctx8l)
{
    extern __shared__ bf16 sm[];
    const int tid = threadIdx.x, lane = tid & 31, wid = tid >> 5;
    const int qb = gridDim.x - 1 - blockIdx.x;
    const int bh = blockIdx.y;
    const int b = bh >> 4, h = bh & 15, kv = h >> 1;
    const int q0 = qb * BQ;
    const uint32_t sbase = (uint32_t)__cvta_generic_to_shared(sm);

    const bf16* Qhg = Qh + ((size_t)(b*HQ  + h )*TT + q0)*HD;
    const bf16* Qlg = Ql + ((size_t)(b*HQ  + h )*TT + q0)*HD;
    const bf16* Khg = Kh + ((size_t)(b*HKV + kv)*TT)*HD;
    const bf16* Klg = Kl + ((size_t)(b*HKV + kv)*TT)*HD;
    const bf16* Vhg = Vh + (size_t)b*TT*(HKV*HD) + kv*HD;
    const bf16* Vlg = Vl + (size_t)b*TT*(HKV*HD) + kv*HD;

#pragma unroll
    for (int i = 0; i < 8; i++) {
        int c = tid + i*256;
        int row = c >> 4, col = (c & 15) * 8;
        cp_async16(sbase + (uint32_t)((row*FP + col) * 2),        Qhg + (size_t)row*HD + col);
        cp_async16(sbase + (uint32_t)((QELE + row*FP + col) * 2), Qlg + (size_t)row*HD + col);
    }

#define ISSUEKV(kt, stage) do {                                                     \
    const int k0_ = (kt) * BK;                                                      \
    const uint32_t kb_ = sbase + (uint32_t)((QAREA + (stage)*STGKV) * 2);           \
    _Pragma("unroll")                                                               \
    for (int i_ = 0; i_ < 4; i_++) {                                                \
        int c_ = tid + i_*256;                                                      \
        int row_ = c_ >> 4, col_ = (c_ & 15) * 8;                                   \
        uint32_t so_ = (uint32_t)((row_*FP + col_) * 2);                            \
        cp_async16(kb_ + so_,              Khg + (size_t)(k0_+row_)*HD + col_);     \
        cp_async16(kb_ + KELE*2 + so_,     Klg + (size_t)(k0_+row_)*HD + col_);     \
        cp_async16(kb_ + 2*KELE*2 + so_,   Vhg + (size_t)(k0_+row_)*(HKV*HD) + col_); \
        cp_async16(kb_ + 3*KELE*2 + so_,   Vlg + (size_t)(k0_+row_)*(HKV*HD) + col_); \
    }                                                                               \
} while (0)

    ISSUEKV(0, 0);
    cp_commit();

    const int r   = lane & 7, blkid = lane >> 3;
    const int a_row = ((blkid & 1) << 3) + r;
    const int a_col = (blkid >> 1) << 3;
    const int b_row = ((blkid >> 1) << 3) + r;
    const int b_col = (blkid & 1) << 3;
    const int gr = lane >> 2;

    float oacc[16][4];
#pragma unroll
    for (int i = 0; i < 16; i++)
#pragma unroll
        for (int j = 0; j < 4; j++) oacc[i][j] = 0.f;
    float m0 = -1e30f, m1 = -1e30f, l0 = 0.f, l1 = 0.f;

    const int row0g = q0 + wid*16 + gr;
    const int row1g = row0g + 8;
    const int nkt = 2*qb + 2;

    for (int kt = 0; kt < nkt; kt++) {
        if (kt + 1 < nkt) {
            ISSUEKV(kt + 1, (kt + 1) & 1);
            cp_commit();
            asm volatile("cp.async.wait_group 1;\n" ::: "memory");
        } else {
            asm volatile("cp.async.wait_group 0;\n" ::: "memory");
        }
        __syncthreads();

        const int k0 = kt * BK;
        const uint32_t kb_s = sbase + (uint32_t)((QAREA + (kt & 1)*STGKV) * 2);

        float sacc[8][4];
#pragma unroll
        for (int i = 0; i < 8; i++)
#pragma unroll
            for (int j = 0; j < 4; j++) sacc[i][j] = 0.f;

#pragma unroll
        for (int ks = 0; ks < 8; ks++) {
            uint32_t qa = sbase + (uint32_t)(((wid*16 + a_row)*FP + ks*16 + a_col) * 2);
            uint32_t qh[4], ql[4];
            ldsm4(qh, qa);
            ldsm4(ql, qa + QELE*2);
#pragma unroll
            for (int np = 0; np < 4; np++) {
                uint32_t ka = kb_s + (uint32_t)(((np*16 + b_row)*FP + ks*16 + b_col) * 2);
                uint32_t kh[4], kl[4];
                ldsm4(kh, ka);
                ldsm4(kl, ka + KELE*2);
                mma16816(sacc[2*np],   qh, &kh[0]);
                mma16816(sacc[2*np+1], qh, &kh[2]);
                mma16816(sacc[2*np],   qh, &kl[0]);
                mma16816(sacc[2*np+1], qh, &kl[2]);
                mma16816(sacc[2*np],   ql, &kh[0]);
                mma16816(sacc[2*np+1], ql, &kh[2]);
            }
        }

        float mx0 = -1e30f, mx1 = -1e30f;
#pragma unroll
        for (int nt = 0; nt < 8; nt++) {
            int cg = k0 + nt*8 + (lane & 3)*2;
            if (cg     > row0g) sacc[nt][0] = -1e30f;
            if (cg + 1 > row0g) sacc[nt][1] = -1e30f;
            if (cg     > row1g) sacc[nt][2] = -1e30f;
            if (cg + 1 > row1g) sacc[nt][3] = -1e30f;
            mx0 = fmaxf(mx0, fmaxf(sacc[nt][0], sacc[nt][1]));
            mx1 = fmaxf(mx1, fmaxf(sacc[nt][2], sacc[nt][3]));
        }
        mx0 = fmaxf(mx0, __shfl_xor_sync(0xffffffffu, mx0, 1));
        mx0 = fmaxf(mx0, __shfl_xor_sync(0xffffffffu, mx0, 2));
        mx1 = fmaxf(mx1, __shfl_xor_sync(0xffffffffu, mx1, 1));
        mx1 = fmaxf(mx1, __shfl_xor_sync(0xffffffffu, mx1, 2));

        float mn0 = fmaxf(m0, mx0), mn1 = fmaxf(m1, mx1);
        float sc0 = exp2f(m0 - mn0), sc1 = exp2f(m1 - mn1);
        m0 = mn0; m1 = mn1;

        float s0 = 0.f, s1 = 0.f;
#pragma unroll
        for (int nt = 0; nt < 8; nt++) {
            sacc[nt][0] = exp2f(sacc[nt][0] - m0);
            sacc[nt][1] = exp2f(sacc[nt][1] - m0);
            sacc[nt][2] = exp2f(sacc[nt][2] - m1);
            sacc[nt][3] = exp2f(sacc[nt][3] - m1);
            s0 += sacc[nt][0] + sacc[nt][1];
            s1 += sacc[nt][2] + sacc[nt][3];
        }
        s0 += __shfl_xor_sync(0xffffffffu, s0, 1);
        s0 += __shfl_xor_sync(0xffffffffu, s0, 2);
        s1 += __shfl_xor_sync(0xffffffffu, s1, 1);
        s1 += __shfl_xor_sync(0xffffffffu, s1, 2);
        l0 = l0*sc0 + s0;
        l1 = l1*sc1 + s1;

#pragma unroll
        for (int i = 0; i < 16; i++) {
            oacc[i][0] *= sc0; oacc[i][1] *= sc0;
            oacc[i][2] *= sc1; oacc[i][3] *= sc1;
        }

        const int vrow = (lane & 7) + ((lane >> 3) & 1)*8;
        const int vcolb = ((lane >> 4) << 3);
#pragma unroll
        for (int kp = 0; kp < 4; kp++) {
            uint32_t ph[4], pl[4];
#pragma unroll
            for (int half = 0; half < 2; half++) {
                float e0 = sacc[2*kp+half][0], e1 = sacc[2*kp+half][1];
                float e2 = sacc[2*kp+half][2], e3 = sacc[2*kp+half][3];
                bf16 b0 = __float2bfloat16(e0), b1 = __float2bfloat16(e1);
                bf16 b2 = __float2bfloat16(e2), b3 = __float2bfloat16(e3);
                ph[2*half]   = packbf(e0, e1);
                ph[2*half+1] = packbf(e2, e3);
                pl[2*half]   = packbf(e0 - __bfloat162float(b0), e1 - __bfloat162float(b1));
                pl[2*half+1] = packbf(e2 - __bfloat162float(b2), e3 - __bfloat162float(b3));
            }
#pragma unroll
            for (int np = 0; np < 8; np++) {
                uint32_t va = kb_s + (uint32_t)((2*KELE + (kp*16 + vrow)*FP + np*16 + vcolb) * 2);
                uint32_t vh[4], vl[4];
                ldsm4t(vh, va);
                ldsm4t(vl, va + KELE*2);
                mma16816(oacc[2*np],   ph, &vh[0]);
                mma16816(oacc[2*np+1], ph, &vh[2]);
                mma16816(oacc[2*np],   ph, &vl[0]);
                mma16816(oacc[2*np+1], ph, &vl[2]);
                mma16816(oacc[2*np],   pl, &vh[0]);
                mma16816(oacc[2*np+1], pl, &vh[2]);
            }
        }
        __syncthreads();
    }
#undef ISSUEKV

    // ---- epilogue: O /= l, write ctx hi (bf16) + s8 planes ----
    const float il0 = 1.f / l0, il1 = 1.f / l1;
    const size_t tok0 = (size_t)(b*TT + q0 + wid*16 + gr);
#pragma unroll
    for (int nt = 0; nt < 16; nt++) {
        int col = h*HD + nt*8 + (lane & 3)*2;
        float v0 = oacc[nt][0]*il0, v1 = oacc[nt][1]*il0;
        float v2 = oacc[nt][2]*il1, v3 = oacc[nt][3]*il1;
        bf16 h0 = __float2bfloat16(v0), h1 = __float2bfloat16(v1);
        bf16 h2 = __float2bfloat16(v2), h3 = __float2bfloat16(v3);
        float e0 = v0 - __bfloat162float(h0), e1 = v1 - __bfloat162float(h1);
        float e2 = v2 - __bfloat162float(h2), e3 = v3 - __bfloat162float(h3);
        *(uint32_t*)&ctxh[tok0*(HQ*HD) + col] =
            ((uint32_t)__bfloat16_as_ushort(h1) << 16) | (uint32_t)__bfloat16_as_ushort(h0);
        *(uint32_t*)&ctxh[(tok0+8)*(HQ*HD) + col] =
            ((uint32_t)__bfloat16_as_ushort(h3) << 16) | (uint32_t)__bfloat16_as_ushort(h2);
        *(uint16_t*)&ctx8 [tok0*(HQ*HD) + col]     = (uint16_t)((q8(v0,SA_FULL)&255) | ((q8(v1,SA_FULL)&255)<<8));
        *(uint16_t*)&ctx8 [(tok0+8)*(HQ*HD) + col] = (uint16_t)((q8(v2,SA_FULL)&255) | ((q8(v3,SA_FULL)&255)<<8));
        *(uint16_t*)&ctx8l[tok0*(HQ*HD) + col]     = (uint16_t)((q8(e0,SA_LO)&255)   | ((q8(e1,SA_LO)&255)<<8));
        *(uint16_t*)&ctx8l[(tok0+8)*(HQ*HD) + col] = (uint16_t)((q8(e2,SA_LO)&255)   | ((q8(e3,SA_LO)&255)<<8));
    }
}

// ---------------- launch ------------------------------------------------------
extern "C" void kernel_launch(void* const* d_in, const int* in_sizes, int n_in,
                              void* d_out, int out_size)
{
    const float* x       = (const float*)d_in[0];
    const float* cosT    = (const float*)d_in[2];
    const float* sinT    = (const float*)d_in[3];
    const float* Wq      = (const float*)d_in[4];
    const float* Wk      = (const float*)d_in[5];
    const float* Wv      = (const float*)d_in[6];
    const float* Wo      = (const float*)d_in[7];
    const float* q_scale = (const float*)d_in[8];
    const float* k_scale = (const float*)d_in[9];
    float* out = (float*)d_out;

    float *Qraw, *Kraw, *Vraw;
    bf16 *xh,*Wqh,*Wkh,*Wvh,*Woh;
    int8_t *x8,*x8l,*Wq8,*Wq8l,*Wk8,*Wk8l,*Wv8,*Wv8l,*Wo8,*Wo8l;
    bf16 *Qh,*Ql,*Kh,*Kl,*Vh,*Vl,*ctxh;
    int8_t *ctx8,*ctx8l;
    cudaGetSymbolAddress((void**)&Qraw, g_Qraw);
    cudaGetSymbolAddress((void**)&Kraw, g_Kraw);
    cudaGetSymbolAddress((void**)&Vraw, g_Vraw);
    cudaGetSymbolAddress((void**)&xh,   g_xh);
    cudaGetSymbolAddress((void**)&x8,   g_x8);   cudaGetSymbolAddress((void**)&x8l,  g_x8l);
    cudaGetSymbolAddress((void**)&Wqh,  g_Wqh);
    cudaGetSymbolAddress((void**)&Wq8,  g_Wq8);  cudaGetSymbolAddress((void**)&Wq8l, g_Wq8l);
    cudaGetSymbolAddress((void**)&Wkh,  g_Wkh);
    cudaGetSymbolAddress((void**)&Wk8,  g_Wk8);  cudaGetSymbolAddress((void**)&Wk8l, g_Wk8l);
    cudaGetSymbolAddress((void**)&Wvh,  g_Wvh);
    cudaGetSymbolAddress((void**)&Wv8,  g_Wv8);  cudaGetSymbolAddress((void**)&Wv8l, g_Wv8l);
    cudaGetSymbolAddress((void**)&Woh,  g_Woh);
    cudaGetSymbolAddress((void**)&Wo8,  g_Wo8);  cudaGetSymbolAddress((void**)&Wo8l, g_Wo8l);
    cudaGetSymbolAddress((void**)&Qh,   g_Qh);   cudaGetSymbolAddress((void**)&Ql,   g_Ql);
    cudaGetSymbolAddress((void**)&Kh,   g_Kh);   cudaGetSymbolAddress((void**)&Kl,   g_Kl);
    cudaGetSymbolAddress((void**)&Vh,   g_Vh);   cudaGetSymbolAddress((void**)&Vl,   g_Vl);
    cudaGetSymbolAddress((void**)&ctxh, g_ctxh);
    cudaGetSymbolAddress((void**)&ctx8, g_ctx8); cudaGetSymbolAddress((void**)&ctx8l, g_ctx8l);

    static bool attr_set = false;
    if (!attr_set) {
        cudaFuncSetAttribute(gemm_hyb,     cudaFuncAttributeMaxDynamicSharedMemorySize, GEMM_SMEM);
        cudaFuncSetAttribute(flash_kernel, cudaFuncAttributeMaxDynamicSharedMemorySize, FLASH_SMEM);
        attr_set = true;
    }

    // 0: 3-plane splits for GEMM operands
    split3_kernel<<<(MROWS*DD/4 + 255)/256, 256>>>((const float4*)x,  xh,  x8,  x8l,  MROWS*DD/4, SA_FULL, SA_LO);
    split3_kernel<<<(HQ*HD*DD/4 + 255)/256, 256>>>((const float4*)Wq, Wqh, Wq8, Wq8l, HQ*HD*DD/4, SB_FULL, SB_LO);
    split3_kernel<<<(HKV*HD*DD/4 + 255)/256, 256>>>((const float4*)Wk, Wkh, Wk8, Wk8l, HKV*HD*DD/4, SB_FULL, SB_LO);
    split3_kernel<<<(HKV*HD*DD/4 + 255)/256, 256>>>((const float4*)Wv, Wvh, Wv8, Wv8l, HKV*HD*DD/4, SB_FULL, SB_LO);
    split3_kernel<<<(DD*HQ*HD/4 + 255)/256, 256>>>((const float4*)Wo, Woh, Wo8, Wo8l, DD*HQ*HD/4, SB_FULL, SB_LO);

    // 1-3: QKV projections (hybrid bf16+int8 tensor cores)
    gemm_hyb<<<dim3((HQ*HD)/128,  MROWS/128), 256, GEMM_SMEM>>>(xh, x8, x8l, Wqh, Wq8, Wq8l, Qraw, MROWS, HQ*HD,  DD);
    gemm_hyb<<<dim3((HKV*HD)/128, MROWS/128), 256, GEMM_SMEM>>>(xh, x8, x8l, Wkh, Wk8, Wk8l, Kraw, MROWS, HKV*HD, DD);
    gemm_hyb<<<dim3((HKV*HD)/128, MROWS/128), 256, GEMM_SMEM>>>(xh, x8, x8l, Wvh, Wv8, Wv8l, Vraw, MROWS, HKV*HD, DD);

    // 4-6: norm+rope -> bf16 hi/lo; V split for flash
    norm_rope_split_kernel<<<MROWS*HQ,  128>>>(Qraw, Qh, Ql, q_scale, cosT, sinT, HQ,  QSCALE);
    norm_rope_split_kernel<<<MROWS*HKV, 128>>>(Kraw, Kh, Kl, k_scale, cosT, sinT, HKV, 1.0f);
    split_kernel<<<(MROWS*HKV*HD/4 + 255)/256, 256>>>((const float4*)Vraw, Vh, Vl, MROWS*HKV*HD/4);

    // 7: fused flash attention (emits ctx 3 planes)
    flash_kernel<<<dim3(TT/BQ, BB*HQ), 256, FLASH_SMEM>>>(Qh, Ql, Kh, Kl, Vh, Vl, ctxh, ctx8, ctx8l);

    // 8: output projection (hybrid)
    gemm_hyb<<<dim3(DD/128, MROWS/128), 256, GEMM_SMEM>>>(ctxh, ctx8, ctx8l, Woh, Wo8, Wo8l, out, MROWS, DD, DD);
}

// round 7
// speedup vs baseline: 2.2134x; 2.2134x over previous
#include <cuda_runtime.h>
#include <cuda_bf16.h>
#include <cstdint>
#include <cstddef>

// Problem constants
#define BB 2
#define TT 2048
#define DD 2048
#define HQ 16
#define HKV 8
#define HD 128
#define MROWS (BB*TT)   // 4096

typedef __nv_bfloat16 bf16;

// log2(e)/sqrt(128)
#define QSCALE 0.12752551164384637f

// ---------------- scratch (static device globals) ---------------------------
__device__ bf16 g_xh [(size_t)MROWS*DD],    g_xl [(size_t)MROWS*DD];
__device__ bf16 g_Wqh[(size_t)HQ*HD*DD],    g_Wql[(size_t)HQ*HD*DD];
__device__ bf16 g_Wkh[(size_t)HKV*HD*DD],   g_Wkl[(size_t)HKV*HD*DD];
__device__ bf16 g_Wvh[(size_t)HKV*HD*DD],   g_Wvl[(size_t)HKV*HD*DD];
__device__ bf16 g_Woh[(size_t)DD*HQ*HD],    g_Wol[(size_t)DD*HQ*HD];
__device__ bf16 g_Qh [(size_t)BB*HQ*TT*HD],  g_Ql [(size_t)BB*HQ*TT*HD];
__device__ bf16 g_Kh [(size_t)BB*HKV*TT*HD], g_Kl [(size_t)BB*HKV*TT*HD];
__device__ bf16 g_Vh [(size_t)MROWS*HKV*HD], g_Vl [(size_t)MROWS*HKV*HD];
__device__ bf16 g_ctxh[(size_t)MROWS*HQ*HD], g_ctxl[(size_t)MROWS*HQ*HD];

// ---------------- PTX helpers ------------------------------------------------
__device__ __forceinline__ void ldsm4(uint32_t* r, uint32_t a) {
    asm volatile("ldmatrix.sync.aligned.m8n8.x4.shared.b16 {%0,%1,%2,%3}, [%4];\n"
        : "=r"(r[0]), "=r"(r[1]), "=r"(r[2]), "=r"(r[3]) : "r"(a));
}
__device__ __forceinline__ void ldsm4t(uint32_t* r, uint32_t a) {
    asm volatile("ldmatrix.sync.aligned.m8n8.x4.trans.shared.b16 {%0,%1,%2,%3}, [%4];\n"
        : "=r"(r[0]), "=r"(r[1]), "=r"(r[2]), "=r"(r[3]) : "r"(a));
}
__device__ __forceinline__ void mma16816(float* c, const uint32_t* a, const uint32_t* b) {
    asm volatile("mma.sync.aligned.m16n8k16.row.col.f32.bf16.bf16.f32 "
        "{%0,%1,%2,%3}, {%4,%5,%6,%7}, {%8,%9}, {%0,%1,%2,%3};\n"
        : "+f"(c[0]), "+f"(c[1]), "+f"(c[2]), "+f"(c[3])
        : "r"(a[0]), "r"(a[1]), "r"(a[2]), "r"(a[3]), "r"(b[0]), "r"(b[1]));
}
__device__ __forceinline__ void cp_async16(uint32_t dst, const void* src) {
    asm volatile("cp.async.ca.shared.global [%0], [%1], 16;\n" :: "r"(dst), "l"(src));
}
__device__ __forceinline__ void cp_commit() {
    asm volatile("cp.async.commit_group;\n" ::: "memory");
}
__device__ __forceinline__ uint32_t packbf(float a, float b) {
    __nv_bfloat162 t = __floats2bfloat162_rn(a, b);
    return *(uint32_t*)&t;
}
__device__ __forceinline__ void split2(float a, float b, uint32_t& h, uint32_t& l) {
    bf16 ha = __float2bfloat16(a), hb = __float2bfloat16(b);
    h = ((uint32_t)__bfloat16_as_ushort(hb) << 16) | (uint32_t)__bfloat16_as_ushort(ha);
    l = packbf(a - __bfloat162float(ha), b - __bfloat162float(hb));
}

// ---------------- fp32 -> bf16 hi/lo split ----------------------------------
__global__ __launch_bounds__(256) void split_kernel(
    const float4* __restrict__ in, bf16* __restrict__ hi, bf16* __restrict__ lo, int n4)
{
    int i = blockIdx.x * 256 + threadIdx.x;
    if (i >= n4) return;
    float4 v = in[i];
    uint32_t h0, l0, h1, l1;
    split2(v.x, v.y, h0, l0);
    split2(v.z, v.w, h1, l1);
    *(uint2*)(hi + (size_t)i*4) = make_uint2(h0, h1);
    *(uint2*)(lo + (size_t)i*4) = make_uint2(l0, l1);
}

// ---------------- GEMM core macros (shared by qkv and o kernels) -------------
#define BKC 32
#define PAD 40
#define ARR (128*PAD)
#define STG (4*ARR)
#define GSMEM (2*STG*2)   // 81920 bytes

#define GEMM_PROLOGUE()                                                         \
    const int tid  = threadIdx.x;                                               \
    const int lane = tid & 31, wid = tid >> 5;                                  \
    const int wm = (wid >> 1) * 32;                                             \
    const int wn = (wid & 1) * 64;                                              \
    const int m0 = tid >> 2;                                                    \
    const int c0 = (tid & 3) * 8;                                               \
    const int r_   = lane & 7, blk_ = lane >> 3;                                \
    const int a_row = ((blk_ & 1) << 3) + r_;                                   \
    const int a_col = (blk_ >> 1) << 3;                                         \
    const int b_row = ((blk_ >> 1) << 3) + r_;                                  \
    const int b_col = (blk_ & 1) << 3;                                          \
    float acc[2][8][4];                                                         \
    _Pragma("unroll") for (int i = 0; i < 2; i++)                               \
    _Pragma("unroll") for (int j = 0; j < 8; j++)                               \
    _Pragma("unroll") for (int k = 0; k < 4; k++) acc[i][j][k] = 0.f;

#define ISSUE(it, stage) do {                                                   \
    const int k0_ = (it) * BKC;                                                 \
    uint32_t sst_ = sbase + (uint32_t)(stage) * (STG * 2);                      \
    _Pragma("unroll")                                                           \
    for (int arr_ = 0; arr_ < 2; arr_++) {                                      \
        _Pragma("unroll")                                                       \
        for (int hh_ = 0; hh_ < 2; hh_++) {                                     \
            int m_ = m0 + hh_ * 64;                                             \
            cp_async16(sst_ + (uint32_t)((arr_*ARR + m_*PAD + c0) * 2),         \
                       gA[arr_] + (size_t)(row0 + m_) * K + k0_ + c0);          \
            cp_async16(sst_ + (uint32_t)(((2+arr_)*ARR + m_*PAD + c0) * 2),     \
                       gB[arr_] + (size_t)(col0 + m_) * K + k0_ + c0);          \
        }                                                                       \
    }                                                                           \
} while (0)

#define GEMM_MAINLOOP()                                                         \
    ISSUE(0, 0);                                                                \
    cp_commit();                                                                \
    for (int it = 0; it < niter; it++) {                                        \
        if (it + 1 < niter) {                                                   \
            ISSUE(it + 1, (it + 1) & 1);                                        \
            cp_commit();                                                        \
            asm volatile("cp.async.wait_group 1;\n" ::: "memory");              \
        } else {                                                                \
            asm volatile("cp.async.wait_group 0;\n" ::: "memory");              \
        }                                                                       \
        __syncthreads();                                                        \
        const uint32_t sst = sbase + (uint32_t)(it & 1) * (STG * 2);            \
        _Pragma("unroll")                                                       \
        for (int ks = 0; ks < 2; ks++) {                                        \
            const int kofs = ks * 16;                                           \
            uint32_t ah[2][4], al[2][4], bh[4][4], bl[4][4];                    \
            _Pragma("unroll")                                                   \
            for (int mt = 0; mt < 2; mt++) {                                    \
                uint32_t addr = sst + (uint32_t)(((wm + mt*16 + a_row)*PAD + kofs + a_col) * 2); \
                ldsm4(ah[mt], addr);                                            \
                ldsm4(al[mt], addr + ARR * 2);                                  \
            }                                                                   \
            _Pragma("unroll")                                                   \
            for (int p = 0; p < 4; p++) {                                       \
                uint32_t addr = sst + (uint32_t)((2*ARR + (wn + p*16 + b_row)*PAD + kofs + b_col) * 2); \
                ldsm4(bh[p], addr);                                             \
                ldsm4(bl[p], addr + ARR * 2);                                   \
            }                                                                   \
            _Pragma("unroll")                                                   \
            for (int mt = 0; mt < 2; mt++)                                      \
            _Pragma("unroll")                                                   \
                for (int p = 0; p < 4; p++) {                                   \
                    mma16816(acc[mt][2*p],   ah[mt], &bh[p][0]);                \
                    mma16816(acc[mt][2*p+1], ah[mt], &bh[p][2]);                \
                    mma16816(acc[mt][2*p],   ah[mt], &bl[p][0]);                \
                    mma16816(acc[mt][2*p+1], ah[mt], &bl[p][2]);                \
                    mma16816(acc[mt][2*p],   al[mt], &bh[p][0]);                \
                    mma16816(acc[mt][2*p+1], al[mt], &bh[p][2]);                \
                }                                                               \
        }                                                                       \
        __syncthreads();                                                        \
    }

// ---------------- merged QKV GEMM with fused norm/rope/split epilogue --------
// grid (32, MROWS/128): bx 0-15 -> Q head bx, 16-23 -> K head bx-16,
// 24-31 -> V head bx-24.
__global__ __launch_bounds__(256, 2) void gemm_qkv(
    const bf16* __restrict__ Ah, const bf16* __restrict__ Al,
    const bf16* __restrict__ Wqh_, const bf16* __restrict__ Wql_,
    const bf16* __restrict__ Wkh_, const bf16* __restrict__ Wkl_,
    const bf16* __restrict__ Wvh_, const bf16* __restrict__ Wvl_,
    bf16* __restrict__ Qh, bf16* __restrict__ Ql,
    bf16* __restrict__ Kh, bf16* __restrict__ Kl,
    bf16* __restrict__ Vh, bf16* __restrict__ Vl,
    const float* __restrict__ q_scale, const float* __restrict__ k_scale,
    const float* __restrict__ cosT, const float* __restrict__ sinT)
{
    extern __shared__ bf16 sm[];
    const uint32_t sbase = (uint32_t)__cvta_generic_to_shared(sm);
    const int bx = blockIdx.x;
    const int row0 = blockIdx.y * 128;
    const int K = DD;
    const int niter = K / BKC;

    // operand selection
    int mode, hloc;
    const bf16 *Bh_, *Bl_;
    if (bx < 16)      { mode = 0; hloc = bx;      Bh_ = Wqh_; Bl_ = Wql_; }
    else if (bx < 24) { mode = 1; hloc = bx - 16; Bh_ = Wkh_; Bl_ = Wkl_; }
    else              { mode = 2; hloc = bx - 24; Bh_ = Wvh_; Bl_ = Wvl_; }
    const int col0 = hloc * 128;
    const bf16* gA[2] = {Ah, Al};
    const bf16* gB[2] = {Bh_, Bl_};

    GEMM_PROLOGUE();
    GEMM_MAINLOOP();

    // ---- stage fp32 tile into smem (reuse pipeline smem) ----
    __syncthreads();
    float* sf = (float*)sm;                 // 128 x 132 floats = 67584 B <= 81920
    const int gr = lane >> 2, gc = (lane & 3) * 2;
#pragma unroll
    for (int mt = 0; mt < 2; mt++)
#pragma unroll
        for (int nt = 0; nt < 8; nt++) {
            int row = wm + mt*16 + gr;
            int col = wn + nt*8 + gc;
            *(float2*)&sf[(size_t)row*132 + col]     = make_float2(acc[mt][nt][0], acc[mt][nt][1]);
            *(float2*)&sf[(size_t)(row+8)*132 + col] = make_float2(acc[mt][nt][2], acc[mt][nt][3]);
        }
    __syncthreads();

    // ---- per-warp row processing: warp wid owns rows wid*16..wid*16+15 ----
    const float* scv = (mode == 0) ? q_scale : k_scale;
    const float smul = (mode == 0) ? QSCALE : 1.0f;
    const int   Hn   = (mode == 0) ? HQ : HKV;
    bf16* outh = (mode == 0) ? Qh : (mode == 1) ? Kh : Vh;
    bf16* outl = (mode == 0) ? Ql : (mode == 1) ? Kl : Vl;

    float4 sc4 = make_float4(1.f,1.f,1.f,1.f);
    if (mode < 2) sc4 = *(const float4*)&scv[lane*4];

    for (int rr = 0; rr < 16; rr++) {
        const int row  = wid*16 + rr;
        const int gtok = row0 + row;
        const int b = gtok >> 11, t = gtok & (TT-1);
        float4 v = *(float4*)&sf[(size_t)row*132 + lane*4];
        float4 o;
        if (mode < 2) {
            float ss = v.x*v.x + v.y*v.y + v.z*v.z + v.w*v.w;
#pragma unroll
            for (int ofs = 16; ofs > 0; ofs >>= 1)
                ss += __shfl_xor_sync(0xffffffffu, ss, ofs);
            float inv = rsqrtf(ss*(1.0f/HD) + 1e-6f);
            v.x *= inv*sc4.x; v.y *= inv*sc4.y; v.z *= inv*sc4.z; v.w *= inv*sc4.w;
            // rope: lane l pairs with lane l^16 (d and d±64)
            float px = __shfl_xor_sync(0xffffffffu, v.x, 16);
            float py = __shfl_xor_sync(0xffffffffu, v.y, 16);
            float pz = __shfl_xor_sync(0xffffffffu, v.z, 16);
            float pw = __shfl_xor_sync(0xffffffffu, v.w, 16);
            float s = (lane < 16) ? -1.f : 1.f;
            float4 cs = *(const float4*)&cosT[(size_t)t*HD + lane*4];
            float4 sn = *(const float4*)&sinT[(size_t)t*HD + lane*4];
            o.x = (v.x*cs.x + s*px*sn.x) * smul;
            o.y = (v.y*cs.y + s*py*sn.y) * smul;
            o.z = (v.z*cs.z + s*pz*sn.z) * smul;
            o.w = (v.w*cs.w + s*pw*sn.w) * smul;
        } else {
            o = v;
        }
        uint32_t H0, L0, H1, L1;
        split2(o.x, o.y, H0, L0);
        split2(o.z, o.w, H1, L1);
        size_t off;
        if (mode < 2) off = (((size_t)(b*Hn + hloc))*TT + t)*HD + lane*4;
        else          off = (size_t)gtok*(HKV*HD) + hloc*HD + lane*4;
        *(uint2*)&outh[off] = make_uint2(H0, H1);
        *(uint2*)&outl[off] = make_uint2(L0, L1);
    }
}

// ---------------- O-projection GEMM (fp32 epilogue) --------------------------
__global__ __launch_bounds__(256, 2) void gemm_o(
    const bf16* __restrict__ Ah, const bf16* __restrict__ Al,
    const bf16* __restrict__ Bh_, const bf16* __restrict__ Bl_,
    float* __restrict__ C, int N)
{
    extern __shared__ bf16 sm[];
    const uint32_t sbase = (uint32_t)__cvta_generic_to_shared(sm);
    const int row0 = blockIdx.y * 128, col0 = blockIdx.x * 128;
    const int K = DD;
    const int niter = K / BKC;
    const bf16* gA[2] = {Ah, Al};
    const bf16* gB[2] = {Bh_, Bl_};

    GEMM_PROLOGUE();
    GEMM_MAINLOOP();

    const int gr = lane >> 2, gc = (lane & 3) * 2;
#pragma unroll
    for (int mt = 0; mt < 2; mt++)
#pragma unroll
        for (int nt = 0; nt < 8; nt++) {
            int row = row0 + wm + mt*16 + gr;
            int col = col0 + wn + nt*8 + gc;
            *(float2*)&C[(size_t)row*N + col]     = make_float2(acc[mt][nt][0], acc[mt][nt][1]);
            *(float2*)&C[(size_t)(row+8)*N + col] = make_float2(acc[mt][nt][2], acc[mt][nt][3]);
        }
}

// ---------------- fused flash attention (bf16x3 QK^T and PV) ----------------
#define BQ 128
#define BK 64
#define FP 136
#define QELE (BQ*FP)
#define KELE (BK*FP)
#define QAREA (2*QELE)
#define STGKV (4*KELE)
#define FLASH_SMEM ((QAREA + 2*STGKV) * 2)

__global__ __launch_bounds__(256) void flash_kernel(
    const bf16* __restrict__ Qh, const bf16* __restrict__ Ql,
    const bf16* __restrict__ Kh, const bf16* __restrict__ Kl,
    const bf16* __restrict__ Vh, const bf16* __restrict__ Vl,
    bf16* __restrict__ ctxh, bf16* __restrict__ ctxl)
{
    extern __shared__ bf16 sm[];
    const int tid = threadIdx.x, lane = tid & 31, wid = tid >> 5;
    const int qb = gridDim.x - 1 - blockIdx.x;
    const int bh = blockIdx.y;
    const int b = bh >> 4, h = bh & 15, kv = h >> 1;
    const int q0 = qb * BQ;
    const uint32_t sbase = (uint32_t)__cvta_generic_to_shared(sm);

    const bf16* Qhg = Qh + ((size_t)(b*HQ  + h )*TT + q0)*HD;
    const bf16* Qlg = Ql + ((size_t)(b*HQ  + h )*TT + q0)*HD;
    const bf16* Khg = Kh + ((size_t)(b*HKV + kv)*TT)*HD;
    const bf16* Klg = Kl + ((size_t)(b*HKV + kv)*TT)*HD;
    const bf16* Vhg = Vh + (size_t)b*TT*(HKV*HD) + kv*HD;
    const bf16* Vlg = Vl + (size_t)b*TT*(HKV*HD) + kv*HD;

#pragma unroll
    for (int i = 0; i < 8; i++) {
        int c = tid + i*256;
        int row = c >> 4, col = (c & 15) * 8;
        cp_async16(sbase + (uint32_t)((row*FP + col) * 2),        Qhg + (size_t)row*HD + col);
        cp_async16(sbase + (uint32_t)((QELE + row*FP + col) * 2), Qlg + (size_t)row*HD + col);
    }

#define ISSUEKV(kt, stage) do {                                                     \
    const int k0_ = (kt) * BK;                                                      \
    const uint32_t kb_ = sbase + (uint32_t)((QAREA + (stage)*STGKV) * 2);           \
    _Pragma("unroll")                                                               \
    for (int i_ = 0; i_ < 4; i_++) {                                                \
        int c_ = tid + i_*256;                                                      \
        int row_ = c_ >> 4, col_ = (c_ & 15) * 8;                                   \
        uint32_t so_ = (uint32_t)((row_*FP + col_) * 2);                            \
        cp_async16(kb_ + so_,              Khg + (size_t)(k0_+row_)*HD + col_);     \
        cp_async16(kb_ + KELE*2 + so_,     Klg + (size_t)(k0_+row_)*HD + col_);     \
        cp_async16(kb_ + 2*KELE*2 + so_,   Vhg + (size_t)(k0_+row_)*(HKV*HD) + col_); \
        cp_async16(kb_ + 3*KELE*2 + so_,   Vlg + (size_t)(k0_+row_)*(HKV*HD) + col_); \
    }                                                                               \
} while (0)

    ISSUEKV(0, 0);
    cp_commit();

    const int r   = lane & 7, blkid = lane >> 3;
    const int a_row = ((blkid & 1) << 3) + r;
    const int a_col = (blkid >> 1) << 3;
    const int b_row = ((blkid >> 1) << 3) + r;
    const int b_col = (blkid & 1) << 3;
    const int gr = lane >> 2;

    float oacc[16][4];
#pragma unroll
    for (int i = 0; i < 16; i++)
#pragma unroll
        for (int j = 0; j < 4; j++) oacc[i][j] = 0.f;
    float m0 = -1e30f, m1 = -1e30f, l0 = 0.f, l1 = 0.f;

    const int row0g = q0 + wid*16 + gr;
    const int row1g = row0g + 8;
    const int nkt = 2*qb + 2;

    for (int kt = 0; kt < nkt; kt++) {
        if (kt + 1 < nkt) {
            ISSUEKV(kt + 1, (kt + 1) & 1);
            cp_commit();
            asm volatile("cp.async.wait_group 1;\n" ::: "memory");
        } else {
            asm volatile("cp.async.wait_group 0;\n" ::: "memory");
        }
        __syncthreads();

        const int k0 = kt * BK;
        const uint32_t kb_s = sbase + (uint32_t)((QAREA + (kt & 1)*STGKV) * 2);

        float sacc[8][4];
#pragma unroll
        for (int i = 0; i < 8; i++)
#pragma unroll
            for (int j = 0; j < 4; j++) sacc[i][j] = 0.f;

#pragma unroll
        for (int ks = 0; ks < 8; ks++) {
            uint32_t qa = sbase + (uint32_t)(((wid*16 + a_row)*FP + ks*16 + a_col) * 2);
            uint32_t qh[4], ql[4];
            ldsm4(qh, qa);
            ldsm4(ql, qa + QELE*2);
#pragma unroll
            for (int np = 0; np < 4; np++) {
                uint32_t ka = kb_s + (uint32_t)(((np*16 + b_row)*FP + ks*16 + b_col) * 2);
                uint32_t kh[4], kl[4];
                ldsm4(kh, ka);
                ldsm4(kl, ka + KELE*2);
                mma16816(sacc[2*np],   qh, &kh[0]);
                mma16816(sacc[2*np+1], qh, &kh[2]);
                mma16816(sacc[2*np],   qh, &kl[0]);
                mma16816(sacc[2*np+1], qh, &kl[2]);
                mma16816(sacc[2*np],   ql, &kh[0]);
                mma16816(sacc[2*np+1], ql, &kh[2]);
            }
        }

        float mx0 = -1e30f, mx1 = -1e30f;
#pragma unroll
        for (int nt = 0; nt < 8; nt++) {
            int cg = k0 + nt*8 + (lane & 3)*2;
            if (cg     > row0g) sacc[nt][0] = -1e30f;
            if (cg + 1 > row0g) sacc[nt][1] = -1e30f;
            if (cg     > row1g) sacc[nt][2] = -1e30f;
            if (cg + 1 > row1g) sacc[nt][3] = -1e30f;
            mx0 = fmaxf(mx0, fmaxf(sacc[nt][0], sacc[nt][1]));
            mx1 = fmaxf(mx1, fmaxf(sacc[nt][2], sacc[nt][3]));
        }
        mx0 = fmaxf(mx0, __shfl_xor_sync(0xffffffffu, mx0, 1));
        mx0 = fmaxf(mx0, __shfl_xor_sync(0xffffffffu, mx0, 2));
        mx1 = fmaxf(mx1, __shfl_xor_sync(0xffffffffu, mx1, 1));
        mx1 = fmaxf(mx1, __shfl_xor_sync(0xffffffffu, mx1, 2));

        float mn0 = fmaxf(m0, mx0), mn1 = fmaxf(m1, mx1);
        float sc0 = exp2f(m0 - mn0), sc1 = exp2f(m1 - mn1);
        m0 = mn0; m1 = mn1;

        float s0 = 0.f, s1 = 0.f;
#pragma unroll
        for (int nt = 0; nt < 8; nt++) {
            sacc[nt][0] = exp2f(sacc[nt][0] - m0);
            sacc[nt][1] = exp2f(sacc[nt][1] - m0);
            sacc[nt][2] = exp2f(sacc[nt][2] - m1);
            sacc[nt][3] = exp2f(sacc[nt][3] - m1);
            s0 += sacc[nt][0] + sacc[nt][1];
            s1 += sacc[nt][2] + sacc[nt][3];
        }
        s0 += __shfl_xor_sync(0xffffffffu, s0, 1);
        s0 += __shfl_xor_sync(0xffffffffu, s0, 2);
        s1 += __shfl_xor_sync(0xffffffffu, s1, 1);
        s1 += __shfl_xor_sync(0xffffffffu, s1, 2);
        l0 = l0*sc0 + s0;
        l1 = l1*sc1 + s1;

#pragma unroll
        for (int i = 0; i < 16; i++) {
            oacc[i][0] *= sc0; oacc[i][1] *= sc0;
            oacc[i][2] *= sc1; oacc[i][3] *= sc1;
        }

        const int vrow = (lane & 7) + ((lane >> 3) & 1)*8;
        const int vcolb = ((lane >> 4) << 3);
#pragma unroll
        for (int kp = 0; kp < 4; kp++) {
            uint32_t ph[4], pl[4];
#pragma unroll
            for (int half = 0; half < 2; half++) {
                float e0 = sacc[2*kp+half][0], e1 = sacc[2*kp+half][1];
                float e2 = sacc[2*kp+half][2], e3 = sacc[2*kp+half][3];
                bf16 b0 = __float2bfloat16(e0), b1 = __float2bfloat16(e1);
                bf16 b2 = __float2bfloat16(e2), b3 = __float2bfloat16(e3);
                ph[2*half]   = packbf(e0, e1);
                ph[2*half+1] = packbf(e2, e3);
                pl[2*half]   = packbf(e0 - __bfloat162float(b0), e1 - __bfloat162float(b1));
                pl[2*half+1] = packbf(e2 - __bfloat162float(b2), e3 - __bfloat162float(b3));
            }
#pragma unroll
            for (int np = 0; np < 8; np++) {
                uint32_t va = kb_s + (uint32_t)((2*KELE + (kp*16 + vrow)*FP + np*16 + vcolb) * 2);
                uint32_t vh[4], vl[4];
                ldsm4t(vh, va);
                ldsm4t(vl, va + KELE*2);
                mma16816(oacc[2*np],   ph, &vh[0]);
                mma16816(oacc[2*np+1], ph, &vh[2]);
                mma16816(oacc[2*np],   ph, &vl[0]);
                mma16816(oacc[2*np+1], ph, &vl[2]);
                mma16816(oacc[2*np],   pl, &vh[0]);
                mma16816(oacc[2*np+1], pl, &vh[2]);
            }
        }
        __syncthreads();
    }
#undef ISSUEKV

    const float il0 = 1.f / l0, il1 = 1.f / l1;
    const size_t tok0 = (size_t)(b*TT + q0 + wid*16 + gr);
#pragma unroll
    for (int nt = 0; nt < 16; nt++) {
        int col = h*HD + nt*8 + (lane & 3)*2;
        float v0 = oacc[nt][0]*il0, v1 = oacc[nt][1]*il0;
        float v2 = oacc[nt][2]*il1, v3 = oacc[nt][3]*il1;
        uint32_t H0, L0, H1, L1;
        split2(v0, v1, H0, L0);
        split2(v2, v3, H1, L1);
        *(uint32_t*)&ctxh[tok0*(HQ*HD) + col]     = H0;
        *(uint32_t*)&ctxl[tok0*(HQ*HD) + col]     = L0;
        *(uint32_t*)&ctxh[(tok0+8)*(HQ*HD) + col] = H1;
        *(uint32_t*)&ctxl[(tok0+8)*(HQ*HD) + col] = L1;
    }
}

// ---------------- launch ------------------------------------------------------
extern "C" void kernel_launch(void* const* d_in, const int* in_sizes, int n_in,
                              void* d_out, int out_size)
{
    const float* x       = (const float*)d_in[0];
    const float* cosT    = (const float*)d_in[2];
    const float* sinT    = (const float*)d_in[3];
    const float* Wq      = (const float*)d_in[4];
    const float* Wk      = (const float*)d_in[5];
    const float* Wv      = (const float*)d_in[6];
    const float* Wo      = (const float*)d_in[7];
    const float* q_scale = (const float*)d_in[8];
    const float* k_scale = (const float*)d_in[9];
    float* out = (float*)d_out;

    bf16 *xh,*xl,*Wqh,*Wql,*Wkh,*Wkl,*Wvh,*Wvl,*Woh,*Wol;
    bf16 *Qh,*Ql,*Kh,*Kl,*Vh,*Vl,*ctxh,*ctxl;
    cudaGetSymbolAddress((void**)&xh,   g_xh);   cudaGetSymbolAddress((void**)&xl,   g_xl);
    cudaGetSymbolAddress((void**)&Wqh,  g_Wqh);  cudaGetSymbolAddress((void**)&Wql,  g_Wql);
    cudaGetSymbolAddress((void**)&Wkh,  g_Wkh);  cudaGetSymbolAddress((void**)&Wkl,  g_Wkl);
    cudaGetSymbolAddress((void**)&Wvh,  g_Wvh);  cudaGetSymbolAddress((void**)&Wvl,  g_Wvl);
    cudaGetSymbolAddress((void**)&Woh,  g_Woh);  cudaGetSymbolAddress((void**)&Wol,  g_Wol);
    cudaGetSymbolAddress((void**)&Qh,   g_Qh);   cudaGetSymbolAddress((void**)&Ql,   g_Ql);
    cudaGetSymbolAddress((void**)&Kh,   g_Kh);   cudaGetSymbolAddress((void**)&Kl,   g_Kl);
    cudaGetSymbolAddress((void**)&Vh,   g_Vh);   cudaGetSymbolAddress((void**)&Vl,   g_Vl);
    cudaGetSymbolAddress((void**)&ctxh, g_ctxh); cudaGetSymbolAddress((void**)&ctxl, g_ctxl);

    static bool attr_set = false;
    if (!attr_set) {
        cudaFuncSetAttribute(gemm_qkv,     cudaFuncAttributeMaxDynamicSharedMemorySize, GSMEM);
        cudaFuncSetAttribute(gemm_o,       cudaFuncAttributeMaxDynamicSharedMemorySize, GSMEM);
        cudaFuncSetAttribute(flash_kernel, cudaFuncAttributeMaxDynamicSharedMemorySize, FLASH_SMEM);
        attr_set = true;
    }

    // 0: split inputs/weights to bf16 hi/lo
    split_kernel<<<(MROWS*DD/4 + 255)/256, 256>>>((const float4*)x,  xh,  xl,  MROWS*DD/4);
    split_kernel<<<(HQ*HD*DD/4 + 255)/256, 256>>>((const float4*)Wq, Wqh, Wql, HQ*HD*DD/4);
    split_kernel<<<(HKV*HD*DD/4 + 255)/256, 256>>>((const float4*)Wk, Wkh, Wkl, HKV*HD*DD/4);
    split_kernel<<<(HKV*HD*DD/4 + 255)/256, 256>>>((const float4*)Wv, Wvh, Wvl, HKV*HD*DD/4);
    split_kernel<<<(DD*HQ*HD/4 + 255)/256, 256>>>((const float4*)Wo, Woh, Wol, DD*HQ*HD/4);

    // 1: merged QKV projection + fused RMSNorm/RoPE/split epilogue
    gemm_qkv<<<dim3(32, MROWS/128), 256, GSMEM>>>(
        xh, xl, Wqh, Wql, Wkh, Wkl, Wvh, Wvl,
        Qh, Ql, Kh, Kl, Vh, Vl, q_scale, k_scale, cosT, sinT);

    // 2: fused flash attention
    flash_kernel<<<dim3(TT/BQ, BB*HQ), 256, FLASH_SMEM>>>(Qh, Ql, Kh, Kl, Vh, Vl, ctxh, ctxl);

    // 3: output projection
    gemm_o<<<dim3(DD/128, MROWS/128), 256, GSMEM>>>(ctxh, ctxl, Woh, Wol, out, DD);
}

// round 8
// speedup vs baseline: 2.7760x; 1.2542x over previous
#include <cuda_runtime.h>
#include <cuda_bf16.h>
#include <cuda_fp16.h>
#include <cstdint>
#include <cstddef>

// Problem constants
#define BB 2
#define TT 2048
#define DD 2048
#define HQ 16
#define HKV 8
#define HD 128
#define MROWS (BB*TT)   // 4096

typedef __nv_bfloat16 bf16;

// log2(e)/sqrt(128)
#define QSCALE 0.12752551164384637f
#define WSCALE 256.0f
#define INV256 0.00390625f

// ---------------- scratch (static device globals) ---------------------------
__device__ __half g_xh [(size_t)MROWS*DD];                      // single plane
__device__ __half g_Wqh[(size_t)HQ*HD*DD],  g_Wql[(size_t)HQ*HD*DD];
__device__ __half g_Wkh[(size_t)HKV*HD*DD], g_Wkl[(size_t)HKV*HD*DD];
__device__ __half g_Wvh[(size_t)HKV*HD*DD], g_Wvl[(size_t)HKV*HD*DD];
__device__ __half g_Woh[(size_t)DD*HQ*HD],  g_Wol[(size_t)DD*HQ*HD];
__device__ bf16 g_Qh [(size_t)BB*HQ*TT*HD],  g_Ql [(size_t)BB*HQ*TT*HD];
__device__ bf16 g_Kh [(size_t)BB*HKV*TT*HD], g_Kl [(size_t)BB*HKV*TT*HD];
__device__ bf16 g_Vh [(size_t)MROWS*HKV*HD], g_Vl [(size_t)MROWS*HKV*HD];
__device__ __half g_ctxh[(size_t)MROWS*HQ*HD];                  // single plane

// ---------------- PTX helpers ------------------------------------------------
__device__ __forceinline__ void ldsm4(uint32_t* r, uint32_t a) {
    asm volatile("ldmatrix.sync.aligned.m8n8.x4.shared.b16 {%0,%1,%2,%3}, [%4];\n"
        : "=r"(r[0]), "=r"(r[1]), "=r"(r[2]), "=r"(r[3]) : "r"(a));
}
__device__ __forceinline__ void ldsm4t(uint32_t* r, uint32_t a) {
    asm volatile("ldmatrix.sync.aligned.m8n8.x4.trans.shared.b16 {%0,%1,%2,%3}, [%4];\n"
        : "=r"(r[0]), "=r"(r[1]), "=r"(r[2]), "=r"(r[3]) : "r"(a));
}
__device__ __forceinline__ void mma16816(float* c, const uint32_t* a, const uint32_t* b) {
    asm volatile("mma.sync.aligned.m16n8k16.row.col.f32.bf16.bf16.f32 "
        "{%0,%1,%2,%3}, {%4,%5,%6,%7}, {%8,%9}, {%0,%1,%2,%3};\n"
        : "+f"(c[0]), "+f"(c[1]), "+f"(c[2]), "+f"(c[3])
        : "r"(a[0]), "r"(a[1]), "r"(a[2]), "r"(a[3]), "r"(b[0]), "r"(b[1]));
}
__device__ __forceinline__ void mma16816h(float* c, const uint32_t* a, const uint32_t* b) {
    asm volatile("mma.sync.aligned.m16n8k16.row.col.f32.f16.f16.f32 "
        "{%0,%1,%2,%3}, {%4,%5,%6,%7}, {%8,%9}, {%0,%1,%2,%3};\n"
        : "+f"(c[0]), "+f"(c[1]), "+f"(c[2]), "+f"(c[3])
        : "r"(a[0]), "r"(a[1]), "r"(a[2]), "r"(a[3]), "r"(b[0]), "r"(b[1]));
}
__device__ __forceinline__ void cp_async16(uint32_t dst, const void* src) {
    asm volatile("cp.async.ca.shared.global [%0], [%1], 16;\n" :: "r"(dst), "l"(src));
}
__device__ __forceinline__ void cp_commit() {
    asm volatile("cp.async.commit_group;\n" ::: "memory");
}
__device__ __forceinline__ uint32_t packbf(float a, float b) {
    __nv_bfloat162 t = __floats2bfloat162_rn(a, b);
    return *(uint32_t*)&t;
}
__device__ __forceinline__ uint32_t packh(float a, float b) {
    __half2 t = __floats2half2_rn(a, b);
    return *(uint32_t*)&t;
}
__device__ __forceinline__ void split2(float a, float b, uint32_t& h, uint32_t& l) {
    bf16 ha = __float2bfloat16(a), hb = __float2bfloat16(b);
    h = ((uint32_t)__bfloat16_as_ushort(hb) << 16) | (uint32_t)__bfloat16_as_ushort(ha);
    l = packbf(a - __bfloat162float(ha), b - __bfloat162float(hb));
}
__device__ __forceinline__ void split2h(float a, float b, uint32_t& h, uint32_t& l) {
    __half ha = __float2half_rn(a), hb = __float2half_rn(b);
    h = ((uint32_t)__half_as_ushort(hb) << 16) | (uint32_t)__half_as_ushort(ha);
    l = packh(a - __half2float(ha), b - __half2float(hb));
}

// ---------------- fp32 -> fp16 single-plane (activations) --------------------
__global__ __launch_bounds__(256) void split_x_kernel(
    const float4* __restrict__ in, __half* __restrict__ out, int n4)
{
    int i = blockIdx.x * 256 + threadIdx.x;
    if (i >= n4) return;
    float4 v = in[i];
    *(uint2*)(out + (size_t)i*4) = make_uint2(packh(v.x, v.y), packh(v.z, v.w));
}

// ---------------- fp32 -> fp16 hi/lo (weights, x256) -------------------------
__global__ __launch_bounds__(256) void split_w_kernel(
    const float4* __restrict__ in, __half* __restrict__ hi, __half* __restrict__ lo, int n4)
{
    int i = blockIdx.x * 256 + threadIdx.x;
    if (i >= n4) return;
    float4 v = in[i];
    uint32_t h0, l0, h1, l1;
    split2h(v.x*WSCALE, v.y*WSCALE, h0, l0);
    split2h(v.z*WSCALE, v.w*WSCALE, h1, l1);
    *(uint2*)(hi + (size_t)i*4) = make_uint2(h0, h1);
    *(uint2*)(lo + (size_t)i*4) = make_uint2(l0, l1);
}

// ---------------- GEMM core macros (fp16 2-mma scheme) ------------------------
// Stage: A single plane + B hi/lo, each 128 x BKC fp16 padded to PAD.
#define BKC 32
#define PAD 40
#define ARR (128*PAD)
#define STG3 (3*ARR)
#define GSMEM_O   (2*STG3*2)    // 61440
#define GSMEM_QKV 67584         // fp32 epilogue staging (128x132 f32)

#define GEMM_PROLOGUE()                                                         \
    const int tid  = threadIdx.x;                                               \
    const int lane = tid & 31, wid = tid >> 5;                                  \
    const int wm = (wid >> 1) * 32;                                             \
    const int wn = (wid & 1) * 64;                                              \
    const int m0 = tid >> 2;                                                    \
    const int c0 = (tid & 3) * 8;                                               \
    const int r_   = lane & 7, blk_ = lane >> 3;                                \
    const int a_row = ((blk_ & 1) << 3) + r_;                                   \
    const int a_col = (blk_ >> 1) << 3;                                         \
    const int b_row = ((blk_ >> 1) << 3) + r_;                                  \
    const int b_col = (blk_ & 1) << 3;                                          \
    float acc[2][8][4];                                                         \
    _Pragma("unroll") for (int i = 0; i < 2; i++)                               \
    _Pragma("unroll") for (int j = 0; j < 8; j++)                               \
    _Pragma("unroll") for (int k = 0; k < 4; k++) acc[i][j][k] = 0.f;

#define ISSUE(it, stage) do {                                                   \
    const int k0_ = (it) * BKC;                                                 \
    uint32_t sst_ = sbase + (uint32_t)(stage) * (STG3 * 2);                     \
    _Pragma("unroll")                                                           \
    for (int hh_ = 0; hh_ < 2; hh_++) {                                         \
        int m_ = m0 + hh_ * 64;                                                 \
        cp_async16(sst_ + (uint32_t)((m_*PAD + c0) * 2),                        \
                   gA + (size_t)(row0 + m_) * K + k0_ + c0);                    \
        cp_async16(sst_ + (uint32_t)((ARR + m_*PAD + c0) * 2),                  \
                   gB0 + (size_t)(col0 + m_) * K + k0_ + c0);                   \
        cp_async16(sst_ + (uint32_t)((2*ARR + m_*PAD + c0) * 2),                \
                   gB1 + (size_t)(col0 + m_) * K + k0_ + c0);                   \
    }                                                                           \
} while (0)

#define GEMM_MAINLOOP()                                                         \
    ISSUE(0, 0);                                                                \
    cp_commit();                                                                \
    for (int it = 0; it < niter; it++) {                                        \
        if (it + 1 < niter) {                                                   \
            ISSUE(it + 1, (it + 1) & 1);                                        \
            cp_commit();                                                        \
            asm volatile("cp.async.wait_group 1;\n" ::: "memory");              \
        } else {                                                                \
            asm volatile("cp.async.wait_group 0;\n" ::: "memory");              \
        }                                                                       \
        __syncthreads();                                                        \
        const uint32_t sst = sbase + (uint32_t)(it & 1) * (STG3 * 2);           \
        _Pragma("unroll")                                                       \
        for (int ks = 0; ks < 2; ks++) {                                        \
            const int kofs = ks * 16;                                           \
            uint32_t a_[2][4], bh_[4][4], bl_[4][4];                            \
            _Pragma("unroll")                                                   \
            for (int mt = 0; mt < 2; mt++)                                      \
                ldsm4(a_[mt], sst + (uint32_t)(((wm + mt*16 + a_row)*PAD + kofs + a_col) * 2)); \
            _Pragma("unroll")                                                   \
            for (int p = 0; p < 4; p++) {                                       \
                uint32_t addr = sst + (uint32_t)((ARR + (wn + p*16 + b_row)*PAD + kofs + b_col) * 2); \
                ldsm4(bh_[p], addr);                                            \
                ldsm4(bl_[p], addr + ARR * 2);                                  \
            }                                                                   \
            _Pragma("unroll")                                                   \
            for (int mt = 0; mt < 2; mt++)                                      \
            _Pragma("unroll")                                                   \
                for (int p = 0; p < 4; p++) {                                   \
                    mma16816h(acc[mt][2*p],   a_[mt], &bh_[p][0]);              \
                    mma16816h(acc[mt][2*p+1], a_[mt], &bh_[p][2]);              \
                    mma16816h(acc[mt][2*p],   a_[mt], &bl_[p][0]);              \
                    mma16816h(acc[mt][2*p+1], a_[mt], &bl_[p][2]);              \
                }                                                               \
        }                                                                       \
        __syncthreads();                                                        \
    }

// ---------------- merged QKV GEMM with fused norm/rope/split epilogue --------
// grid (32, MROWS/128): bx 0-15 -> Q head, 16-23 -> K head, 24-31 -> V head.
__global__ __launch_bounds__(256, 2) void gemm_qkv(
    const __half* __restrict__ gA,
    const __half* __restrict__ Wqh_, const __half* __restrict__ Wql_,
    const __half* __restrict__ Wkh_, const __half* __restrict__ Wkl_,
    const __half* __restrict__ Wvh_, const __half* __restrict__ Wvl_,
    bf16* __restrict__ Qh, bf16* __restrict__ Ql,
    bf16* __restrict__ Kh, bf16* __restrict__ Kl,
    bf16* __restrict__ Vh, bf16* __restrict__ Vl,
    const float* __restrict__ q_scale, const float* __restrict__ k_scale,
    const float* __restrict__ cosT, const float* __restrict__ sinT)
{
    extern __shared__ __half sm[];
    const uint32_t sbase = (uint32_t)__cvta_generic_to_shared(sm);
    const int bx = blockIdx.x;
    const int row0 = blockIdx.y * 128;
    const int K = DD;
    const int niter = K / BKC;

    int mode, hloc;
    const __half *gB0, *gB1;
    if (bx < 16)      { mode = 0; hloc = bx;      gB0 = Wqh_; gB1 = Wql_; }
    else if (bx < 24) { mode = 1; hloc = bx - 16; gB0 = Wkh_; gB1 = Wkl_; }
    else              { mode = 2; hloc = bx - 24; gB0 = Wvh_; gB1 = Wvl_; }
    const int col0 = hloc * 128;

    GEMM_PROLOGUE();
    GEMM_MAINLOOP();

    // ---- stage fp32 tile into smem (reuse pipeline smem) ----
    __syncthreads();
    float* sf = (float*)sm;                 // 128 x 132 floats = 67584 B
    const int gr = lane >> 2, gc = (lane & 3) * 2;
#pragma unroll
    for (int mt = 0; mt < 2; mt++)
#pragma unroll
        for (int nt = 0; nt < 8; nt++) {
            int row = wm + mt*16 + gr;
            int col = wn + nt*8 + gc;
            *(float2*)&sf[(size_t)row*132 + col]     = make_float2(acc[mt][nt][0], acc[mt][nt][1]);
            *(float2*)&sf[(size_t)(row+8)*132 + col] = make_float2(acc[mt][nt][2], acc[mt][nt][3]);
        }
    __syncthreads();

    const float* scv = (mode == 0) ? q_scale : k_scale;
    const float smul = (mode == 0) ? QSCALE : 1.0f;
    const int   Hn   = (mode == 0) ? HQ : HKV;
    bf16* outh = (mode == 0) ? Qh : (mode == 1) ? Kh : Vh;
    bf16* outl = (mode == 0) ? Ql : (mode == 1) ? Kl : Vl;

    float4 sc4 = make_float4(1.f,1.f,1.f,1.f);
    if (mode < 2) sc4 = *(const float4*)&scv[lane*4];

    for (int rr = 0; rr < 16; rr++) {
        const int row  = wid*16 + rr;
        const int gtok = row0 + row;
        const int b = gtok >> 11, t = gtok & (TT-1);
        float4 v = *(float4*)&sf[(size_t)row*132 + lane*4];
        v.x *= INV256; v.y *= INV256; v.z *= INV256; v.w *= INV256;   // weight descale
        float4 o;
        if (mode < 2) {
            float ss = v.x*v.x + v.y*v.y + v.z*v.z + v.w*v.w;
#pragma unroll
            for (int ofs = 16; ofs > 0; ofs >>= 1)
                ss += __shfl_xor_sync(0xffffffffu, ss, ofs);
            float inv = rsqrtf(ss*(1.0f/HD) + 1e-6f);
            v.x *= inv*sc4.x; v.y *= inv*sc4.y; v.z *= inv*sc4.z; v.w *= inv*sc4.w;
            float px = __shfl_xor_sync(0xffffffffu, v.x, 16);
            float py = __shfl_xor_sync(0xffffffffu, v.y, 16);
            float pz = __shfl_xor_sync(0xffffffffu, v.z, 16);
            float pw = __shfl_xor_sync(0xffffffffu, v.w, 16);
            float s = (lane < 16) ? -1.f : 1.f;
            float4 cs = *(const float4*)&cosT[(size_t)t*HD + lane*4];
            float4 sn = *(const float4*)&sinT[(size_t)t*HD + lane*4];
            o.x = (v.x*cs.x + s*px*sn.x) * smul;
            o.y = (v.y*cs.y + s*py*sn.y) * smul;
            o.z = (v.z*cs.z + s*pz*sn.z) * smul;
            o.w = (v.w*cs.w + s*pw*sn.w) * smul;
        } else {
            o = v;
        }
        uint32_t H0, L0, H1, L1;
        split2(o.x, o.y, H0, L0);
        split2(o.z, o.w, H1, L1);
        size_t off;
        if (mode < 2) off = (((size_t)(b*Hn + hloc))*TT + t)*HD + lane*4;
        else          off = (size_t)gtok*(HKV*HD) + hloc*HD + lane*4;
        *(uint2*)&outh[off] = make_uint2(H0, H1);
        *(uint2*)&outl[off] = make_uint2(L0, L1);
    }
}

// ---------------- O-projection GEMM (fp32 epilogue, descale) -----------------
__global__ __launch_bounds__(256, 2) void gemm_o(
    const __half* __restrict__ gA,
    const __half* __restrict__ gB0, const __half* __restrict__ gB1,
    float* __restrict__ C, int N)
{
    extern __shared__ __half sm[];
    const uint32_t sbase = (uint32_t)__cvta_generic_to_shared(sm);
    const int row0 = blockIdx.y * 128, col0 = blockIdx.x * 128;
    const int K = DD;
    const int niter = K / BKC;

    GEMM_PROLOGUE();
    GEMM_MAINLOOP();

    const int gr = lane >> 2, gc = (lane & 3) * 2;
#pragma unroll
    for (int mt = 0; mt < 2; mt++)
#pragma unroll
        for (int nt = 0; nt < 8; nt++) {
            int row = row0 + wm + mt*16 + gr;
            int col = col0 + wn + nt*8 + gc;
            *(float2*)&C[(size_t)row*N + col]     = make_float2(acc[mt][nt][0]*INV256, acc[mt][nt][1]*INV256);
            *(float2*)&C[(size_t)(row+8)*N + col] = make_float2(acc[mt][nt][2]*INV256, acc[mt][nt][3]*INV256);
        }
}

// ---------------- fused flash attention (bf16x3 QK^T and PV) ----------------
#define BQ 128
#define BK 64
#define FP 136
#define QELE (BQ*FP)
#define KELE (BK*FP)
#define QAREA (2*QELE)
#define STGKV (4*KELE)
#define FLASH_SMEM ((QAREA + 2*STGKV) * 2)

__global__ __launch_bounds__(256) void flash_kernel(
    const bf16* __restrict__ Qh, const bf16* __restrict__ Ql,
    const bf16* __restrict__ Kh, const bf16* __restrict__ Kl,
    const bf16* __restrict__ Vh, const bf16* __restrict__ Vl,
    __half* __restrict__ ctxh)
{
    extern __shared__ bf16 smf[];
    const int tid = threadIdx.x, lane = tid & 31, wid = tid >> 5;
    const int qb = gridDim.x - 1 - blockIdx.x;
    const int bh = blockIdx.y;
    const int b = bh >> 4, h = bh & 15, kv = h >> 1;
    const int q0 = qb * BQ;
    const uint32_t sbase = (uint32_t)__cvta_generic_to_shared(smf);

    const bf16* Qhg = Qh + ((size_t)(b*HQ  + h )*TT + q0)*HD;
    const bf16* Qlg = Ql + ((size_t)(b*HQ  + h )*TT + q0)*HD;
    const bf16* Khg = Kh + ((size_t)(b*HKV + kv)*TT)*HD;
    const bf16* Klg = Kl + ((size_t)(b*HKV + kv)*TT)*HD;
    const bf16* Vhg = Vh + (size_t)b*TT*(HKV*HD) + kv*HD;
    const bf16* Vlg = Vl + (size_t)b*TT*(HKV*HD) + kv*HD;

#pragma unroll
    for (int i = 0; i < 8; i++) {
        int c = tid + i*256;
        int row = c >> 4, col = (c & 15) * 8;
        cp_async16(sbase + (uint32_t)((row*FP + col) * 2),        Qhg + (size_t)row*HD + col);
        cp_async16(sbase + (uint32_t)((QELE + row*FP + col) * 2), Qlg + (size_t)row*HD + col);
    }

#define ISSUEKV(kt, stage) do {                                                     \
    const int k0_ = (kt) * BK;                                                      \
    const uint32_t kb_ = sbase + (uint32_t)((QAREA + (stage)*STGKV) * 2);           \
    _Pragma("unroll")                                                               \
    for (int i_ = 0; i_ < 4; i_++) {                                                \
        int c_ = tid + i_*256;                                                      \
        int row_ = c_ >> 4, col_ = (c_ & 15) * 8;                                   \
        uint32_t so_ = (uint32_t)((row_*FP + col_) * 2);                            \
        cp_async16(kb_ + so_,              Khg + (size_t)(k0_+row_)*HD + col_);     \
        cp_async16(kb_ + KELE*2 + so_,     Klg + (size_t)(k0_+row_)*HD + col_);     \
        cp_async16(kb_ + 2*KELE*2 + so_,   Vhg + (size_t)(k0_+row_)*(HKV*HD) + col_); \
        cp_async16(kb_ + 3*KELE*2 + so_,   Vlg + (size_t)(k0_+row_)*(HKV*HD) + col_); \
    }                                                                               \
} while (0)

    ISSUEKV(0, 0);
    cp_commit();

    const int r   = lane & 7, blkid = lane >> 3;
    const int a_row = ((blkid & 1) << 3) + r;
    const int a_col = (blkid >> 1) << 3;
    const int b_row = ((blkid >> 1) << 3) + r;
    const int b_col = (blkid & 1) << 3;
    const int gr = lane >> 2;

    float oacc[16][4];
#pragma unroll
    for (int i = 0; i < 16; i++)
#pragma unroll
        for (int j = 0; j < 4; j++) oacc[i][j] = 0.f;
    float m0 = -1e30f, m1 = -1e30f, l0 = 0.f, l1 = 0.f;

    const int row0g = q0 + wid*16 + gr;
    const int row1g = row0g + 8;
    const int nkt = 2*qb + 2;

    for (int kt = 0; kt < nkt; kt++) {
        if (kt + 1 < nkt) {
            ISSUEKV(kt + 1, (kt + 1) & 1);
            cp_commit();
            asm volatile("cp.async.wait_group 1;\n" ::: "memory");
        } else {
            asm volatile("cp.async.wait_group 0;\n" ::: "memory");
        }
        __syncthreads();

        const int k0 = kt * BK;
        const uint32_t kb_s = sbase + (uint32_t)((QAREA + (kt & 1)*STGKV) * 2);

        float sacc[8][4];
#pragma unroll
        for (int i = 0; i < 8; i++)
#pragma unroll
            for (int j = 0; j < 4; j++) sacc[i][j] = 0.f;

#pragma unroll
        for (int ks = 0; ks < 8; ks++) {
            uint32_t qa = sbase + (uint32_t)(((wid*16 + a_row)*FP + ks*16 + a_col) * 2);
            uint32_t qh[4], ql[4];
            ldsm4(qh, qa);
            ldsm4(ql, qa + QELE*2);
#pragma unroll
            for (int np = 0; np < 4; np++) {
                uint32_t ka = kb_s + (uint32_t)(((np*16 + b_row)*FP + ks*16 + b_col) * 2);
                uint32_t kh[4], kl[4];
                ldsm4(kh, ka);
                ldsm4(kl, ka + KELE*2);
                mma16816(sacc[2*np],   qh, &kh[0]);
                mma16816(sacc[2*np+1], qh, &kh[2]);
                mma16816(sacc[2*np],   qh, &kl[0]);
                mma16816(sacc[2*np+1], qh, &kl[2]);
                mma16816(sacc[2*np],   ql, &kh[0]);
                mma16816(sacc[2*np+1], ql, &kh[2]);
            }
        }

        float mx0 = -1e30f, mx1 = -1e30f;
#pragma unroll
        for (int nt = 0; nt < 8; nt++) {
            int cg = k0 + nt*8 + (lane & 3)*2;
            if (cg     > row0g) sacc[nt][0] = -1e30f;
            if (cg + 1 > row0g) sacc[nt][1] = -1e30f;
            if (cg     > row1g) sacc[nt][2] = -1e30f;
            if (cg + 1 > row1g) sacc[nt][3] = -1e30f;
            mx0 = fmaxf(mx0, fmaxf(sacc[nt][0], sacc[nt][1]));
            mx1 = fmaxf(mx1, fmaxf(sacc[nt][2], sacc[nt][3]));
        }
        mx0 = fmaxf(mx0, __shfl_xor_sync(0xffffffffu, mx0, 1));
        mx0 = fmaxf(mx0, __shfl_xor_sync(0xffffffffu, mx0, 2));
        mx1 = fmaxf(mx1, __shfl_xor_sync(0xffffffffu, mx1, 1));
        mx1 = fmaxf(mx1, __shfl_xor_sync(0xffffffffu, mx1, 2));

        float mn0 = fmaxf(m0, mx0), mn1 = fmaxf(m1, mx1);
        float sc0 = exp2f(m0 - mn0), sc1 = exp2f(m1 - mn1);
        m0 = mn0; m1 = mn1;

        float s0 = 0.f, s1 = 0.f;
#pragma unroll
        for (int nt = 0; nt < 8; nt++) {
            sacc[nt][0] = exp2f(sacc[nt][0] - m0);
            sacc[nt][1] = exp2f(sacc[nt][1] - m0);
            sacc[nt][2] = exp2f(sacc[nt][2] - m1);
            sacc[nt][3] = exp2f(sacc[nt][3] - m1);
            s0 += sacc[nt][0] + sacc[nt][1];
            s1 += sacc[nt][2] + sacc[nt][3];
        }
        s0 += __shfl_xor_sync(0xffffffffu, s0, 1);
        s0 += __shfl_xor_sync(0xffffffffu, s0, 2);
        s1 += __shfl_xor_sync(0xffffffffu, s1, 1);
        s1 += __shfl_xor_sync(0xffffffffu, s1, 2);
        l0 = l0*sc0 + s0;
        l1 = l1*sc1 + s1;

#pragma unroll
        for (int i = 0; i < 16; i++) {
            oacc[i][0] *= sc0; oacc[i][1] *= sc0;
            oacc[i][2] *= sc1; oacc[i][3] *= sc1;
        }

        const int vrow = (lane & 7) + ((lane >> 3) & 1)*8;
        const int vcolb = ((lane >> 4) << 3);
#pragma unroll
        for (int kp = 0; kp < 4; kp++) {
            uint32_t ph[4], pl[4];
#pragma unroll
            for (int half = 0; half < 2; half++) {
                float e0 = sacc[2*kp+half][0], e1 = sacc[2*kp+half][1];
                float e2 = sacc[2*kp+half][2], e3 = sacc[2*kp+half][3];
                bf16 b0 = __float2bfloat16(e0), b1 = __float2bfloat16(e1);
                bf16 b2 = __float2bfloat16(e2), b3 = __float2bfloat16(e3);
                ph[2*half]   = packbf(e0, e1);
                ph[2*half+1] = packbf(e2, e3);
                pl[2*half]   = packbf(e0 - __bfloat162float(b0), e1 - __bfloat162float(b1));
                pl[2*half+1] = packbf(e2 - __bfloat162float(b2), e3 - __bfloat162float(b3));
            }
#pragma unroll
            for (int np = 0; np < 8; np++) {
                uint32_t va = kb_s + (uint32_t)((2*KELE + (kp*16 + vrow)*FP + np*16 + vcolb) * 2);
                uint32_t vh[4], vl[4];
                ldsm4t(vh, va);
                ldsm4t(vl, va + KELE*2);
                mma16816(oacc[2*np],   ph, &vh[0]);
                mma16816(oacc[2*np+1], ph, &vh[2]);
                mma16816(oacc[2*np],   ph, &vl[0]);
                mma16816(oacc[2*np+1], ph, &vl[2]);
                mma16816(oacc[2*np],   pl, &vh[0]);
                mma16816(oacc[2*np+1], pl, &vh[2]);
            }
        }
        __syncthreads();
    }
#undef ISSUEKV

    // ---- epilogue: O /= l, write ctx fp16 single plane ----
    const float il0 = 1.f / l0, il1 = 1.f / l1;
    const size_t tok0 = (size_t)(b*TT + q0 + wid*16 + gr);
#pragma unroll
    for (int nt = 0; nt < 16; nt++) {
        int col = h*HD + nt*8 + (lane & 3)*2;
        *(uint32_t*)&ctxh[tok0*(HQ*HD) + col]     = packh(oacc[nt][0]*il0, oacc[nt][1]*il0);
        *(uint32_t*)&ctxh[(tok0+8)*(HQ*HD) + col] = packh(oacc[nt][2]*il1, oacc[nt][3]*il1);
    }
}

// ---------------- launch ------------------------------------------------------
extern "C" void kernel_launch(void* const* d_in, const int* in_sizes, int n_in,
                              void* d_out, int out_size)
{
    const float* x       = (const float*)d_in[0];
    const float* cosT    = (const float*)d_in[2];
    const float* sinT    = (const float*)d_in[3];
    const float* Wq      = (const float*)d_in[4];
    const float* Wk      = (const float*)d_in[5];
    const float* Wv      = (const float*)d_in[6];
    const float* Wo      = (const float*)d_in[7];
    const float* q_scale = (const float*)d_in[8];
    const float* k_scale = (const float*)d_in[9];
    float* out = (float*)d_out;

    __half *xh,*Wqh,*Wql,*Wkh,*Wkl,*Wvh,*Wvl,*Woh,*Wol,*ctxh;
    bf16 *Qh,*Ql,*Kh,*Kl,*Vh,*Vl;
    cudaGetSymbolAddress((void**)&xh,   g_xh);
    cudaGetSymbolAddress((void**)&Wqh,  g_Wqh);  cudaGetSymbolAddress((void**)&Wql,  g_Wql);
    cudaGetSymbolAddress((void**)&Wkh,  g_Wkh);  cudaGetSymbolAddress((void**)&Wkl,  g_Wkl);
    cudaGetSymbolAddress((void**)&Wvh,  g_Wvh);  cudaGetSymbolAddress((void**)&Wvl,  g_Wvl);
    cudaGetSymbolAddress((void**)&Woh,  g_Woh);  cudaGetSymbolAddress((void**)&Wol,  g_Wol);
    cudaGetSymbolAddress((void**)&Qh,   g_Qh);   cudaGetSymbolAddress((void**)&Ql,   g_Ql);
    cudaGetSymbolAddress((void**)&Kh,   g_Kh);   cudaGetSymbolAddress((void**)&Kl,   g_Kl);
    cudaGetSymbolAddress((void**)&Vh,   g_Vh);   cudaGetSymbolAddress((void**)&Vl,   g_Vl);
    cudaGetSymbolAddress((void**)&ctxh, g_ctxh);

    static bool attr_set = false;
    if (!attr_set) {
        cudaFuncSetAttribute(gemm_qkv,     cudaFuncAttributeMaxDynamicSharedMemorySize, GSMEM_QKV);
        cudaFuncSetAttribute(gemm_o,       cudaFuncAttributeMaxDynamicSharedMemorySize, GSMEM_O);
        cudaFuncSetAttribute(flash_kernel, cudaFuncAttributeMaxDynamicSharedMemorySize, FLASH_SMEM);
        attr_set = true;
    }

    // 0: operand conversion
    split_x_kernel<<<(MROWS*DD/4 + 255)/256, 256>>>((const float4*)x, xh, MROWS*DD/4);
    split_w_kernel<<<(HQ*HD*DD/4 + 255)/256, 256>>>((const float4*)Wq, Wqh, Wql, HQ*HD*DD/4);
    split_w_kernel<<<(HKV*HD*DD/4 + 255)/256, 256>>>((const float4*)Wk, Wkh, Wkl, HKV*HD*DD/4);
    split_w_kernel<<<(HKV*HD*DD/4 + 255)/256, 256>>>((const float4*)Wv, Wvh, Wvl, HKV*HD*DD/4);
    split_w_kernel<<<(DD*HQ*HD/4 + 255)/256, 256>>>((const float4*)Wo, Woh, Wol, DD*HQ*HD/4);

    // 1: merged QKV projection (fp16 2-mma) + fused RMSNorm/RoPE/split epilogue
    gemm_qkv<<<dim3(32, MROWS/128), 256, GSMEM_QKV>>>(
        xh, Wqh, Wql, Wkh, Wkl, Wvh, Wvl,
        Qh, Ql, Kh, Kl, Vh, Vl, q_scale, k_scale, cosT, sinT);

    // 2: fused flash attention (bf16x3, unchanged math)
    flash_kernel<<<dim3(TT/BQ, BB*HQ), 256, FLASH_SMEM>>>(Qh, Ql, Kh, Kl, Vh, Vl, ctxh);

    // 3: output projection (fp16 2-mma, descale)
    gemm_o<<<dim3(DD/128, MROWS/128), 256, GSMEM_O>>>(ctxh, Woh, Wol, out, DD);
}

// round 9
// speedup vs baseline: 2.9788x; 1.0731x over previous
#include <cuda_runtime.h>
#include <cuda_bf16.h>
#include <cuda_fp16.h>
#include <cstdint>
#include <cstddef>

// Problem constants
#define BB 2
#define TT 2048
#define DD 2048
#define HQ 16
#define HKV 8
#define HD 128
#define MROWS (BB*TT)   // 4096

typedef __nv_bfloat16 bf16;

// log2(e)/sqrt(128)
#define QSCALE 0.12752551164384637f
#define WSCALE 256.0f
#define INV256 0.00390625f

// ---------------- scratch (static device globals) ---------------------------
__device__ __half g_xh [(size_t)MROWS*DD];                      // single plane
__device__ __half g_Wqh[(size_t)HQ*HD*DD],  g_Wql[(size_t)HQ*HD*DD];
__device__ __half g_Wkh[(size_t)HKV*HD*DD], g_Wkl[(size_t)HKV*HD*DD];
__device__ __half g_Wvh[(size_t)HKV*HD*DD], g_Wvl[(size_t)HKV*HD*DD];
__device__ __half g_Woh[(size_t)DD*HQ*HD],  g_Wol[(size_t)DD*HQ*HD];
__device__ bf16 g_Qh [(size_t)BB*HQ*TT*HD],  g_Ql [(size_t)BB*HQ*TT*HD];
__device__ bf16 g_Kh [(size_t)BB*HKV*TT*HD], g_Kl [(size_t)BB*HKV*TT*HD];
__device__ __half g_Vh [(size_t)MROWS*HKV*HD], g_Vl [(size_t)MROWS*HKV*HD];
__device__ __half g_ctxh[(size_t)MROWS*HQ*HD];                  // single plane

// ---------------- PTX helpers ------------------------------------------------
__device__ __forceinline__ void ldsm4(uint32_t* r, uint32_t a) {
    asm volatile("ldmatrix.sync.aligned.m8n8.x4.shared.b16 {%0,%1,%2,%3}, [%4];\n"
        : "=r"(r[0]), "=r"(r[1]), "=r"(r[2]), "=r"(r[3]) : "r"(a));
}
__device__ __forceinline__ void ldsm4t(uint32_t* r, uint32_t a) {
    asm volatile("ldmatrix.sync.aligned.m8n8.x4.trans.shared.b16 {%0,%1,%2,%3}, [%4];\n"
        : "=r"(r[0]), "=r"(r[1]), "=r"(r[2]), "=r"(r[3]) : "r"(a));
}
__device__ __forceinline__ void mma16816(float* c, const uint32_t* a, const uint32_t* b) {
    asm volatile("mma.sync.aligned.m16n8k16.row.col.f32.bf16.bf16.f32 "
        "{%0,%1,%2,%3}, {%4,%5,%6,%7}, {%8,%9}, {%0,%1,%2,%3};\n"
        : "+f"(c[0]), "+f"(c[1]), "+f"(c[2]), "+f"(c[3])
        : "r"(a[0]), "r"(a[1]), "r"(a[2]), "r"(a[3]), "r"(b[0]), "r"(b[1]));
}
__device__ __forceinline__ void mma16816h(float* c, const uint32_t* a, const uint32_t* b) {
    asm volatile("mma.sync.aligned.m16n8k16.row.col.f32.f16.f16.f32 "
        "{%0,%1,%2,%3}, {%4,%5,%6,%7}, {%8,%9}, {%0,%1,%2,%3};\n"
        : "+f"(c[0]), "+f"(c[1]), "+f"(c[2]), "+f"(c[3])
        : "r"(a[0]), "r"(a[1]), "r"(a[2]), "r"(a[3]), "r"(b[0]), "r"(b[1]));
}
__device__ __forceinline__ void cp_async16(uint32_t dst, const void* src) {
    asm volatile("cp.async.ca.shared.global [%0], [%1], 16;\n" :: "r"(dst), "l"(src));
}
__device__ __forceinline__ void cp_commit() {
    asm volatile("cp.async.commit_group;\n" ::: "memory");
}
__device__ __forceinline__ uint32_t packbf(float a, float b) {
    __nv_bfloat162 t = __floats2bfloat162_rn(a, b);
    return *(uint32_t*)&t;
}
__device__ __forceinline__ uint32_t packh(float a, float b) {
    __half2 t = __floats2half2_rn(a, b);
    return *(uint32_t*)&t;
}
__device__ __forceinline__ void split2(float a, float b, uint32_t& h, uint32_t& l) {
    bf16 ha = __float2bfloat16(a), hb = __float2bfloat16(b);
    h = ((uint32_t)__bfloat16_as_ushort(hb) << 16) | (uint32_t)__bfloat16_as_ushort(ha);
    l = packbf(a - __bfloat162float(ha), b - __bfloat162float(hb));
}
__device__ __forceinline__ void split2h(float a, float b, uint32_t& h, uint32_t& l) {
    __half ha = __float2half_rn(a), hb = __float2half_rn(b);
    h = ((uint32_t)__half_as_ushort(hb) << 16) | (uint32_t)__half_as_ushort(ha);
    l = packh(a - __half2float(ha), b - __half2float(hb));
}

// ---------------- fused operand conversion (single launch) -------------------
// blocks [0,8192): x -> fp16 single plane
// blocks [8192,12288): Wq, [12288,14336): Wk, [14336,16384): Wv, [16384,20480): Wo
__global__ __launch_bounds__(256) void split_all_kernel(
    const float4* __restrict__ x,  const float4* __restrict__ Wq,
    const float4* __restrict__ Wk, const float4* __restrict__ Wv,
    const float4* __restrict__ Wo,
    __half* __restrict__ xh,
    __half* __restrict__ Wqh, __half* __restrict__ Wql,
    __half* __restrict__ Wkh, __half* __restrict__ Wkl,
    __half* __restrict__ Wvh, __half* __restrict__ Wvl,
    __half* __restrict__ Woh, __half* __restrict__ Wol)
{
    int blk = blockIdx.x;
    if (blk < 8192) {
        int i = blk*256 + threadIdx.x;
        float4 v = x[i];
        *(uint2*)(xh + (size_t)i*4) = make_uint2(packh(v.x, v.y), packh(v.z, v.w));
        return;
    }
    blk -= 8192;
    const float4* in; __half *hi, *lo;
    if (blk < 4096)      {                in = Wq; hi = Wqh; lo = Wql; }
    else if (blk < 6144) { blk -= 4096;   in = Wk; hi = Wkh; lo = Wkl; }
    else if (blk < 8192) { blk -= 6144;   in = Wv; hi = Wvh; lo = Wvl; }
    else                 { blk -= 8192;   in = Wo; hi = Woh; lo = Wol; }
    int i = blk*256 + threadIdx.x;
    float4 v = in[i];
    uint32_t h0, l0, h1, l1;
    split2h(v.x*WSCALE, v.y*WSCALE, h0, l0);
    split2h(v.z*WSCALE, v.w*WSCALE, h1, l1);
    *(uint2*)(hi + (size_t)i*4) = make_uint2(h0, h1);
    *(uint2*)(lo + (size_t)i*4) = make_uint2(l0, l1);
}

// ---------------- GEMM core macros (fp16 2-mma scheme) ------------------------
#define BKC 32
#define PAD 40
#define ARR (128*PAD)
#define STG3 (3*ARR)
#define GSMEM_O   (2*STG3*2)    // 61440
#define GSMEM_QKV 67584         // fp32 epilogue staging (128x132 f32)

#define GEMM_PROLOGUE()                                                         \
    const int tid  = threadIdx.x;                                               \
    const int lane = tid & 31, wid = tid >> 5;                                  \
    const int wm = (wid >> 1) * 32;                                             \
    const int wn = (wid & 1) * 64;                                              \
    const int m0 = tid >> 2;                                                    \
    const int c0 = (tid & 3) * 8;                                               \
    const int r_   = lane & 7, blk_ = lane >> 3;                                \
    const int a_row = ((blk_ & 1) << 3) + r_;                                   \
    const int a_col = (blk_ >> 1) << 3;                                         \
    const int b_row = ((blk_ >> 1) << 3) + r_;                                  \
    const int b_col = (blk_ & 1) << 3;                                          \
    float acc[2][8][4];                                                         \
    _Pragma("unroll") for (int i = 0; i < 2; i++)                               \
    _Pragma("unroll") for (int j = 0; j < 8; j++)                               \
    _Pragma("unroll") for (int k = 0; k < 4; k++) acc[i][j][k] = 0.f;

#define ISSUE(it, stage) do {                                                   \
    const int k0_ = (it) * BKC;                                                 \
    uint32_t sst_ = sbase + (uint32_t)(stage) * (STG3 * 2);                     \
    _Pragma("unroll")                                                           \
    for (int hh_ = 0; hh_ < 2; hh_++) {                                         \
        int m_ = m0 + hh_ * 64;                                                 \
        cp_async16(sst_ + (uint32_t)((m_*PAD + c0) * 2),                        \
                   gA + (size_t)(row0 + m_) * K + k0_ + c0);                    \
        cp_async16(sst_ + (uint32_t)((ARR + m_*PAD + c0) * 2),                  \
                   gB0 + (size_t)(col0 + m_) * K + k0_ + c0);                   \
        cp_async16(sst_ + (uint32_t)((2*ARR + m_*PAD + c0) * 2),                \
                   gB1 + (size_t)(col0 + m_) * K + k0_ + c0);                   \
    }                                                                           \
} while (0)

#define GEMM_MAINLOOP()                                                         \
    ISSUE(0, 0);                                                                \
    cp_commit();                                                                \
    for (int it = 0; it < niter; it++) {                                        \
        if (it + 1 < niter) {                                                   \
            ISSUE(it + 1, (it + 1) & 1);                                        \
            cp_commit();                                                        \
            asm volatile("cp.async.wait_group 1;\n" ::: "memory");              \
        } else {                                                                \
            asm volatile("cp.async.wait_group 0;\n" ::: "memory");              \
        }                                                                       \
        __syncthreads();                                                        \
        const uint32_t sst = sbase + (uint32_t)(it & 1) * (STG3 * 2);           \
        _Pragma("unroll")                                                       \
        for (int ks = 0; ks < 2; ks++) {                                        \
            const int kofs = ks * 16;                                           \
            uint32_t a_[2][4], bh_[4][4], bl_[4][4];                            \
            _Pragma("unroll")                                                   \
            for (int mt = 0; mt < 2; mt++)                                      \
                ldsm4(a_[mt], sst + (uint32_t)(((wm + mt*16 + a_row)*PAD + kofs + a_col) * 2)); \
            _Pragma("unroll")                                                   \
            for (int p = 0; p < 4; p++) {                                       \
                uint32_t addr = sst + (uint32_t)((ARR + (wn + p*16 + b_row)*PAD + kofs + b_col) * 2); \
                ldsm4(bh_[p], addr);                                            \
                ldsm4(bl_[p], addr + ARR * 2);                                  \
            }                                                                   \
            _Pragma("unroll")                                                   \
            for (int mt = 0; mt < 2; mt++)                                      \
            _Pragma("unroll")                                                   \
                for (int p = 0; p < 4; p++) {                                   \
                    mma16816h(acc[mt][2*p],   a_[mt], &bh_[p][0]);              \
                    mma16816h(acc[mt][2*p+1], a_[mt], &bh_[p][2]);              \
                    mma16816h(acc[mt][2*p],   a_[mt], &bl_[p][0]);              \
                    mma16816h(acc[mt][2*p+1], a_[mt], &bl_[p][2]);              \
                }                                                               \
        }                                                                       \
        __syncthreads();                                                        \
    }

// ---------------- merged QKV GEMM with fused norm/rope/split epilogue --------
// grid (32, MROWS/128): bx 0-15 -> Q head, 16-23 -> K head, 24-31 -> V head.
__global__ __launch_bounds__(256, 2) void gemm_qkv(
    const __half* __restrict__ gA,
    const __half* __restrict__ Wqh_, const __half* __restrict__ Wql_,
    const __half* __restrict__ Wkh_, const __half* __restrict__ Wkl_,
    const __half* __restrict__ Wvh_, const __half* __restrict__ Wvl_,
    bf16* __restrict__ Qh, bf16* __restrict__ Ql,
    bf16* __restrict__ Kh, bf16* __restrict__ Kl,
    __half* __restrict__ Vh, __half* __restrict__ Vl,
    const float* __restrict__ q_scale, const float* __restrict__ k_scale,
    const float* __restrict__ cosT, const float* __restrict__ sinT)
{
    extern __shared__ __half sm[];
    const uint32_t sbase = (uint32_t)__cvta_generic_to_shared(sm);
    const int bx = blockIdx.x;
    const int row0 = blockIdx.y * 128;
    const int K = DD;
    const int niter = K / BKC;

    int mode, hloc;
    const __half *gB0, *gB1;
    if (bx < 16)      { mode = 0; hloc = bx;      gB0 = Wqh_; gB1 = Wql_; }
    else if (bx < 24) { mode = 1; hloc = bx - 16; gB0 = Wkh_; gB1 = Wkl_; }
    else              { mode = 2; hloc = bx - 24; gB0 = Wvh_; gB1 = Wvl_; }
    const int col0 = hloc * 128;

    GEMM_PROLOGUE();
    GEMM_MAINLOOP();

    // ---- stage fp32 tile into smem (reuse pipeline smem) ----
    __syncthreads();
    float* sf = (float*)sm;                 // 128 x 132 floats = 67584 B
    const int gr = lane >> 2, gc = (lane & 3) * 2;
#pragma unroll
    for (int mt = 0; mt < 2; mt++)
#pragma unroll
        for (int nt = 0; nt < 8; nt++) {
            int row = wm + mt*16 + gr;
            int col = wn + nt*8 + gc;
            *(float2*)&sf[(size_t)row*132 + col]     = make_float2(acc[mt][nt][0], acc[mt][nt][1]);
            *(float2*)&sf[(size_t)(row+8)*132 + col] = make_float2(acc[mt][nt][2], acc[mt][nt][3]);
        }
    __syncthreads();

    const float* scv = (mode == 0) ? q_scale : k_scale;
    const float smul = (mode == 0) ? QSCALE : 1.0f;
    const int   Hn   = (mode == 0) ? HQ : HKV;
    bf16* outh = (mode == 0) ? Qh : Kh;
    bf16* outl = (mode == 0) ? Ql : Kl;

    float4 sc4 = make_float4(1.f,1.f,1.f,1.f);
    if (mode < 2) sc4 = *(const float4*)&scv[lane*4];

    for (int rr = 0; rr < 16; rr++) {
        const int row  = wid*16 + rr;
        const int gtok = row0 + row;
        const int b = gtok >> 11, t = gtok & (TT-1);
        float4 v = *(float4*)&sf[(size_t)row*132 + lane*4];
        v.x *= INV256; v.y *= INV256; v.z *= INV256; v.w *= INV256;   // weight descale
        if (mode < 2) {
            float ss = v.x*v.x + v.y*v.y + v.z*v.z + v.w*v.w;
#pragma unroll
            for (int ofs = 16; ofs > 0; ofs >>= 1)
                ss += __shfl_xor_sync(0xffffffffu, ss, ofs);
            float inv = rsqrtf(ss*(1.0f/HD) + 1e-6f);
            v.x *= inv*sc4.x; v.y *= inv*sc4.y; v.z *= inv*sc4.z; v.w *= inv*sc4.w;
            float px = __shfl_xor_sync(0xffffffffu, v.x, 16);
            float py = __shfl_xor_sync(0xffffffffu, v.y, 16);
            float pz = __shfl_xor_sync(0xffffffffu, v.z, 16);
            float pw = __shfl_xor_sync(0xffffffffu, v.w, 16);
            float s = (lane < 16) ? -1.f : 1.f;
            float4 cs = *(const float4*)&cosT[(size_t)t*HD + lane*4];
            float4 sn = *(const float4*)&sinT[(size_t)t*HD + lane*4];
            float4 o;
            o.x = (v.x*cs.x + s*px*sn.x) * smul;
            o.y = (v.y*cs.y + s*py*sn.y) * smul;
            o.z = (v.z*cs.z + s*pz*sn.z) * smul;
            o.w = (v.w*cs.w + s*pw*sn.w) * smul;
            uint32_t H0, L0, H1, L1;
            split2(o.x, o.y, H0, L0);
            split2(o.z, o.w, H1, L1);
            size_t off = (((size_t)(b*Hn + hloc))*TT + t)*HD + lane*4;
            *(uint2*)&outh[off] = make_uint2(H0, H1);
            *(uint2*)&outl[off] = make_uint2(L0, L1);
        } else {
            uint32_t H0, L0, H1, L1;
            split2h(v.x, v.y, H0, L0);
            split2h(v.z, v.w, H1, L1);
            size_t off = (size_t)gtok*(HKV*HD) + hloc*HD + lane*4;
            *(uint2*)&Vh[off] = make_uint2(H0, H1);
            *(uint2*)&Vl[off] = make_uint2(L0, L1);
        }
    }
}

// ---------------- O-projection GEMM (fp32 epilogue, descale) -----------------
__global__ __launch_bounds__(256, 2) void gemm_o(
    const __half* __restrict__ gA,
    const __half* __restrict__ gB0, const __half* __restrict__ gB1,
    float* __restrict__ C, int N)
{
    extern __shared__ __half sm[];
    const uint32_t sbase = (uint32_t)__cvta_generic_to_shared(sm);
    const int row0 = blockIdx.y * 128, col0 = blockIdx.x * 128;
    const int K = DD;
    const int niter = K / BKC;

    GEMM_PROLOGUE();
    GEMM_MAINLOOP();

    const int gr = lane >> 2, gc = (lane & 3) * 2;
#pragma unroll
    for (int mt = 0; mt < 2; mt++)
#pragma unroll
        for (int nt = 0; nt < 8; nt++) {
            int row = row0 + wm + mt*16 + gr;
            int col = col0 + wn + nt*8 + gc;
            *(float2*)&C[(size_t)row*N + col]     = make_float2(acc[mt][nt][0]*INV256, acc[mt][nt][1]*INV256);
            *(float2*)&C[(size_t)(row+8)*N + col] = make_float2(acc[mt][nt][2]*INV256, acc[mt][nt][3]*INV256);
        }
}

// ---------------- fused flash attention -------------------------------------
// QK^T: bf16x3 (accuracy-critical). PV: fp16 2-mma (P single plane, V hi/lo).
#define BQ 128
#define BK 64
#define FP 136
#define QELE (BQ*FP)
#define KELE (BK*FP)
#define QAREA (2*QELE)
#define STGKV (4*KELE)
#define FLASH_SMEM ((QAREA + 2*STGKV) * 2)

__global__ __launch_bounds__(256) void flash_kernel(
    const bf16* __restrict__ Qh, const bf16* __restrict__ Ql,
    const bf16* __restrict__ Kh, const bf16* __restrict__ Kl,
    const __half* __restrict__ Vh, const __half* __restrict__ Vl,
    __half* __restrict__ ctxh)
{
    extern __shared__ bf16 smf[];
    const int tid = threadIdx.x, lane = tid & 31, wid = tid >> 5;
    const int qb = gridDim.x - 1 - blockIdx.x;
    const int bh = blockIdx.y;
    const int b = bh >> 4, h = bh & 15, kv = h >> 1;
    const int q0 = qb * BQ;
    const uint32_t sbase = (uint32_t)__cvta_generic_to_shared(smf);

    const bf16* Qhg = Qh + ((size_t)(b*HQ  + h )*TT + q0)*HD;
    const bf16* Qlg = Ql + ((size_t)(b*HQ  + h )*TT + q0)*HD;
    const bf16* Khg = Kh + ((size_t)(b*HKV + kv)*TT)*HD;
    const bf16* Klg = Kl + ((size_t)(b*HKV + kv)*TT)*HD;
    const __half* Vhg = Vh + (size_t)b*TT*(HKV*HD) + kv*HD;
    const __half* Vlg = Vl + (size_t)b*TT*(HKV*HD) + kv*HD;

#pragma unroll
    for (int i = 0; i < 8; i++) {
        int c = tid + i*256;
        int row = c >> 4, col = (c & 15) * 8;
        cp_async16(sbase + (uint32_t)((row*FP + col) * 2),        Qhg + (size_t)row*HD + col);
        cp_async16(sbase + (uint32_t)((QELE + row*FP + col) * 2), Qlg + (size_t)row*HD + col);
    }

#define ISSUEKV(kt, stage) do {                                                     \
    const int k0_ = (kt) * BK;                                                      \
    const uint32_t kb_ = sbase + (uint32_t)((QAREA + (stage)*STGKV) * 2);           \
    _Pragma("unroll")                                                               \
    for (int i_ = 0; i_ < 4; i_++) {                                                \
        int c_ = tid + i_*256;                                                      \
        int row_ = c_ >> 4, col_ = (c_ & 15) * 8;                                   \
        uint32_t so_ = (uint32_t)((row_*FP + col_) * 2);                            \
        cp_async16(kb_ + so_,              Khg + (size_t)(k0_+row_)*HD + col_);     \
        cp_async16(kb_ + KELE*2 + so_,     Klg + (size_t)(k0_+row_)*HD + col_);     \
        cp_async16(kb_ + 2*KELE*2 + so_,   Vhg + (size_t)(k0_+row_)*(HKV*HD) + col_); \
        cp_async16(kb_ + 3*KELE*2 + so_,   Vlg + (size_t)(k0_+row_)*(HKV*HD) + col_); \
    }                                                                               \
} while (0)

    ISSUEKV(0, 0);
    cp_commit();

    const int r   = lane & 7, blkid = lane >> 3;
    const int a_row = ((blkid & 1) << 3) + r;
    const int a_col = (blkid >> 1) << 3;
    const int b_row = ((blkid >> 1) << 3) + r;
    const int b_col = (blkid & 1) << 3;
    const int gr = lane >> 2;

    float oacc[16][4];
#pragma unroll
    for (int i = 0; i < 16; i++)
#pragma unroll
        for (int j = 0; j < 4; j++) oacc[i][j] = 0.f;
    float m0 = -1e30f, m1 = -1e30f, l0 = 0.f, l1 = 0.f;

    const int row0g = q0 + wid*16 + gr;
    const int row1g = row0g + 8;
    const int rowmin = q0 + wid*16;
    const int nkt = 2*qb + 2;

    for (int kt = 0; kt < nkt; kt++) {
        if (kt + 1 < nkt) {
            ISSUEKV(kt + 1, (kt + 1) & 1);
            cp_commit();
            asm volatile("cp.async.wait_group 1;\n" ::: "memory");
        } else {
            asm volatile("cp.async.wait_group 0;\n" ::: "memory");
        }
        __syncthreads();

        const int k0 = kt * BK;
        const uint32_t kb_s = sbase + (uint32_t)((QAREA + (kt & 1)*STGKV) * 2);

        float sacc[8][4];
#pragma unroll
        for (int i = 0; i < 8; i++)
#pragma unroll
            for (int j = 0; j < 4; j++) sacc[i][j] = 0.f;

#pragma unroll
        for (int ks = 0; ks < 8; ks++) {
            uint32_t qa = sbase + (uint32_t)(((wid*16 + a_row)*FP + ks*16 + a_col) * 2);
            uint32_t qh[4], ql[4];
            ldsm4(qh, qa);
            ldsm4(ql, qa + QELE*2);
#pragma unroll
            for (int np = 0; np < 4; np++) {
                uint32_t ka = kb_s + (uint32_t)(((np*16 + b_row)*FP + ks*16 + b_col) * 2);
                uint32_t kh[4], kl[4];
                ldsm4(kh, ka);
                ldsm4(kl, ka + KELE*2);
                mma16816(sacc[2*np],   qh, &kh[0]);
                mma16816(sacc[2*np+1], qh, &kh[2]);
                mma16816(sacc[2*np],   qh, &kl[0]);
                mma16816(sacc[2*np+1], qh, &kl[2]);
                mma16816(sacc[2*np],   ql, &kh[0]);
                mma16816(sacc[2*np+1], ql, &kh[2]);
            }
        }

        // ---- causal mask (only near diagonal) + online softmax ----
        float mx0 = -1e30f, mx1 = -1e30f;
        if (k0 + 63 > rowmin) {
#pragma unroll
            for (int nt = 0; nt < 8; nt++) {
                int cg = k0 + nt*8 + (lane & 3)*2;
                if (cg     > row0g) sacc[nt][0] = -1e30f;
                if (cg + 1 > row0g) sacc[nt][1] = -1e30f;
                if (cg     > row1g) sacc[nt][2] = -1e30f;
                if (cg + 1 > row1g) sacc[nt][3] = -1e30f;
                mx0 = fmaxf(mx0, fmaxf(sacc[nt][0], sacc[nt][1]));
                mx1 = fmaxf(mx1, fmaxf(sacc[nt][2], sacc[nt][3]));
            }
        } else {
#pragma unroll
            for (int nt = 0; nt < 8; nt++) {
                mx0 = fmaxf(mx0, fmaxf(sacc[nt][0], sacc[nt][1]));
                mx1 = fmaxf(mx1, fmaxf(sacc[nt][2], sacc[nt][3]));
            }
        }
        mx0 = fmaxf(mx0, __shfl_xor_sync(0xffffffffu, mx0, 1));
        mx0 = fmaxf(mx0, __shfl_xor_sync(0xffffffffu, mx0, 2));
        mx1 = fmaxf(mx1, __shfl_xor_sync(0xffffffffu, mx1, 1));
        mx1 = fmaxf(mx1, __shfl_xor_sync(0xffffffffu, mx1, 2));

        float mn0 = fmaxf(m0, mx0), mn1 = fmaxf(m1, mx1);
        float sc0 = exp2f(m0 - mn0), sc1 = exp2f(m1 - mn1);
        m0 = mn0; m1 = mn1;

        float s0 = 0.f, s1 = 0.f;
#pragma unroll
        for (int nt = 0; nt < 8; nt++) {
            sacc[nt][0] = exp2f(sacc[nt][0] - m0);
            sacc[nt][1] = exp2f(sacc[nt][1] - m0);
            sacc[nt][2] = exp2f(sacc[nt][2] - m1);
            sacc[nt][3] = exp2f(sacc[nt][3] - m1);
            s0 += sacc[nt][0] + sacc[nt][1];
            s1 += sacc[nt][2] + sacc[nt][3];
        }
        s0 += __shfl_xor_sync(0xffffffffu, s0, 1);
        s0 += __shfl_xor_sync(0xffffffffu, s0, 2);
        s1 += __shfl_xor_sync(0xffffffffu, s1, 1);
        s1 += __shfl_xor_sync(0xffffffffu, s1, 2);
        l0 = l0*sc0 + s0;
        l1 = l1*sc1 + s1;

#pragma unroll
        for (int i = 0; i < 16; i++) {
            oacc[i][0] *= sc0; oacc[i][1] *= sc0;
            oacc[i][2] *= sc1; oacc[i][3] *= sc1;
        }

        // ---- O += P V (fp16 2-mma: P single plane, V hi/lo) ----
        const int vrow = (lane & 7) + ((lane >> 3) & 1)*8;
        const int vcolb = ((lane >> 4) << 3);
#pragma unroll
        for (int kp = 0; kp < 4; kp++) {
            uint32_t ph[4];
#pragma unroll
            for (int half = 0; half < 2; half++) {
                ph[2*half]   = packh(sacc[2*kp+half][0], sacc[2*kp+half][1]);
                ph[2*half+1] = packh(sacc[2*kp+half][2], sacc[2*kp+half][3]);
            }
#pragma unroll
            for (int np = 0; np < 8; np++) {
                uint32_t va = kb_s + (uint32_t)((2*KELE + (kp*16 + vrow)*FP + np*16 + vcolb) * 2);
                uint32_t vh[4], vl[4];
                ldsm4t(vh, va);
                ldsm4t(vl, va + KELE*2);
                mma16816h(oacc[2*np],   ph, &vh[0]);
                mma16816h(oacc[2*np+1], ph, &vh[2]);
                mma16816h(oacc[2*np],   ph, &vl[0]);
                mma16816h(oacc[2*np+1], ph, &vl[2]);
            }
        }
        __syncthreads();
    }
#undef ISSUEKV

    // ---- epilogue: O /= l, write ctx fp16 single plane ----
    const float il0 = 1.f / l0, il1 = 1.f / l1;
    const size_t tok0 = (size_t)(b*TT + q0 + wid*16 + gr);
#pragma unroll
    for (int nt = 0; nt < 16; nt++) {
        int col = h*HD + nt*8 + (lane & 3)*2;
        *(uint32_t*)&ctxh[tok0*(HQ*HD) + col]     = packh(oacc[nt][0]*il0, oacc[nt][1]*il0);
        *(uint32_t*)&ctxh[(tok0+8)*(HQ*HD) + col] = packh(oacc[nt][2]*il1, oacc[nt][3]*il1);
    }
}

// ---------------- launch ------------------------------------------------------
extern "C" void kernel_launch(void* const* d_in, const int* in_sizes, int n_in,
                              void* d_out, int out_size)
{
    const float* x       = (const float*)d_in[0];
    const float* cosT    = (const float*)d_in[2];
    const float* sinT    = (const float*)d_in[3];
    const float* Wq      = (const float*)d_in[4];
    const float* Wk      = (const float*)d_in[5];
    const float* Wv      = (const float*)d_in[6];
    const float* Wo      = (const float*)d_in[7];
    const float* q_scale = (const float*)d_in[8];
    const float* k_scale = (const float*)d_in[9];
    float* out = (float*)d_out;

    __half *xh,*Wqh,*Wql,*Wkh,*Wkl,*Wvh,*Wvl,*Woh,*Wol,*ctxh,*Vh,*Vl;
    bf16 *Qh,*Ql,*Kh,*Kl;
    cudaGetSymbolAddress((void**)&xh,   g_xh);
    cudaGetSymbolAddress((void**)&Wqh,  g_Wqh);  cudaGetSymbolAddress((void**)&Wql,  g_Wql);
    cudaGetSymbolAddress((void**)&Wkh,  g_Wkh);  cudaGetSymbolAddress((void**)&Wkl,  g_Wkl);
    cudaGetSymbolAddress((void**)&Wvh,  g_Wvh);  cudaGetSymbolAddress((void**)&Wvl,  g_Wvl);
    cudaGetSymbolAddress((void**)&Woh,  g_Woh);  cudaGetSymbolAddress((void**)&Wol,  g_Wol);
    cudaGetSymbolAddress((void**)&Qh,   g_Qh);   cudaGetSymbolAddress((void**)&Ql,   g_Ql);
    cudaGetSymbolAddress((void**)&Kh,   g_Kh);   cudaGetSymbolAddress((void**)&Kl,   g_Kl);
    cudaGetSymbolAddress((void**)&Vh,   g_Vh);   cudaGetSymbolAddress((void**)&Vl,   g_Vl);
    cudaGetSymbolAddress((void**)&ctxh, g_ctxh);

    static bool attr_set = false;
    if (!attr_set) {
        cudaFuncSetAttribute(gemm_qkv,     cudaFuncAttributeMaxDynamicSharedMemorySize, GSMEM_QKV);
        cudaFuncSetAttribute(gemm_o,       cudaFuncAttributeMaxDynamicSharedMemorySize, GSMEM_O);
        cudaFuncSetAttribute(flash_kernel, cudaFuncAttributeMaxDynamicSharedMemorySize, FLASH_SMEM);
        attr_set = true;
    }

    // 0: all operand conversions in one launch (20480 blocks)
    split_all_kernel<<<20480, 256>>>(
        (const float4*)x, (const float4*)Wq, (const float4*)Wk,
        (const float4*)Wv, (const float4*)Wo,
        xh, Wqh, Wql, Wkh, Wkl, Wvh, Wvl, Woh, Wol);

    // 1: merged QKV projection (fp16 2-mma) + fused RMSNorm/RoPE/split epilogue
    gemm_qkv<<<dim3(32, MROWS/128), 256, GSMEM_QKV>>>(
        xh, Wqh, Wql, Wkh, Wkl, Wvh, Wvl,
        Qh, Ql, Kh, Kl, Vh, Vl, q_scale, k_scale, cosT, sinT);

    // 2: fused flash attention (QK bf16x3, PV fp16 2-mma)
    flash_kernel<<<dim3(TT/BQ, BB*HQ), 256, FLASH_SMEM>>>(Qh, Ql, Kh, Kl, Vh, Vl, ctxh);

    // 3: output projection (fp16 2-mma, descale)
    gemm_o<<<dim3(DD/128, MROWS/128), 256, GSMEM_O>>>(ctxh, Woh, Wol, out, DD);
}

// round 10
// speedup vs baseline: 3.0700x; 1.0306x over previous
#include <cuda_runtime.h>
#include <cuda_bf16.h>
#include <cuda_fp16.h>
#include <cstdint>
#include <cstddef>

// Problem constants
#define BB 2
#define TT 2048
#define DD 2048
#define HQ 16
#define HKV 8
#define HD 128
#define MROWS (BB*TT)   // 4096

typedef __nv_bfloat16 bf16;

// log2(e)/sqrt(128)
#define QSCALE 0.12752551164384637f
#define WSCALE 256.0f
#define INV256 0.00390625f

// ---------------- scratch (static device globals) ---------------------------
__device__ __half g_xh [(size_t)MROWS*DD];                      // single plane
__device__ __half g_Wqh[(size_t)HQ*HD*DD],  g_Wql[(size_t)HQ*HD*DD];
__device__ __half g_Wkh[(size_t)HKV*HD*DD], g_Wkl[(size_t)HKV*HD*DD];
__device__ __half g_Wvh[(size_t)HKV*HD*DD], g_Wvl[(size_t)HKV*HD*DD];
__device__ __half g_Woh[(size_t)DD*HQ*HD],  g_Wol[(size_t)DD*HQ*HD];
__device__ bf16 g_Qh [(size_t)BB*HQ*TT*HD],  g_Ql [(size_t)BB*HQ*TT*HD];
__device__ bf16 g_Kh [(size_t)BB*HKV*TT*HD], g_Kl [(size_t)BB*HKV*TT*HD];
__device__ __half g_Vh [(size_t)MROWS*HKV*HD];                  // single plane
__device__ __half g_ctxh[(size_t)MROWS*HQ*HD];                  // single plane

// ---------------- PTX helpers ------------------------------------------------
__device__ __forceinline__ void ldsm4(uint32_t* r, uint32_t a) {
    asm volatile("ldmatrix.sync.aligned.m8n8.x4.shared.b16 {%0,%1,%2,%3}, [%4];\n"
        : "=r"(r[0]), "=r"(r[1]), "=r"(r[2]), "=r"(r[3]) : "r"(a));
}
__device__ __forceinline__ void ldsm4t(uint32_t* r, uint32_t a) {
    asm volatile("ldmatrix.sync.aligned.m8n8.x4.trans.shared.b16 {%0,%1,%2,%3}, [%4];\n"
        : "=r"(r[0]), "=r"(r[1]), "=r"(r[2]), "=r"(r[3]) : "r"(a));
}
__device__ __forceinline__ void mma16816(float* c, const uint32_t* a, const uint32_t* b) {
    asm volatile("mma.sync.aligned.m16n8k16.row.col.f32.bf16.bf16.f32 "
        "{%0,%1,%2,%3}, {%4,%5,%6,%7}, {%8,%9}, {%0,%1,%2,%3};\n"
        : "+f"(c[0]), "+f"(c[1]), "+f"(c[2]), "+f"(c[3])
        : "r"(a[0]), "r"(a[1]), "r"(a[2]), "r"(a[3]), "r"(b[0]), "r"(b[1]));
}
__device__ __forceinline__ void mma16816h(float* c, const uint32_t* a, const uint32_t* b) {
    asm volatile("mma.sync.aligned.m16n8k16.row.col.f32.f16.f16.f32 "
        "{%0,%1,%2,%3}, {%4,%5,%6,%7}, {%8,%9}, {%0,%1,%2,%3};\n"
        : "+f"(c[0]), "+f"(c[1]), "+f"(c[2]), "+f"(c[3])
        : "r"(a[0]), "r"(a[1]), "r"(a[2]), "r"(a[3]), "r"(b[0]), "r"(b[1]));
}
__device__ __forceinline__ void cp_async16(uint32_t dst, const void* src) {
    asm volatile("cp.async.ca.shared.global [%0], [%1], 16;\n" :: "r"(dst), "l"(src));
}
__device__ __forceinline__ void cp_commit() {
    asm volatile("cp.async.commit_group;\n" ::: "memory");
}
__device__ __forceinline__ uint32_t packbf(float a, float b) {
    __nv_bfloat162 t = __floats2bfloat162_rn(a, b);
    return *(uint32_t*)&t;
}
__device__ __forceinline__ uint32_t packh(float a, float b) {
    __half2 t = __floats2half2_rn(a, b);
    return *(uint32_t*)&t;
}
__device__ __forceinline__ void split2(float a, float b, uint32_t& h, uint32_t& l) {
    bf16 ha = __float2bfloat16(a), hb = __float2bfloat16(b);
    h = ((uint32_t)__bfloat16_as_ushort(hb) << 16) | (uint32_t)__bfloat16_as_ushort(ha);
    l = packbf(a - __bfloat162float(ha), b - __bfloat162float(hb));
}
__device__ __forceinline__ void split2h(float a, float b, uint32_t& h, uint32_t& l) {
    __half ha = __float2half_rn(a), hb = __float2half_rn(b);
    h = ((uint32_t)__half_as_ushort(hb) << 16) | (uint32_t)__half_as_ushort(ha);
    l = packh(a - __half2float(ha), b - __half2float(hb));
}

// ---------------- fused operand conversion (single launch) -------------------
__global__ __launch_bounds__(256) void split_all_kernel(
    const float4* __restrict__ x,  const float4* __restrict__ Wq,
    const float4* __restrict__ Wk, const float4* __restrict__ Wv,
    const float4* __restrict__ Wo,
    __half* __restrict__ xh,
    __half* __restrict__ Wqh, __half* __restrict__ Wql,
    __half* __restrict__ Wkh, __half* __restrict__ Wkl,
    __half* __restrict__ Wvh, __half* __restrict__ Wvl,
    __half* __restrict__ Woh, __half* __restrict__ Wol)
{
    int blk = blockIdx.x;
    if (blk < 8192) {
        int i = blk*256 + threadIdx.x;
        float4 v = x[i];
        *(uint2*)(xh + (size_t)i*4) = make_uint2(packh(v.x, v.y), packh(v.z, v.w));
        return;
    }
    blk -= 8192;
    const float4* in; __half *hi, *lo;
    if (blk < 4096)      {                in = Wq; hi = Wqh; lo = Wql; }
    else if (blk < 6144) { blk -= 4096;   in = Wk; hi = Wkh; lo = Wkl; }
    else if (blk < 8192) { blk -= 6144;   in = Wv; hi = Wvh; lo = Wvl; }
    else                 { blk -= 8192;   in = Wo; hi = Woh; lo = Wol; }
    int i = blk*256 + threadIdx.x;
    float4 v = in[i];
    uint32_t h0, l0, h1, l1;
    split2h(v.x*WSCALE, v.y*WSCALE, h0, l0);
    split2h(v.z*WSCALE, v.w*WSCALE, h1, l1);
    *(uint2*)(hi + (size_t)i*4) = make_uint2(h0, h1);
    *(uint2*)(lo + (size_t)i*4) = make_uint2(l0, l1);
}

// ---------------- GEMM core macros (fp16 2-mma, 3-stage pipeline) ------------
#define BKC 32
#define PAD 40
#define ARR (128*PAD)
#define STG3 (3*ARR)
#define GSMEM (3*STG3*2)        // 92160 bytes (3 stages)

#define GEMM_PROLOGUE()                                                         \
    const int tid  = threadIdx.x;                                               \
    const int lane = tid & 31, wid = tid >> 5;                                  \
    const int wm = (wid >> 1) * 32;                                             \
    const int wn = (wid & 1) * 64;                                              \
    const int m0 = tid >> 2;                                                    \
    const int c0 = (tid & 3) * 8;                                               \
    const int r_   = lane & 7, blk_ = lane >> 3;                                \
    const int a_row = ((blk_ & 1) << 3) + r_;                                   \
    const int a_col = (blk_ >> 1) << 3;                                         \
    const int b_row = ((blk_ >> 1) << 3) + r_;                                  \
    const int b_col = (blk_ & 1) << 3;                                          \
    float acc[2][8][4];                                                         \
    _Pragma("unroll") for (int i = 0; i < 2; i++)                               \
    _Pragma("unroll") for (int j = 0; j < 8; j++)                               \
    _Pragma("unroll") for (int k = 0; k < 4; k++) acc[i][j][k] = 0.f;

#define ISSUE(it, stage) do {                                                   \
    const int k0_ = (it) * BKC;                                                 \
    uint32_t sst_ = sbase + (uint32_t)(stage) * (STG3 * 2);                     \
    _Pragma("unroll")                                                           \
    for (int hh_ = 0; hh_ < 2; hh_++) {                                         \
        int m_ = m0 + hh_ * 64;                                                 \
        cp_async16(sst_ + (uint32_t)((m_*PAD + c0) * 2),                        \
                   gA + (size_t)(row0 + m_) * K + k0_ + c0);                    \
        cp_async16(sst_ + (uint32_t)((ARR + m_*PAD + c0) * 2),                  \
                   gB0 + (size_t)(col0 + m_) * K + k0_ + c0);                   \
        cp_async16(sst_ + (uint32_t)((2*ARR + m_*PAD + c0) * 2),                \
                   gB1 + (size_t)(col0 + m_) * K + k0_ + c0);                   \
    }                                                                           \
} while (0)

#define GEMM_MAINLOOP()                                                         \
    ISSUE(0, 0);                                                                \
    cp_commit();                                                                \
    ISSUE(1, 1);                                                                \
    cp_commit();                                                                \
    int stg = 0;                                                                \
    for (int it = 0; it < niter; it++) {                                        \
        if (it + 2 < niter) {                                                   \
            int s2 = stg + 2; if (s2 >= 3) s2 -= 3;                             \
            ISSUE(it + 2, s2);                                                  \
            cp_commit();                                                        \
            asm volatile("cp.async.wait_group 2;\n" ::: "memory");              \
        } else if (it + 1 < niter) {                                            \
            asm volatile("cp.async.wait_group 1;\n" ::: "memory");              \
        } else {                                                                \
            asm volatile("cp.async.wait_group 0;\n" ::: "memory");              \
        }                                                                       \
        __syncthreads();                                                        \
        const uint32_t sst = sbase + (uint32_t)stg * (STG3 * 2);                \
        _Pragma("unroll")                                                       \
        for (int ks = 0; ks < 2; ks++) {                                        \
            const int kofs = ks * 16;                                           \
            uint32_t a_[2][4], bh_[4][4], bl_[4][4];                            \
            _Pragma("unroll")                                                   \
            for (int mt = 0; mt < 2; mt++)                                      \
                ldsm4(a_[mt], sst + (uint32_t)(((wm + mt*16 + a_row)*PAD + kofs + a_col) * 2)); \
            _Pragma("unroll")                                                   \
            for (int p = 0; p < 4; p++) {                                       \
                uint32_t addr = sst + (uint32_t)((ARR + (wn + p*16 + b_row)*PAD + kofs + b_col) * 2); \
                ldsm4(bh_[p], addr);                                            \
                ldsm4(bl_[p], addr + ARR * 2);                                  \
            }                                                                   \
            _Pragma("unroll")                                                   \
            for (int mt = 0; mt < 2; mt++)                                      \
            _Pragma("unroll")                                                   \
                for (int p = 0; p < 4; p++) {                                   \
                    mma16816h(acc[mt][2*p],   a_[mt], &bh_[p][0]);              \
                    mma16816h(acc[mt][2*p+1], a_[mt], &bh_[p][2]);              \
                    mma16816h(acc[mt][2*p],   a_[mt], &bl_[p][0]);              \
                    mma16816h(acc[mt][2*p+1], a_[mt], &bl_[p][2]);              \
                }                                                               \
        }                                                                       \
        __syncthreads();                                                        \
        if (++stg == 3) stg = 0;                                                \
    }

// ---------------- merged QKV GEMM with fused norm/rope/split epilogue --------
__global__ __launch_bounds__(256, 2) void gemm_qkv(
    const __half* __restrict__ gA,
    const __half* __restrict__ Wqh_, const __half* __restrict__ Wql_,
    const __half* __restrict__ Wkh_, const __half* __restrict__ Wkl_,
    const __half* __restrict__ Wvh_, const __half* __restrict__ Wvl_,
    bf16* __restrict__ Qh, bf16* __restrict__ Ql,
    bf16* __restrict__ Kh, bf16* __restrict__ Kl,
    __half* __restrict__ Vh,
    const float* __restrict__ q_scale, const float* __restrict__ k_scale,
    const float* __restrict__ cosT, const float* __restrict__ sinT)
{
    extern __shared__ __half sm[];
    const uint32_t sbase = (uint32_t)__cvta_generic_to_shared(sm);
    const int bx = blockIdx.x;
    const int row0 = blockIdx.y * 128;
    const int K = DD;
    const int niter = K / BKC;

    int mode, hloc;
    const __half *gB0, *gB1;
    if (bx < 16)      { mode = 0; hloc = bx;      gB0 = Wqh_; gB1 = Wql_; }
    else if (bx < 24) { mode = 1; hloc = bx - 16; gB0 = Wkh_; gB1 = Wkl_; }
    else              { mode = 2; hloc = bx - 24; gB0 = Wvh_; gB1 = Wvl_; }
    const int col0 = hloc * 128;

    GEMM_PROLOGUE();
    GEMM_MAINLOOP();

    // ---- stage fp32 tile into smem (reuse pipeline smem) ----
    __syncthreads();
    float* sf = (float*)sm;                 // 128 x 132 floats = 67584 B <= 92160
    const int gr = lane >> 2, gc = (lane & 3) * 2;
#pragma unroll
    for (int mt = 0; mt < 2; mt++)
#pragma unroll
        for (int nt = 0; nt < 8; nt++) {
            int row = wm + mt*16 + gr;
            int col = wn + nt*8 + gc;
            *(float2*)&sf[(size_t)row*132 + col]     = make_float2(acc[mt][nt][0], acc[mt][nt][1]);
            *(float2*)&sf[(size_t)(row+8)*132 + col] = make_float2(acc[mt][nt][2], acc[mt][nt][3]);
        }
    __syncthreads();

    const float* scv = (mode == 0) ? q_scale : k_scale;
    const float smul = (mode == 0) ? QSCALE : 1.0f;
    const int   Hn   = (mode == 0) ? HQ : HKV;
    bf16* outh = (mode == 0) ? Qh : Kh;
    bf16* outl = (mode == 0) ? Ql : Kl;

    float4 sc4 = make_float4(1.f,1.f,1.f,1.f);
    if (mode < 2) sc4 = *(const float4*)&scv[lane*4];

    for (int rr = 0; rr < 16; rr++) {
        const int row  = wid*16 + rr;
        const int gtok = row0 + row;
        const int b = gtok >> 11, t = gtok & (TT-1);
        float4 v = *(float4*)&sf[(size_t)row*132 + lane*4];
        v.x *= INV256; v.y *= INV256; v.z *= INV256; v.w *= INV256;   // weight descale
        if (mode < 2) {
            float ss = v.x*v.x + v.y*v.y + v.z*v.z + v.w*v.w;
#pragma unroll
            for (int ofs = 16; ofs > 0; ofs >>= 1)
                ss += __shfl_xor_sync(0xffffffffu, ss, ofs);
            float inv = rsqrtf(ss*(1.0f/HD) + 1e-6f);
            v.x *= inv*sc4.x; v.y *= inv*sc4.y; v.z *= inv*sc4.z; v.w *= inv*sc4.w;
            float px = __shfl_xor_sync(0xffffffffu, v.x, 16);
            float py = __shfl_xor_sync(0xffffffffu, v.y, 16);
            float pz = __shfl_xor_sync(0xffffffffu, v.z, 16);
            float pw = __shfl_xor_sync(0xffffffffu, v.w, 16);
            float s = (lane < 16) ? -1.f : 1.f;
            float4 cs = *(const float4*)&cosT[(size_t)t*HD + lane*4];
            float4 sn = *(const float4*)&sinT[(size_t)t*HD + lane*4];
            float4 o;
            o.x = (v.x*cs.x + s*px*sn.x) * smul;
            o.y = (v.y*cs.y + s*py*sn.y) * smul;
            o.z = (v.z*cs.z + s*pz*sn.z) * smul;
            o.w = (v.w*cs.w + s*pw*sn.w) * smul;
            uint32_t H0, L0, H1, L1;
            split2(o.x, o.y, H0, L0);
            split2(o.z, o.w, H1, L1);
            size_t off = (((size_t)(b*Hn + hloc))*TT + t)*HD + lane*4;
            *(uint2*)&outh[off] = make_uint2(H0, H1);
            *(uint2*)&outl[off] = make_uint2(L0, L1);
        } else {
            size_t off = (size_t)gtok*(HKV*HD) + hloc*HD + lane*4;
            *(uint2*)&Vh[off] = make_uint2(packh(v.x, v.y), packh(v.z, v.w));
        }
    }
}

// ---------------- O-projection GEMM (fp32 epilogue, descale) -----------------
__global__ __launch_bounds__(256, 2) void gemm_o(
    const __half* __restrict__ gA,
    const __half* __restrict__ gB0, const __half* __restrict__ gB1,
    float* __restrict__ C, int N)
{
    extern __shared__ __half sm[];
    const uint32_t sbase = (uint32_t)__cvta_generic_to_shared(sm);
    const int row0 = blockIdx.y * 128, col0 = blockIdx.x * 128;
    const int K = DD;
    const int niter = K / BKC;

    GEMM_PROLOGUE();
    GEMM_MAINLOOP();

    const int gr = lane >> 2, gc = (lane & 3) * 2;
#pragma unroll
    for (int mt = 0; mt < 2; mt++)
#pragma unroll
        for (int nt = 0; nt < 8; nt++) {
            int row = row0 + wm + mt*16 + gr;
            int col = col0 + wn + nt*8 + gc;
            *(float2*)&C[(size_t)row*N + col]     = make_float2(acc[mt][nt][0]*INV256, acc[mt][nt][1]*INV256);
            *(float2*)&C[(size_t)(row+8)*N + col] = make_float2(acc[mt][nt][2]*INV256, acc[mt][nt][3]*INV256);
        }
}

// ---------------- fused flash attention -------------------------------------
// QK^T: bf16x3 (accuracy-critical). PV: fp16 1-mma (P and V single planes).
// 3-stage KV pipeline.
#define BQ 128
#define BK 64
#define FP 136
#define QELE (BQ*FP)
#define KELE (BK*FP)
#define QAREA (2*QELE)
#define STGKV (3*KELE)
#define FLASH_SMEM ((QAREA + 3*STGKV) * 2)   // 226304 bytes

__global__ __launch_bounds__(256) void flash_kernel(
    const bf16* __restrict__ Qh, const bf16* __restrict__ Ql,
    const bf16* __restrict__ Kh, const bf16* __restrict__ Kl,
    const __half* __restrict__ Vh,
    __half* __restrict__ ctxh)
{
    extern __shared__ bf16 smf[];
    const int tid = threadIdx.x, lane = tid & 31, wid = tid >> 5;
    const int qb = gridDim.x - 1 - blockIdx.x;
    const int bh = blockIdx.y;
    const int b = bh >> 4, h = bh & 15, kv = h >> 1;
    const int q0 = qb * BQ;
    const uint32_t sbase = (uint32_t)__cvta_generic_to_shared(smf);

    const bf16* Qhg = Qh + ((size_t)(b*HQ  + h )*TT + q0)*HD;
    const bf16* Qlg = Ql + ((size_t)(b*HQ  + h )*TT + q0)*HD;
    const bf16* Khg = Kh + ((size_t)(b*HKV + kv)*TT)*HD;
    const bf16* Klg = Kl + ((size_t)(b*HKV + kv)*TT)*HD;
    const __half* Vhg = Vh + (size_t)b*TT*(HKV*HD) + kv*HD;

#pragma unroll
    for (int i = 0; i < 8; i++) {
        int c = tid + i*256;
        int row = c >> 4, col = (c & 15) * 8;
        cp_async16(sbase + (uint32_t)((row*FP + col) * 2),        Qhg + (size_t)row*HD + col);
        cp_async16(sbase + (uint32_t)((QELE + row*FP + col) * 2), Qlg + (size_t)row*HD + col);
    }

#define ISSUEKV(kt, stage) do {                                                     \
    const int k0_ = (kt) * BK;                                                      \
    const uint32_t kb_ = sbase + (uint32_t)((QAREA + (stage)*STGKV) * 2);           \
    _Pragma("unroll")                                                               \
    for (int i_ = 0; i_ < 4; i_++) {                                                \
        int c_ = tid + i_*256;                                                      \
        int row_ = c_ >> 4, col_ = (c_ & 15) * 8;                                   \
        uint32_t so_ = (uint32_t)((row_*FP + col_) * 2);                            \
        cp_async16(kb_ + so_,            Khg + (size_t)(k0_+row_)*HD + col_);       \
        cp_async16(kb_ + KELE*2 + so_,   Klg + (size_t)(k0_+row_)*HD + col_);       \
        cp_async16(kb_ + 2*KELE*2 + so_, Vhg + (size_t)(k0_+row_)*(HKV*HD) + col_); \
    }                                                                               \
} while (0)

    const int nkt = 2*qb + 2;
    ISSUEKV(0, 0);
    cp_commit();
    ISSUEKV(1, 1);
    cp_commit();

    const int r   = lane & 7, blkid = lane >> 3;
    const int a_row = ((blkid & 1) << 3) + r;
    const int a_col = (blkid >> 1) << 3;
    const int b_row = ((blkid >> 1) << 3) + r;
    const int b_col = (blkid & 1) << 3;
    const int gr = lane >> 2;

    float oacc[16][4];
#pragma unroll
    for (int i = 0; i < 16; i++)
#pragma unroll
        for (int j = 0; j < 4; j++) oacc[i][j] = 0.f;
    float m0 = -1e30f, m1 = -1e30f, l0 = 0.f, l1 = 0.f;

    const int row0g = q0 + wid*16 + gr;
    const int row1g = row0g + 8;
    const int rowmin = q0 + wid*16;

    int stg = 0;
    for (int kt = 0; kt < nkt; kt++) {
        if (kt + 2 < nkt) {
            int s2 = stg + 2; if (s2 >= 3) s2 -= 3;
            ISSUEKV(kt + 2, s2);
            cp_commit();
            asm volatile("cp.async.wait_group 2;\n" ::: "memory");
        } else if (kt + 1 < nkt) {
            asm volatile("cp.async.wait_group 1;\n" ::: "memory");
        } else {
            asm volatile("cp.async.wait_group 0;\n" ::: "memory");
        }
        __syncthreads();

        const int k0 = kt * BK;
        const uint32_t kb_s = sbase + (uint32_t)((QAREA + stg*STGKV) * 2);

        float sacc[8][4];
#pragma unroll
        for (int i = 0; i < 8; i++)
#pragma unroll
            for (int j = 0; j < 4; j++) sacc[i][j] = 0.f;

#pragma unroll
        for (int ks = 0; ks < 8; ks++) {
            uint32_t qa = sbase + (uint32_t)(((wid*16 + a_row)*FP + ks*16 + a_col) * 2);
            uint32_t qh[4], ql[4];
            ldsm4(qh, qa);
            ldsm4(ql, qa + QELE*2);
#pragma unroll
            for (int np = 0; np < 4; np++) {
                uint32_t ka = kb_s + (uint32_t)(((np*16 + b_row)*FP + ks*16 + b_col) * 2);
                uint32_t kh[4], kl[4];
                ldsm4(kh, ka);
                ldsm4(kl, ka + KELE*2);
                mma16816(sacc[2*np],   qh, &kh[0]);
                mma16816(sacc[2*np+1], qh, &kh[2]);
                mma16816(sacc[2*np],   qh, &kl[0]);
                mma16816(sacc[2*np+1], qh, &kl[2]);
                mma16816(sacc[2*np],   ql, &kh[0]);
                mma16816(sacc[2*np+1], ql, &kh[2]);
            }
        }

        // ---- causal mask (only near diagonal) + online softmax ----
        float mx0 = -1e30f, mx1 = -1e30f;
        if (k0 + 63 > rowmin) {
#pragma unroll
            for (int nt = 0; nt < 8; nt++) {
                int cg = k0 + nt*8 + (lane & 3)*2;
                if (cg     > row0g) sacc[nt][0] = -1e30f;
                if (cg + 1 > row0g) sacc[nt][1] = -1e30f;
                if (cg     > row1g) sacc[nt][2] = -1e30f;
                if (cg + 1 > row1g) sacc[nt][3] = -1e30f;
                mx0 = fmaxf(mx0, fmaxf(sacc[nt][0], sacc[nt][1]));
                mx1 = fmaxf(mx1, fmaxf(sacc[nt][2], sacc[nt][3]));
            }
        } else {
#pragma unroll
            for (int nt = 0; nt < 8; nt++) {
                mx0 = fmaxf(mx0, fmaxf(sacc[nt][0], sacc[nt][1]));
                mx1 = fmaxf(mx1, fmaxf(sacc[nt][2], sacc[nt][3]));
            }
        }
        mx0 = fmaxf(mx0, __shfl_xor_sync(0xffffffffu, mx0, 1));
        mx0 = fmaxf(mx0, __shfl_xor_sync(0xffffffffu, mx0, 2));
        mx1 = fmaxf(mx1, __shfl_xor_sync(0xffffffffu, mx1, 1));
        mx1 = fmaxf(mx1, __shfl_xor_sync(0xffffffffu, mx1, 2));

        float mn0 = fmaxf(m0, mx0), mn1 = fmaxf(m1, mx1);
        float sc0 = exp2f(m0 - mn0), sc1 = exp2f(m1 - mn1);
        m0 = mn0; m1 = mn1;

        float s0 = 0.f, s1 = 0.f;
#pragma unroll
        for (int nt = 0; nt < 8; nt++) {
            sacc[nt][0] = exp2f(sacc[nt][0] - m0);
            sacc[nt][1] = exp2f(sacc[nt][1] - m0);
            sacc[nt][2] = exp2f(sacc[nt][2] - m1);
            sacc[nt][3] = exp2f(sacc[nt][3] - m1);
            s0 += sacc[nt][0] + sacc[nt][1];
            s1 += sacc[nt][2] + sacc[nt][3];
        }
        s0 += __shfl_xor_sync(0xffffffffu, s0, 1);
        s0 += __shfl_xor_sync(0xffffffffu, s0, 2);
        s1 += __shfl_xor_sync(0xffffffffu, s1, 1);
        s1 += __shfl_xor_sync(0xffffffffu, s1, 2);
        l0 = l0*sc0 + s0;
        l1 = l1*sc1 + s1;

#pragma unroll
        for (int i = 0; i < 16; i++) {
            oacc[i][0] *= sc0; oacc[i][1] *= sc0;
            oacc[i][2] *= sc1; oacc[i][3] *= sc1;
        }

        // ---- O += P V (fp16 1-mma: P and V single planes) ----
        const int vrow = (lane & 7) + ((lane >> 3) & 1)*8;
        const int vcolb = ((lane >> 4) << 3);
#pragma unroll
        for (int kp = 0; kp < 4; kp++) {
            uint32_t ph[4];
#pragma unroll
            for (int half = 0; half < 2; half++) {
                ph[2*half]   = packh(sacc[2*kp+half][0], sacc[2*kp+half][1]);
                ph[2*half+1] = packh(sacc[2*kp+half][2], sacc[2*kp+half][3]);
            }
#pragma unroll
            for (int np = 0; np < 8; np++) {
                uint32_t va = kb_s + (uint32_t)((2*KELE + (kp*16 + vrow)*FP + np*16 + vcolb) * 2);
                uint32_t vh[4];
                ldsm4t(vh, va);
                mma16816h(oacc[2*np],   ph, &vh[0]);
                mma16816h(oacc[2*np+1], ph, &vh[2]);
            }
        }
        __syncthreads();
        if (++stg == 3) stg = 0;
    }
#undef ISSUEKV

    // ---- epilogue: O /= l, write ctx fp16 single plane ----
    const float il0 = 1.f / l0, il1 = 1.f / l1;
    const size_t tok0 = (size_t)(b*TT + q0 + wid*16 + gr);
#pragma unroll
    for (int nt = 0; nt < 16; nt++) {
        int col = h*HD + nt*8 + (lane & 3)*2;
        *(uint32_t*)&ctxh[tok0*(HQ*HD) + col]     = packh(oacc[nt][0]*il0, oacc[nt][1]*il0);
        *(uint32_t*)&ctxh[(tok0+8)*(HQ*HD) + col] = packh(oacc[nt][2]*il1, oacc[nt][3]*il1);
    }
}

// ---------------- launch ------------------------------------------------------
extern "C" void kernel_launch(void* const* d_in, const int* in_sizes, int n_in,
                              void* d_out, int out_size)
{
    const float* x       = (const float*)d_in[0];
    const float* cosT    = (const float*)d_in[2];
    const float* sinT    = (const float*)d_in[3];
    const float* Wq      = (const float*)d_in[4];
    const float* Wk      = (const float*)d_in[5];
    const float* Wv      = (const float*)d_in[6];
    const float* Wo      = (const float*)d_in[7];
    const float* q_scale = (const float*)d_in[8];
    const float* k_scale = (const float*)d_in[9];
    float* out = (float*)d_out;

    __half *xh,*Wqh,*Wql,*Wkh,*Wkl,*Wvh,*Wvl,*Woh,*Wol,*ctxh,*Vh;
    bf16 *Qh,*Ql,*Kh,*Kl;
    cudaGetSymbolAddress((void**)&xh,   g_xh);
    cudaGetSymbolAddress((void**)&Wqh,  g_Wqh);  cudaGetSymbolAddress((void**)&Wql,  g_Wql);
    cudaGetSymbolAddress((void**)&Wkh,  g_Wkh);  cudaGetSymbolAddress((void**)&Wkl,  g_Wkl);
    cudaGetSymbolAddress((void**)&Wvh,  g_Wvh);  cudaGetSymbolAddress((void**)&Wvl,  g_Wvl);
    cudaGetSymbolAddress((void**)&Woh,  g_Woh);  cudaGetSymbolAddress((void**)&Wol,  g_Wol);
    cudaGetSymbolAddress((void**)&Qh,   g_Qh);   cudaGetSymbolAddress((void**)&Ql,   g_Ql);
    cudaGetSymbolAddress((void**)&Kh,   g_Kh);   cudaGetSymbolAddress((void**)&Kl,   g_Kl);
    cudaGetSymbolAddress((void**)&Vh,   g_Vh);
    cudaGetSymbolAddress((void**)&ctxh, g_ctxh);

    static bool attr_set = false;
    if (!attr_set) {
        cudaFuncSetAttribute(gemm_qkv,     cudaFuncAttributeMaxDynamicSharedMemorySize, GSMEM);
        cudaFuncSetAttribute(gemm_o,       cudaFuncAttributeMaxDynamicSharedMemorySize, GSMEM);
        cudaFuncSetAttribute(flash_kernel, cudaFuncAttributeMaxDynamicSharedMemorySize, FLASH_SMEM);
        attr_set = true;
    }

    // 0: all operand conversions in one launch
    split_all_kernel<<<20480, 256>>>(
        (const float4*)x, (const float4*)Wq, (const float4*)Wk,
        (const float4*)Wv, (const float4*)Wo,
        xh, Wqh, Wql, Wkh, Wkl, Wvh, Wvl, Woh, Wol);

    // 1: merged QKV projection (fp16 2-mma, 3-stage) + fused norm/rope/split
    gemm_qkv<<<dim3(32, MROWS/128), 256, GSMEM>>>(
        xh, Wqh, Wql, Wkh, Wkl, Wvh, Wvl,
        Qh, Ql, Kh, Kl, Vh, q_scale, k_scale, cosT, sinT);

    // 2: fused flash attention (QK bf16x3, PV fp16 1-mma, 3-stage KV)
    flash_kernel<<<dim3(TT/BQ, BB*HQ), 256, FLASH_SMEM>>>(Qh, Ql, Kh, Kl, Vh, ctxh);

    // 3: output projection (fp16 2-mma, 3-stage, descale)
    gemm_o<<<dim3(DD/128, MROWS/128), 256, GSMEM>>>(ctxh, Woh, Wol, out, DD);
}

// round 11
// speedup vs baseline: 3.0896x; 1.0064x over previous
#include <cuda_runtime.h>
#include <cuda_bf16.h>
#include <cuda_fp16.h>
#include <cstdint>
#include <cstddef>

// Problem constants
#define BB 2
#define TT 2048
#define DD 2048
#define HQ 16
#define HKV 8
#define HD 128
#define MROWS (BB*TT)   // 4096

typedef __nv_bfloat16 bf16;

// log2(e)/sqrt(128)
#define QSCALE 0.12752551164384637f
#define WSCALE 256.0f
#define INV256 0.00390625f

// ---------------- scratch (static device globals) ---------------------------
__device__ __half g_xh [(size_t)MROWS*DD];                      // single plane
__device__ __half g_Wqh[(size_t)HQ*HD*DD],  g_Wql[(size_t)HQ*HD*DD];
__device__ __half g_Wkh[(size_t)HKV*HD*DD], g_Wkl[(size_t)HKV*HD*DD];
__device__ __half g_Wvh[(size_t)HKV*HD*DD], g_Wvl[(size_t)HKV*HD*DD];
__device__ __half g_Woh[(size_t)DD*HQ*HD],  g_Wol[(size_t)DD*HQ*HD];
__device__ bf16 g_Qh [(size_t)BB*HQ*TT*HD],  g_Ql [(size_t)BB*HQ*TT*HD];
__device__ bf16 g_Kh [(size_t)BB*HKV*TT*HD], g_Kl [(size_t)BB*HKV*TT*HD];
__device__ __half g_Vh [(size_t)MROWS*HKV*HD];                  // single plane
__device__ __half g_ctxh[(size_t)MROWS*HQ*HD];                  // single plane

// ---------------- PTX helpers ------------------------------------------------
__device__ __forceinline__ void ldsm4(uint32_t* r, uint32_t a) {
    asm volatile("ldmatrix.sync.aligned.m8n8.x4.shared.b16 {%0,%1,%2,%3}, [%4];\n"
        : "=r"(r[0]), "=r"(r[1]), "=r"(r[2]), "=r"(r[3]) : "r"(a));
}
__device__ __forceinline__ void ldsm4t(uint32_t* r, uint32_t a) {
    asm volatile("ldmatrix.sync.aligned.m8n8.x4.trans.shared.b16 {%0,%1,%2,%3}, [%4];\n"
        : "=r"(r[0]), "=r"(r[1]), "=r"(r[2]), "=r"(r[3]) : "r"(a));
}
__device__ __forceinline__ void mma16816(float* c, const uint32_t* a, const uint32_t* b) {
    asm volatile("mma.sync.aligned.m16n8k16.row.col.f32.bf16.bf16.f32 "
        "{%0,%1,%2,%3}, {%4,%5,%6,%7}, {%8,%9}, {%0,%1,%2,%3};\n"
        : "+f"(c[0]), "+f"(c[1]), "+f"(c[2]), "+f"(c[3])
        : "r"(a[0]), "r"(a[1]), "r"(a[2]), "r"(a[3]), "r"(b[0]), "r"(b[1]));
}
__device__ __forceinline__ void mma16816h(float* c, const uint32_t* a, const uint32_t* b) {
    asm volatile("mma.sync.aligned.m16n8k16.row.col.f32.f16.f16.f32 "
        "{%0,%1,%2,%3}, {%4,%5,%6,%7}, {%8,%9}, {%0,%1,%2,%3};\n"
        : "+f"(c[0]), "+f"(c[1]), "+f"(c[2]), "+f"(c[3])
        : "r"(a[0]), "r"(a[1]), "r"(a[2]), "r"(a[3]), "r"(b[0]), "r"(b[1]));
}
__device__ __forceinline__ void cp_async16(uint32_t dst, const void* src) {
    asm volatile("cp.async.ca.shared.global [%0], [%1], 16;\n" :: "r"(dst), "l"(src));
}
__device__ __forceinline__ void cp_commit() {
    asm volatile("cp.async.commit_group;\n" ::: "memory");
}
__device__ __forceinline__ uint32_t packbf(float a, float b) {
    __nv_bfloat162 t = __floats2bfloat162_rn(a, b);
    return *(uint32_t*)&t;
}
__device__ __forceinline__ uint32_t packh(float a, float b) {
    __half2 t = __floats2half2_rn(a, b);
    return *(uint32_t*)&t;
}
__device__ __forceinline__ void split2(float a, float b, uint32_t& h, uint32_t& l) {
    bf16 ha = __float2bfloat16(a), hb = __float2bfloat16(b);
    h = ((uint32_t)__bfloat16_as_ushort(hb) << 16) | (uint32_t)__bfloat16_as_ushort(ha);
    l = packbf(a - __bfloat162float(ha), b - __bfloat162float(hb));
}
__device__ __forceinline__ void split2h(float a, float b, uint32_t& h, uint32_t& l) {
    __half ha = __float2half_rn(a), hb = __float2half_rn(b);
    h = ((uint32_t)__half_as_ushort(hb) << 16) | (uint32_t)__half_as_ushort(ha);
    l = packh(a - __half2float(ha), b - __half2float(hb));
}

// ---------------- fused operand conversion (single launch) -------------------
__global__ __launch_bounds__(256) void split_all_kernel(
    const float4* __restrict__ x,  const float4* __restrict__ Wq,
    const float4* __restrict__ Wk, const float4* __restrict__ Wv,
    const float4* __restrict__ Wo,
    __half* __restrict__ xh,
    __half* __restrict__ Wqh, __half* __restrict__ Wql,
    __half* __restrict__ Wkh, __half* __restrict__ Wkl,
    __half* __restrict__ Wvh, __half* __restrict__ Wvl,
    __half* __restrict__ Woh, __half* __restrict__ Wol)
{
    int blk = blockIdx.x;
    if (blk < 8192) {
        int i = blk*256 + threadIdx.x;
        float4 v = x[i];
        *(uint2*)(xh + (size_t)i*4) = make_uint2(packh(v.x, v.y), packh(v.z, v.w));
        return;
    }
    blk -= 8192;
    const float4* in; __half *hi, *lo;
    if (blk < 4096)      {                in = Wq; hi = Wqh; lo = Wql; }
    else if (blk < 6144) { blk -= 4096;   in = Wk; hi = Wkh; lo = Wkl; }
    else if (blk < 8192) { blk -= 6144;   in = Wv; hi = Wvh; lo = Wvl; }
    else                 { blk -= 8192;   in = Wo; hi = Woh; lo = Wol; }
    int i = blk*256 + threadIdx.x;
    float4 v = in[i];
    uint32_t h0, l0, h1, l1;
    split2h(v.x*WSCALE, v.y*WSCALE, h0, l0);
    split2h(v.z*WSCALE, v.w*WSCALE, h1, l1);
    *(uint2*)(hi + (size_t)i*4) = make_uint2(h0, h1);
    *(uint2*)(lo + (size_t)i*4) = make_uint2(l0, l1);
}

// ---------------- GEMM core macros (fp16 2-mma, 3-stage single-sync) ---------
#define BKC 32
#define PAD 40
#define ARR (128*PAD)
#define STG3 (3*ARR)
#define GSMEM (3*STG3*2)        // 92160 bytes (3 stages)

#define GEMM_PROLOGUE()                                                         \
    const int tid  = threadIdx.x;                                               \
    const int lane = tid & 31, wid = tid >> 5;                                  \
    const int wm = (wid >> 1) * 32;                                             \
    const int wn = (wid & 1) * 64;                                              \
    const int m0 = tid >> 2;                                                    \
    const int c0 = (tid & 3) * 8;                                               \
    const int r_   = lane & 7, blk_ = lane >> 3;                                \
    const int a_row = ((blk_ & 1) << 3) + r_;                                   \
    const int a_col = (blk_ >> 1) << 3;                                         \
    const int b_row = ((blk_ >> 1) << 3) + r_;                                  \
    const int b_col = (blk_ & 1) << 3;                                          \
    float acc[2][8][4];                                                         \
    _Pragma("unroll") for (int i = 0; i < 2; i++)                               \
    _Pragma("unroll") for (int j = 0; j < 8; j++)                               \
    _Pragma("unroll") for (int k = 0; k < 4; k++) acc[i][j][k] = 0.f;

#define ISSUE(it, stage) do {                                                   \
    const int k0_ = (it) * BKC;                                                 \
    uint32_t sst_ = sbase + (uint32_t)(stage) * (STG3 * 2);                     \
    _Pragma("unroll")                                                           \
    for (int hh_ = 0; hh_ < 2; hh_++) {                                         \
        int m_ = m0 + hh_ * 64;                                                 \
        cp_async16(sst_ + (uint32_t)((m_*PAD + c0) * 2),                        \
                   gA + (size_t)(row0 + m_) * K + k0_ + c0);                    \
        cp_async16(sst_ + (uint32_t)((ARR + m_*PAD + c0) * 2),                  \
                   gB0 + (size_t)(col0 + m_) * K + k0_ + c0);                   \
        cp_async16(sst_ + (uint32_t)((2*ARR + m_*PAD + c0) * 2),                \
                   gB1 + (size_t)(col0 + m_) * K + k0_ + c0);                   \
    }                                                                           \
} while (0)

// Single barrier per iteration: wait(stage j ready) -> sync(all readers of
// stage j-1 done) -> issue into stage (j+2)%3 == (j-1)%3 -> compute stage j.
#define GEMM_MAINLOOP()                                                         \
    ISSUE(0, 0);                                                                \
    cp_commit();                                                                \
    ISSUE(1, 1);                                                                \
    cp_commit();                                                                \
    int stg = 0;                                                                \
    for (int it = 0; it < niter; it++) {                                        \
        if (it + 1 < niter) {                                                   \
            asm volatile("cp.async.wait_group 1;\n" ::: "memory");              \
        } else {                                                                \
            asm volatile("cp.async.wait_group 0;\n" ::: "memory");              \
        }                                                                       \
        __syncthreads();                                                        \
        if (it + 2 < niter) {                                                   \
            int s2 = stg + 2; if (s2 >= 3) s2 -= 3;                             \
            ISSUE(it + 2, s2);                                                  \
            cp_commit();                                                        \
        }                                                                       \
        const uint32_t sst = sbase + (uint32_t)stg * (STG3 * 2);                \
        _Pragma("unroll")                                                       \
        for (int ks = 0; ks < 2; ks++) {                                        \
            const int kofs = ks * 16;                                           \
            uint32_t a_[2][4], bh_[4][4], bl_[4][4];                            \
            _Pragma("unroll")                                                   \
            for (int mt = 0; mt < 2; mt++)                                      \
                ldsm4(a_[mt], sst + (uint32_t)(((wm + mt*16 + a_row)*PAD + kofs + a_col) * 2)); \
            _Pragma("unroll")                                                   \
            for (int p = 0; p < 4; p++) {                                       \
                uint32_t addr = sst + (uint32_t)((ARR + (wn + p*16 + b_row)*PAD + kofs + b_col) * 2); \
                ldsm4(bh_[p], addr);                                            \
                ldsm4(bl_[p], addr + ARR * 2);                                  \
            }                                                                   \
            _Pragma("unroll")                                                   \
            for (int mt = 0; mt < 2; mt++)                                      \
            _Pragma("unroll")                                                   \
                for (int p = 0; p < 4; p++) {                                   \
                    mma16816h(acc[mt][2*p],   a_[mt], &bh_[p][0]);              \
                    mma16816h(acc[mt][2*p+1], a_[mt], &bh_[p][2]);              \
                    mma16816h(acc[mt][2*p],   a_[mt], &bl_[p][0]);              \
                    mma16816h(acc[mt][2*p+1], a_[mt], &bl_[p][2]);              \
                }                                                               \
        }                                                                       \
        if (++stg == 3) stg = 0;                                                \
    }

// ---------------- merged QKV GEMM with fused norm/rope/split epilogue --------
__global__ __launch_bounds__(256, 2) void gemm_qkv(
    const __half* __restrict__ gA,
    const __half* __restrict__ Wqh_, const __half* __restrict__ Wql_,
    const __half* __restrict__ Wkh_, const __half* __restrict__ Wkl_,
    const __half* __restrict__ Wvh_, const __half* __restrict__ Wvl_,
    bf16* __restrict__ Qh, bf16* __restrict__ Ql,
    bf16* __restrict__ Kh, bf16* __restrict__ Kl,
    __half* __restrict__ Vh,
    const float* __restrict__ q_scale, const float* __restrict__ k_scale,
    const float* __restrict__ cosT, const float* __restrict__ sinT)
{
    extern __shared__ __half sm[];
    const uint32_t sbase = (uint32_t)__cvta_generic_to_shared(sm);
    const int bx = blockIdx.x;
    const int row0 = blockIdx.y * 128;
    const int K = DD;
    const int niter = K / BKC;

    int mode, hloc;
    const __half *gB0, *gB1;
    if (bx < 16)      { mode = 0; hloc = bx;      gB0 = Wqh_; gB1 = Wql_; }
    else if (bx < 24) { mode = 1; hloc = bx - 16; gB0 = Wkh_; gB1 = Wkl_; }
    else              { mode = 2; hloc = bx - 24; gB0 = Wvh_; gB1 = Wvl_; }
    const int col0 = hloc * 128;

    GEMM_PROLOGUE();
    GEMM_MAINLOOP();

    // ---- stage fp32 tile into smem (reuse pipeline smem) ----
    __syncthreads();
    float* sf = (float*)sm;                 // 128 x 132 floats = 67584 B <= 92160
    const int gr = lane >> 2, gc = (lane & 3) * 2;
#pragma unroll
    for (int mt = 0; mt < 2; mt++)
#pragma unroll
        for (int nt = 0; nt < 8; nt++) {
            int row = wm + mt*16 + gr;
            int col = wn + nt*8 + gc;
            *(float2*)&sf[(size_t)row*132 + col]     = make_float2(acc[mt][nt][0], acc[mt][nt][1]);
            *(float2*)&sf[(size_t)(row+8)*132 + col] = make_float2(acc[mt][nt][2], acc[mt][nt][3]);
        }
    __syncthreads();

    const float* scv = (mode == 0) ? q_scale : k_scale;
    const float smul = (mode == 0) ? QSCALE : 1.0f;
    const int   Hn   = (mode == 0) ? HQ : HKV;
    bf16* outh = (mode == 0) ? Qh : Kh;
    bf16* outl = (mode == 0) ? Ql : Kl;

    float4 sc4 = make_float4(1.f,1.f,1.f,1.f);
    if (mode < 2) sc4 = *(const float4*)&scv[lane*4];

    for (int rr = 0; rr < 16; rr++) {
        const int row  = wid*16 + rr;
        const int gtok = row0 + row;
        const int b = gtok >> 11, t = gtok & (TT-1);
        float4 v = *(float4*)&sf[(size_t)row*132 + lane*4];
        v.x *= INV256; v.y *= INV256; v.z *= INV256; v.w *= INV256;   // weight descale
        if (mode < 2) {
            float ss = v.x*v.x + v.y*v.y + v.z*v.z + v.w*v.w;
#pragma unroll
            for (int ofs = 16; ofs > 0; ofs >>= 1)
                ss += __shfl_xor_sync(0xffffffffu, ss, ofs);
            float inv = rsqrtf(ss*(1.0f/HD) + 1e-6f);
            v.x *= inv*sc4.x; v.y *= inv*sc4.y; v.z *= inv*sc4.z; v.w *= inv*sc4.w;
            float px = __shfl_xor_sync(0xffffffffu, v.x, 16);
            float py = __shfl_xor_sync(0xffffffffu, v.y, 16);
            float pz = __shfl_xor_sync(0xffffffffu, v.z, 16);
            float pw = __shfl_xor_sync(0xffffffffu, v.w, 16);
            float s = (lane < 16) ? -1.f : 1.f;
            float4 cs = *(const float4*)&cosT[(size_t)t*HD + lane*4];
            float4 sn = *(const float4*)&sinT[(size_t)t*HD + lane*4];
            float4 o;
            o.x = (v.x*cs.x + s*px*sn.x) * smul;
            o.y = (v.y*cs.y + s*py*sn.y) * smul;
            o.z = (v.z*cs.z + s*pz*sn.z) * smul;
            o.w = (v.w*cs.w + s*pw*sn.w) * smul;
            uint32_t H0, L0, H1, L1;
            split2(o.x, o.y, H0, L0);
            split2(o.z, o.w, H1, L1);
            size_t off = (((size_t)(b*Hn + hloc))*TT + t)*HD + lane*4;
            *(uint2*)&outh[off] = make_uint2(H0, H1);
            *(uint2*)&outl[off] = make_uint2(L0, L1);
        } else {
            size_t off = (size_t)gtok*(HKV*HD) + hloc*HD + lane*4;
            *(uint2*)&Vh[off] = make_uint2(packh(v.x, v.y), packh(v.z, v.w));
        }
    }
}

// ---------------- O-projection GEMM (fp32 epilogue, descale) -----------------
__global__ __launch_bounds__(256, 2) void gemm_o(
    const __half* __restrict__ gA,
    const __half* __restrict__ gB0, const __half* __restrict__ gB1,
    float* __restrict__ C, int N)
{
    extern __shared__ __half sm[];
    const uint32_t sbase = (uint32_t)__cvta_generic_to_shared(sm);
    const int row0 = blockIdx.y * 128, col0 = blockIdx.x * 128;
    const int K = DD;
    const int niter = K / BKC;

    GEMM_PROLOGUE();
    GEMM_MAINLOOP();

    const int gr = lane >> 2, gc = (lane & 3) * 2;
#pragma unroll
    for (int mt = 0; mt < 2; mt++)
#pragma unroll
        for (int nt = 0; nt < 8; nt++) {
            int row = row0 + wm + mt*16 + gr;
            int col = col0 + wn + nt*8 + gc;
            *(float2*)&C[(size_t)row*N + col]     = make_float2(acc[mt][nt][0]*INV256, acc[mt][nt][1]*INV256);
            *(float2*)&C[(size_t)(row+8)*N + col] = make_float2(acc[mt][nt][2]*INV256, acc[mt][nt][3]*INV256);
        }
}

// ---------------- fused flash attention -------------------------------------
// QK^T: bf16x3 (accuracy-critical). PV: fp16 1-mma (P and V single planes).
// 3-stage KV pipeline, single barrier per tile.
#define BQ 128
#define BK 64
#define FP 136
#define QELE (BQ*FP)
#define KELE (BK*FP)
#define QAREA (2*QELE)
#define STGKV (3*KELE)
#define FLASH_SMEM ((QAREA + 3*STGKV) * 2)   // 226304 bytes

__global__ __launch_bounds__(256) void flash_kernel(
    const bf16* __restrict__ Qh, const bf16* __restrict__ Ql,
    const bf16* __restrict__ Kh, const bf16* __restrict__ Kl,
    const __half* __restrict__ Vh,
    __half* __restrict__ ctxh)
{
    extern __shared__ bf16 smf[];
    const int tid = threadIdx.x, lane = tid & 31, wid = tid >> 5;
    const int qb = gridDim.x - 1 - blockIdx.x;
    const int bh = blockIdx.y;
    const int b = bh >> 4, h = bh & 15, kv = h >> 1;
    const int q0 = qb * BQ;
    const uint32_t sbase = (uint32_t)__cvta_generic_to_shared(smf);

    const bf16* Qhg = Qh + ((size_t)(b*HQ  + h )*TT + q0)*HD;
    const bf16* Qlg = Ql + ((size_t)(b*HQ  + h )*TT + q0)*HD;
    const bf16* Khg = Kh + ((size_t)(b*HKV + kv)*TT)*HD;
    const bf16* Klg = Kl + ((size_t)(b*HKV + kv)*TT)*HD;
    const __half* Vhg = Vh + (size_t)b*TT*(HKV*HD) + kv*HD;

#pragma unroll
    for (int i = 0; i < 8; i++) {
        int c = tid + i*256;
        int row = c >> 4, col = (c & 15) * 8;
        cp_async16(sbase + (uint32_t)((row*FP + col) * 2),        Qhg + (size_t)row*HD + col);
        cp_async16(sbase + (uint32_t)((QELE + row*FP + col) * 2), Qlg + (size_t)row*HD + col);
    }

#define ISSUEKV(kt, stage) do {                                                     \
    const int k0_ = (kt) * BK;                                                      \
    const uint32_t kb_ = sbase + (uint32_t)((QAREA + (stage)*STGKV) * 2);           \
    _Pragma("unroll")                                                               \
    for (int i_ = 0; i_ < 4; i_++) {                                                \
        int c_ = tid + i_*256;                                                      \
        int row_ = c_ >> 4, col_ = (c_ & 15) * 8;                                   \
        uint32_t so_ = (uint32_t)((row_*FP + col_) * 2);                            \
        cp_async16(kb_ + so_,            Khg + (size_t)(k0_+row_)*HD + col_);       \
        cp_async16(kb_ + KELE*2 + so_,   Klg + (size_t)(k0_+row_)*HD + col_);       \
        cp_async16(kb_ + 2*KELE*2 + so_, Vhg + (size_t)(k0_+row_)*(HKV*HD) + col_); \
    }                                                                               \
} while (0)

    const int nkt = 2*qb + 2;
    ISSUEKV(0, 0);
    cp_commit();
    ISSUEKV(1, 1);
    cp_commit();

    const int r   = lane & 7, blkid = lane >> 3;
    const int a_row = ((blkid & 1) << 3) + r;
    const int a_col = (blkid >> 1) << 3;
    const int b_row = ((blkid >> 1) << 3) + r;
    const int b_col = (blkid & 1) << 3;
    const int gr = lane >> 2;

    float oacc[16][4];
#pragma unroll
    for (int i = 0; i < 16; i++)
#pragma unroll
        for (int j = 0; j < 4; j++) oacc[i][j] = 0.f;
    float m0 = -1e30f, m1 = -1e30f, l0 = 0.f, l1 = 0.f;

    const int row0g = q0 + wid*16 + gr;
    const int row1g = row0g + 8;
    const int rowmin = q0 + wid*16;

    int stg = 0;
    for (int kt = 0; kt < nkt; kt++) {
        if (kt + 1 < nkt) {
            asm volatile("cp.async.wait_group 1;\n" ::: "memory");
        } else {
            asm volatile("cp.async.wait_group 0;\n" ::: "memory");
        }
        __syncthreads();
        if (kt + 2 < nkt) {
            int s2 = stg + 2; if (s2 >= 3) s2 -= 3;
            ISSUEKV(kt + 2, s2);
            cp_commit();
        }

        const int k0 = kt * BK;
        const uint32_t kb_s = sbase + (uint32_t)((QAREA + stg*STGKV) * 2);

        float sacc[8][4];
#pragma unroll
        for (int i = 0; i < 8; i++)
#pragma unroll
            for (int j = 0; j < 4; j++) sacc[i][j] = 0.f;

#pragma unroll
        for (int ks = 0; ks < 8; ks++) {
            uint32_t qa = sbase + (uint32_t)(((wid*16 + a_row)*FP + ks*16 + a_col) * 2);
            uint32_t qh[4], ql[4];
            ldsm4(qh, qa);
            ldsm4(ql, qa + QELE*2);
#pragma unroll
            for (int np = 0; np < 4; np++) {
                uint32_t ka = kb_s + (uint32_t)(((np*16 + b_row)*FP + ks*16 + b_col) * 2);
                uint32_t kh[4], kl[4];
                ldsm4(kh, ka);
                ldsm4(kl, ka + KELE*2);
                mma16816(sacc[2*np],   qh, &kh[0]);
                mma16816(sacc[2*np+1], qh, &kh[2]);
                mma16816(sacc[2*np],   qh, &kl[0]);
                mma16816(sacc[2*np+1], qh, &kl[2]);
                mma16816(sacc[2*np],   ql, &kh[0]);
                mma16816(sacc[2*np+1], ql, &kh[2]);
            }
        }

        // ---- causal mask (only near diagonal) + online softmax ----
        float mx0 = -1e30f, mx1 = -1e30f;
        if (k0 + 63 > rowmin) {
#pragma unroll
            for (int nt = 0; nt < 8; nt++) {
                int cg = k0 + nt*8 + (lane & 3)*2;
                if (cg     > row0g) sacc[nt][0] = -1e30f;
                if (cg + 1 > row0g) sacc[nt][1] = -1e30f;
                if (cg     > row1g) sacc[nt][2] = -1e30f;
                if (cg + 1 > row1g) sacc[nt][3] = -1e30f;
                mx0 = fmaxf(mx0, fmaxf(sacc[nt][0], sacc[nt][1]));
                mx1 = fmaxf(mx1, fmaxf(sacc[nt][2], sacc[nt][3]));
            }
        } else {
#pragma unroll
            for (int nt = 0; nt < 8; nt++) {
                mx0 = fmaxf(mx0, fmaxf(sacc[nt][0], sacc[nt][1]));
                mx1 = fmaxf(mx1, fmaxf(sacc[nt][2], sacc[nt][3]));
            }
        }
        mx0 = fmaxf(mx0, __shfl_xor_sync(0xffffffffu, mx0, 1));
        mx0 = fmaxf(mx0, __shfl_xor_sync(0xffffffffu, mx0, 2));
        mx1 = fmaxf(mx1, __shfl_xor_sync(0xffffffffu, mx1, 1));
        mx1 = fmaxf(mx1, __shfl_xor_sync(0xffffffffu, mx1, 2));

        float mn0 = fmaxf(m0, mx0), mn1 = fmaxf(m1, mx1);
        float sc0 = exp2f(m0 - mn0), sc1 = exp2f(m1 - mn1);
        m0 = mn0; m1 = mn1;

        float s0 = 0.f, s1 = 0.f;
#pragma unroll
        for (int nt = 0; nt < 8; nt++) {
            sacc[nt][0] = exp2f(sacc[nt][0] - m0);
            sacc[nt][1] = exp2f(sacc[nt][1] - m0);
            sacc[nt][2] = exp2f(sacc[nt][2] - m1);
            sacc[nt][3] = exp2f(sacc[nt][3] - m1);
            s0 += sacc[nt][0] + sacc[nt][1];
            s1 += sacc[nt][2] + sacc[nt][3];
        }
        s0 += __shfl_xor_sync(0xffffffffu, s0, 1);
        s0 += __shfl_xor_sync(0xffffffffu, s0, 2);
        s1 += __shfl_xor_sync(0xffffffffu, s1, 1);
        s1 += __shfl_xor_sync(0xffffffffu, s1, 2);
        l0 = l0*sc0 + s0;
        l1 = l1*sc1 + s1;

#pragma unroll
        for (int i = 0; i < 16; i++) {
            oacc[i][0] *= sc0; oacc[i][1] *= sc0;
            oacc[i][2] *= sc1; oacc[i][3] *= sc1;
        }

        // ---- O += P V (fp16 1-mma: P and V single planes) ----
        const int vrow = (lane & 7) + ((lane >> 3) & 1)*8;
        const int vcolb = ((lane >> 4) << 3);
#pragma unroll
        for (int kp = 0; kp < 4; kp++) {
            uint32_t ph[4];
#pragma unroll
            for (int half = 0; half < 2; half++) {
                ph[2*half]   = packh(sacc[2*kp+half][0], sacc[2*kp+half][1]);
                ph[2*half+1] = packh(sacc[2*kp+half][2], sacc[2*kp+half][3]);
            }
#pragma unroll
            for (int np = 0; np < 8; np++) {
                uint32_t va = kb_s + (uint32_t)((2*KELE + (kp*16 + vrow)*FP + np*16 + vcolb) * 2);
                uint32_t vh[4];
                ldsm4t(vh, va);
                mma16816h(oacc[2*np],   ph, &vh[0]);
                mma16816h(oacc[2*np+1], ph, &vh[2]);
            }
        }
        if (++stg == 3) stg = 0;
    }
#undef ISSUEKV

    // ---- epilogue: O /= l, write ctx fp16 single plane ----
    const float il0 = 1.f / l0, il1 = 1.f / l1;
    const size_t tok0 = (size_t)(b*TT + q0 + wid*16 + gr);
#pragma unroll
    for (int nt = 0; nt < 16; nt++) {
        int col = h*HD + nt*8 + (lane & 3)*2;
        *(uint32_t*)&ctxh[tok0*(HQ*HD) + col]     = packh(oacc[nt][0]*il0, oacc[nt][1]*il0);
        *(uint32_t*)&ctxh[(tok0+8)*(HQ*HD) + col] = packh(oacc[nt][2]*il1, oacc[nt][3]*il1);
    }
}

// ---------------- launch ------------------------------------------------------
extern "C" void kernel_launch(void* const* d_in, const int* in_sizes, int n_in,
                              void* d_out, int out_size)
{
    const float* x       = (const float*)d_in[0];
    const float* cosT    = (const float*)d_in[2];
    const float* sinT    = (const float*)d_in[3];
    const float* Wq      = (const float*)d_in[4];
    const float* Wk      = (const float*)d_in[5];
    const float* Wv      = (const float*)d_in[6];
    const float* Wo      = (const float*)d_in[7];
    const float* q_scale = (const float*)d_in[8];
    const float* k_scale = (const float*)d_in[9];
    float* out = (float*)d_out;

    __half *xh,*Wqh,*Wql,*Wkh,*Wkl,*Wvh,*Wvl,*Woh,*Wol,*ctxh,*Vh;
    bf16 *Qh,*Ql,*Kh,*Kl;
    cudaGetSymbolAddress((void**)&xh,   g_xh);
    cudaGetSymbolAddress((void**)&Wqh,  g_Wqh);  cudaGetSymbolAddress((void**)&Wql,  g_Wql);
    cudaGetSymbolAddress((void**)&Wkh,  g_Wkh);  cudaGetSymbolAddress((void**)&Wkl,  g_Wkl);
    cudaGetSymbolAddress((void**)&Wvh,  g_Wvh);  cudaGetSymbolAddress((void**)&Wvl,  g_Wvl);
    cudaGetSymbolAddress((void**)&Woh,  g_Woh);  cudaGetSymbolAddress((void**)&Wol,  g_Wol);
    cudaGetSymbolAddress((void**)&Qh,   g_Qh);   cudaGetSymbolAddress((void**)&Ql,   g_Ql);
    cudaGetSymbolAddress((void**)&Kh,   g_Kh);   cudaGetSymbolAddress((void**)&Kl,   g_Kl);
    cudaGetSymbolAddress((void**)&Vh,   g_Vh);
    cudaGetSymbolAddress((void**)&ctxh, g_ctxh);

    static bool attr_set = false;
    if (!attr_set) {
        cudaFuncSetAttribute(gemm_qkv,     cudaFuncAttributeMaxDynamicSharedMemorySize, GSMEM);
        cudaFuncSetAttribute(gemm_o,       cudaFuncAttributeMaxDynamicSharedMemorySize, GSMEM);
        cudaFuncSetAttribute(flash_kernel, cudaFuncAttributeMaxDynamicSharedMemorySize, FLASH_SMEM);
        attr_set = true;
    }

    // 0: all operand conversions in one launch
    split_all_kernel<<<20480, 256>>>(
        (const float4*)x, (const float4*)Wq, (const float4*)Wk,
        (const float4*)Wv, (const float4*)Wo,
        xh, Wqh, Wql, Wkh, Wkl, Wvh, Wvl, Woh, Wol);

    // 1: merged QKV projection (fp16 2-mma, 3-stage single-sync) + fused epilogue
    gemm_qkv<<<dim3(32, MROWS/128), 256, GSMEM>>>(
        xh, Wqh, Wql, Wkh, Wkl, Wvh, Wvl,
        Qh, Ql, Kh, Kl, Vh, q_scale, k_scale, cosT, sinT);

    // 2: fused flash attention (QK bf16x3, PV fp16 1-mma, 3-stage single-sync)
    flash_kernel<<<dim3(TT/BQ, BB*HQ), 256, FLASH_SMEM>>>(Qh, Ql, Kh, Kl, Vh, ctxh);

    // 3: output projection (fp16 2-mma, 3-stage single-sync, descale)
    gemm_o<<<dim3(DD/128, MROWS/128), 256, GSMEM>>>(ctxh, Woh, Wol, out, DD);
}

// round 12
// speedup vs baseline: 3.1943x; 1.0339x over previous
#include <cuda_runtime.h>
#include <cuda_bf16.h>
#include <cuda_fp16.h>
#include <cstdint>
#include <cstddef>

// Problem constants
#define BB 2
#define TT 2048
#define DD 2048
#define HQ 16
#define HKV 8
#define HD 128
#define MROWS (BB*TT)   // 4096

typedef __nv_bfloat16 bf16;

// log2(e)/sqrt(128)
#define QSCALE 0.12752551164384637f
#define WSCALE 256.0f
#define INV256 0.00390625f

// ---------------- scratch (static device globals) ---------------------------
__device__ __half g_xh [(size_t)MROWS*DD];                      // single plane
__device__ __half g_Wqh[(size_t)HQ*HD*DD],  g_Wql[(size_t)HQ*HD*DD];
__device__ __half g_Wkh[(size_t)HKV*HD*DD], g_Wkl[(size_t)HKV*HD*DD];
__device__ __half g_Wvh[(size_t)HKV*HD*DD], g_Wvl[(size_t)HKV*HD*DD];
__device__ __half g_Woh[(size_t)DD*HQ*HD],  g_Wol[(size_t)DD*HQ*HD];
__device__ bf16 g_Qh [(size_t)BB*HQ*TT*HD],  g_Ql [(size_t)BB*HQ*TT*HD];
__device__ bf16 g_Kh [(size_t)BB*HKV*TT*HD], g_Kl [(size_t)BB*HKV*TT*HD];
__device__ __half g_Vh [(size_t)MROWS*HKV*HD];                  // single plane
__device__ __half g_ctxh[(size_t)MROWS*HQ*HD];                  // single plane

// ---------------- PTX helpers ------------------------------------------------
__device__ __forceinline__ void ldsm4(uint32_t* r, uint32_t a) {
    asm volatile("ldmatrix.sync.aligned.m8n8.x4.shared.b16 {%0,%1,%2,%3}, [%4];\n"
        : "=r"(r[0]), "=r"(r[1]), "=r"(r[2]), "=r"(r[3]) : "r"(a));
}
__device__ __forceinline__ void ldsm4t(uint32_t* r, uint32_t a) {
    asm volatile("ldmatrix.sync.aligned.m8n8.x4.trans.shared.b16 {%0,%1,%2,%3}, [%4];\n"
        : "=r"(r[0]), "=r"(r[1]), "=r"(r[2]), "=r"(r[3]) : "r"(a));
}
__device__ __forceinline__ void mma16816(float* c, const uint32_t* a, const uint32_t* b) {
    asm volatile("mma.sync.aligned.m16n8k16.row.col.f32.bf16.bf16.f32 "
        "{%0,%1,%2,%3}, {%4,%5,%6,%7}, {%8,%9}, {%0,%1,%2,%3};\n"
        : "+f"(c[0]), "+f"(c[1]), "+f"(c[2]), "+f"(c[3])
        : "r"(a[0]), "r"(a[1]), "r"(a[2]), "r"(a[3]), "r"(b[0]), "r"(b[1]));
}
__device__ __forceinline__ void mma16816h(float* c, const uint32_t* a, const uint32_t* b) {
    asm volatile("mma.sync.aligned.m16n8k16.row.col.f32.f16.f16.f32 "
        "{%0,%1,%2,%3}, {%4,%5,%6,%7}, {%8,%9}, {%0,%1,%2,%3};\n"
        : "+f"(c[0]), "+f"(c[1]), "+f"(c[2]), "+f"(c[3])
        : "r"(a[0]), "r"(a[1]), "r"(a[2]), "r"(a[3]), "r"(b[0]), "r"(b[1]));
}
__device__ __forceinline__ void cp_async16(uint32_t dst, const void* src) {
    asm volatile("cp.async.cg.shared.global [%0], [%1], 16;\n" :: "r"(dst), "l"(src));
}
__device__ __forceinline__ void cp_commit() {
    asm volatile("cp.async.commit_group;\n" ::: "memory");
}
__device__ __forceinline__ uint32_t packbf(float a, float b) {
    __nv_bfloat162 t = __floats2bfloat162_rn(a, b);
    return *(uint32_t*)&t;
}
__device__ __forceinline__ uint32_t packh(float a, float b) {
    __half2 t = __floats2half2_rn(a, b);
    return *(uint32_t*)&t;
}
__device__ __forceinline__ void split2(float a, float b, uint32_t& h, uint32_t& l) {
    bf16 ha = __float2bfloat16(a), hb = __float2bfloat16(b);
    h = ((uint32_t)__bfloat16_as_ushort(hb) << 16) | (uint32_t)__bfloat16_as_ushort(ha);
    l = packbf(a - __bfloat162float(ha), b - __bfloat162float(hb));
}
__device__ __forceinline__ void split2h(float a, float b, uint32_t& h, uint32_t& l) {
    __half ha = __float2half_rn(a), hb = __float2half_rn(b);
    h = ((uint32_t)__half_as_ushort(hb) << 16) | (uint32_t)__half_as_ushort(ha);
    l = packh(a - __half2float(ha), b - __half2float(hb));
}

// ---------------- fused operand conversion (single launch) -------------------
__global__ __launch_bounds__(256) void split_all_kernel(
    const float4* __restrict__ x,  const float4* __restrict__ Wq,
    const float4* __restrict__ Wk, const float4* __restrict__ Wv,
    const float4* __restrict__ Wo,
    __half* __restrict__ xh,
    __half* __restrict__ Wqh, __half* __restrict__ Wql,
    __half* __restrict__ Wkh, __half* __restrict__ Wkl,
    __half* __restrict__ Wvh, __half* __restrict__ Wvl,
    __half* __restrict__ Woh, __half* __restrict__ Wol)
{
    int blk = blockIdx.x;
    if (blk < 8192) {
        int i = blk*256 + threadIdx.x;
        float4 v = x[i];
        *(uint2*)(xh + (size_t)i*4) = make_uint2(packh(v.x, v.y), packh(v.z, v.w));
        return;
    }
    blk -= 8192;
    const float4* in; __half *hi, *lo;
    if (blk < 4096)      {                in = Wq; hi = Wqh; lo = Wql; }
    else if (blk < 6144) { blk -= 4096;   in = Wk; hi = Wkh; lo = Wkl; }
    else if (blk < 8192) { blk -= 6144;   in = Wv; hi = Wvh; lo = Wvl; }
    else                 { blk -= 8192;   in = Wo; hi = Woh; lo = Wol; }
    int i = blk*256 + threadIdx.x;
    float4 v = in[i];
    uint32_t h0, l0, h1, l1;
    split2h(v.x*WSCALE, v.y*WSCALE, h0, l0);
    split2h(v.z*WSCALE, v.w*WSCALE, h1, l1);
    *(uint2*)(hi + (size_t)i*4) = make_uint2(h0, h1);
    *(uint2*)(lo + (size_t)i*4) = make_uint2(l0, l1);
}

// ---------------- GEMM core macros (fp16 2-mma, 64x32 warp tiles) ------------
#define BKC 32
#define PAD 40
#define ARR (128*PAD)
#define STG3 (3*ARR)
#define GSMEM (3*STG3*2)        // 92160 bytes (3 stages)

#define GEMM_PROLOGUE()                                                         \
    const int tid  = threadIdx.x;                                               \
    const int lane = tid & 31, wid = tid >> 5;                                  \
    const int wm = (wid & 1) * 64;                                              \
    const int wn = (wid >> 1) * 32;                                             \
    const int m0 = tid >> 2;                                                    \
    const int c0 = (tid & 3) * 8;                                               \
    const int r_   = lane & 7, blk_ = lane >> 3;                                \
    const int a_row = ((blk_ & 1) << 3) + r_;                                   \
    const int a_col = (blk_ >> 1) << 3;                                         \
    const int b_row = ((blk_ >> 1) << 3) + r_;                                  \
    const int b_col = (blk_ & 1) << 3;                                          \
    float acc[4][4][4];                                                         \
    _Pragma("unroll") for (int i = 0; i < 4; i++)                               \
    _Pragma("unroll") for (int j = 0; j < 4; j++)                               \
    _Pragma("unroll") for (int k = 0; k < 4; k++) acc[i][j][k] = 0.f;

#define ISSUE(it, stage) do {                                                   \
    const int k0_ = (it) * BKC;                                                 \
    uint32_t sst_ = sbase + (uint32_t)(stage) * (STG3 * 2);                     \
    _Pragma("unroll")                                                           \
    for (int hh_ = 0; hh_ < 2; hh_++) {                                         \
        int m_ = m0 + hh_ * 64;                                                 \
        cp_async16(sst_ + (uint32_t)((m_*PAD + c0) * 2),                        \
                   gA + (size_t)(row0 + m_) * K + k0_ + c0);                    \
        cp_async16(sst_ + (uint32_t)((ARR + m_*PAD + c0) * 2),                  \
                   gB0 + (size_t)(col0 + m_) * K + k0_ + c0);                   \
        cp_async16(sst_ + (uint32_t)((2*ARR + m_*PAD + c0) * 2),                \
                   gB1 + (size_t)(col0 + m_) * K + k0_ + c0);                   \
    }                                                                           \
} while (0)

// Single barrier per iteration; 64x32 warp tile: B frags reused across 4 M-subtiles.
#define GEMM_MAINLOOP()                                                         \
    ISSUE(0, 0);                                                                \
    cp_commit();                                                                \
    ISSUE(1, 1);                                                                \
    cp_commit();                                                                \
    int stg = 0;                                                                \
    for (int it = 0; it < niter; it++) {                                        \
        if (it + 1 < niter) {                                                   \
            asm volatile("cp.async.wait_group 1;\n" ::: "memory");              \
        } else {                                                                \
            asm volatile("cp.async.wait_group 0;\n" ::: "memory");              \
        }                                                                       \
        __syncthreads();                                                        \
        if (it + 2 < niter) {                                                   \
            int s2 = stg + 2; if (s2 >= 3) s2 -= 3;                             \
            ISSUE(it + 2, s2);                                                  \
            cp_commit();                                                        \
        }                                                                       \
        const uint32_t sst = sbase + (uint32_t)stg * (STG3 * 2);                \
        _Pragma("unroll")                                                       \
        for (int ks = 0; ks < 2; ks++) {                                        \
            const int kofs = ks * 16;                                           \
            uint32_t a_[4][4], bh_[2][4], bl_[2][4];                            \
            _Pragma("unroll")                                                   \
            for (int mt = 0; mt < 4; mt++)                                      \
                ldsm4(a_[mt], sst + (uint32_t)(((wm + mt*16 + a_row)*PAD + kofs + a_col) * 2)); \
            _Pragma("unroll")                                                   \
            for (int p = 0; p < 2; p++) {                                       \
                uint32_t addr = sst + (uint32_t)((ARR + (wn + p*16 + b_row)*PAD + kofs + b_col) * 2); \
                ldsm4(bh_[p], addr);                                            \
                ldsm4(bl_[p], addr + ARR * 2);                                  \
            }                                                                   \
            _Pragma("unroll")                                                   \
            for (int mt = 0; mt < 4; mt++)                                      \
            _Pragma("unroll")                                                   \
                for (int p = 0; p < 2; p++) {                                   \
                    mma16816h(acc[mt][2*p],   a_[mt], &bh_[p][0]);              \
                    mma16816h(acc[mt][2*p+1], a_[mt], &bh_[p][2]);              \
                    mma16816h(acc[mt][2*p],   a_[mt], &bl_[p][0]);              \
                    mma16816h(acc[mt][2*p+1], a_[mt], &bl_[p][2]);              \
                }                                                               \
        }                                                                       \
        if (++stg == 3) stg = 0;                                                \
    }

// ---------------- merged QKV GEMM with fused norm/rope/split epilogue --------
__global__ __launch_bounds__(256, 2) void gemm_qkv(
    const __half* __restrict__ gA,
    const __half* __restrict__ Wqh_, const __half* __restrict__ Wql_,
    const __half* __restrict__ Wkh_, const __half* __restrict__ Wkl_,
    const __half* __restrict__ Wvh_, const __half* __restrict__ Wvl_,
    bf16* __restrict__ Qh, bf16* __restrict__ Ql,
    bf16* __restrict__ Kh, bf16* __restrict__ Kl,
    __half* __restrict__ Vh,
    const float* __restrict__ q_scale, const float* __restrict__ k_scale,
    const float* __restrict__ cosT, const float* __restrict__ sinT)
{
    extern __shared__ __half sm[];
    const uint32_t sbase = (uint32_t)__cvta_generic_to_shared(sm);
    const int bx = blockIdx.x;
    const int row0 = blockIdx.y * 128;
    const int K = DD;
    const int niter = K / BKC;

    int mode, hloc;
    const __half *gB0, *gB1;
    if (bx < 16)      { mode = 0; hloc = bx;      gB0 = Wqh_; gB1 = Wql_; }
    else if (bx < 24) { mode = 1; hloc = bx - 16; gB0 = Wkh_; gB1 = Wkl_; }
    else              { mode = 2; hloc = bx - 24; gB0 = Wvh_; gB1 = Wvl_; }
    const int col0 = hloc * 128;

    GEMM_PROLOGUE();
    GEMM_MAINLOOP();

    // ---- stage fp32 tile into smem (reuse pipeline smem) ----
    __syncthreads();
    float* sf = (float*)sm;                 // 128 x 132 floats = 67584 B <= 92160
    const int gr = lane >> 2, gc = (lane & 3) * 2;
#pragma unroll
    for (int mt = 0; mt < 4; mt++)
#pragma unroll
        for (int nt = 0; nt < 4; nt++) {
            int row = wm + mt*16 + gr;
            int col = wn + nt*8 + gc;
            *(float2*)&sf[(size_t)row*132 + col]     = make_float2(acc[mt][nt][0], acc[mt][nt][1]);
            *(float2*)&sf[(size_t)(row+8)*132 + col] = make_float2(acc[mt][nt][2], acc[mt][nt][3]);
        }
    __syncthreads();

    const float* scv = (mode == 0) ? q_scale : k_scale;
    const float smul = (mode == 0) ? QSCALE : 1.0f;
    const int   Hn   = (mode == 0) ? HQ : HKV;
    bf16* outh = (mode == 0) ? Qh : Kh;
    bf16* outl = (mode == 0) ? Ql : Kl;

    float4 sc4 = make_float4(1.f,1.f,1.f,1.f);
    if (mode < 2) sc4 = *(const float4*)&scv[lane*4];

    for (int rr = 0; rr < 16; rr++) {
        const int row  = wid*16 + rr;
        const int gtok = row0 + row;
        const int b = gtok >> 11, t = gtok & (TT-1);
        float4 v = *(float4*)&sf[(size_t)row*132 + lane*4];
        v.x *= INV256; v.y *= INV256; v.z *= INV256; v.w *= INV256;   // weight descale
        if (mode < 2) {
            float ss = v.x*v.x + v.y*v.y + v.z*v.z + v.w*v.w;
#pragma unroll
            for (int ofs = 16; ofs > 0; ofs >>= 1)
                ss += __shfl_xor_sync(0xffffffffu, ss, ofs);
            float inv = rsqrtf(ss*(1.0f/HD) + 1e-6f);
            v.x *= inv*sc4.x; v.y *= inv*sc4.y; v.z *= inv*sc4.z; v.w *= inv*sc4.w;
            float px = __shfl_xor_sync(0xffffffffu, v.x, 16);
            float py = __shfl_xor_sync(0xffffffffu, v.y, 16);
            float pz = __shfl_xor_sync(0xffffffffu, v.z, 16);
            float pw = __shfl_xor_sync(0xffffffffu, v.w, 16);
            float s = (lane < 16) ? -1.f : 1.f;
            float4 cs = *(const float4*)&cosT[(size_t)t*HD + lane*4];
            float4 sn = *(const float4*)&sinT[(size_t)t*HD + lane*4];
            float4 o;
            o.x = (v.x*cs.x + s*px*sn.x) * smul;
            o.y = (v.y*cs.y + s*py*sn.y) * smul;
            o.z = (v.z*cs.z + s*pz*sn.z) * smul;
            o.w = (v.w*cs.w + s*pw*sn.w) * smul;
            uint32_t H0, L0, H1, L1;
            split2(o.x, o.y, H0, L0);
            split2(o.z, o.w, H1, L1);
            size_t off = (((size_t)(b*Hn + hloc))*TT + t)*HD + lane*4;
            *(uint2*)&outh[off] = make_uint2(H0, H1);
            *(uint2*)&outl[off] = make_uint2(L0, L1);
        } else {
            size_t off = (size_t)gtok*(HKV*HD) + hloc*HD + lane*4;
            *(uint2*)&Vh[off] = make_uint2(packh(v.x, v.y), packh(v.z, v.w));
        }
    }
}

// ---------------- O-projection GEMM (fp32 epilogue, descale) -----------------
__global__ __launch_bounds__(256, 2) void gemm_o(
    const __half* __restrict__ gA,
    const __half* __restrict__ gB0, const __half* __restrict__ gB1,
    float* __restrict__ C, int N)
{
    extern __shared__ __half sm[];
    const uint32_t sbase = (uint32_t)__cvta_generic_to_shared(sm);
    const int row0 = blockIdx.y * 128, col0 = blockIdx.x * 128;
    const int K = DD;
    const int niter = K / BKC;

    GEMM_PROLOGUE();
    GEMM_MAINLOOP();

    const int gr = lane >> 2, gc = (lane & 3) * 2;
#pragma unroll
    for (int mt = 0; mt < 4; mt++)
#pragma unroll
        for (int nt = 0; nt < 4; nt++) {
            int row = row0 + wm + mt*16 + gr;
            int col = col0 + wn + nt*8 + gc;
            *(float2*)&C[(size_t)row*N + col]     = make_float2(acc[mt][nt][0]*INV256, acc[mt][nt][1]*INV256);
            *(float2*)&C[(size_t)(row+8)*N + col] = make_float2(acc[mt][nt][2]*INV256, acc[mt][nt][3]*INV256);
        }
}

// ---------------- fused flash attention -------------------------------------
// QK^T: bf16x3 (accuracy-critical). PV: fp16 1-mma (P and V single planes).
// 3-stage KV pipeline, single barrier per tile.
#define BQ 128
#define BK 64
#define FP 136
#define QELE (BQ*FP)
#define KELE (BK*FP)
#define QAREA (2*QELE)
#define STGKV (3*KELE)
#define FLASH_SMEM ((QAREA + 3*STGKV) * 2)   // 226304 bytes

__global__ __launch_bounds__(256) void flash_kernel(
    const bf16* __restrict__ Qh, const bf16* __restrict__ Ql,
    const bf16* __restrict__ Kh, const bf16* __restrict__ Kl,
    const __half* __restrict__ Vh,
    __half* __restrict__ ctxh)
{
    extern __shared__ bf16 smf[];
    const int tid = threadIdx.x, lane = tid & 31, wid = tid >> 5;
    const int qb = gridDim.x - 1 - blockIdx.x;
    const int bh = blockIdx.y;
    const int b = bh >> 4, h = bh & 15, kv = h >> 1;
    const int q0 = qb * BQ;
    const uint32_t sbase = (uint32_t)__cvta_generic_to_shared(smf);

    const bf16* Qhg = Qh + ((size_t)(b*HQ  + h )*TT + q0)*HD;
    const bf16* Qlg = Ql + ((size_t)(b*HQ  + h )*TT + q0)*HD;
    const bf16* Khg = Kh + ((size_t)(b*HKV + kv)*TT)*HD;
    const bf16* Klg = Kl + ((size_t)(b*HKV + kv)*TT)*HD;
    const __half* Vhg = Vh + (size_t)b*TT*(HKV*HD) + kv*HD;

#pragma unroll
    for (int i = 0; i < 8; i++) {
        int c = tid + i*256;
        int row = c >> 4, col = (c & 15) * 8;
        cp_async16(sbase + (uint32_t)((row*FP + col) * 2),        Qhg + (size_t)row*HD + col);
        cp_async16(sbase + (uint32_t)((QELE + row*FP + col) * 2), Qlg + (size_t)row*HD + col);
    }

#define ISSUEKV(kt, stage) do {                                                     \
    const int k0_ = (kt) * BK;                                                      \
    const uint32_t kb_ = sbase + (uint32_t)((QAREA + (stage)*STGKV) * 2);           \
    _Pragma("unroll")                                                               \
    for (int i_ = 0; i_ < 4; i_++) {                                                \
        int c_ = tid + i_*256;                                                      \
        int row_ = c_ >> 4, col_ = (c_ & 15) * 8;                                   \
        uint32_t so_ = (uint32_t)((row_*FP + col_) * 2);                            \
        cp_async16(kb_ + so_,            Khg + (size_t)(k0_+row_)*HD + col_);       \
        cp_async16(kb_ + KELE*2 + so_,   Klg + (size_t)(k0_+row_)*HD + col_);       \
        cp_async16(kb_ + 2*KELE*2 + so_, Vhg + (size_t)(k0_+row_)*(HKV*HD) + col_); \
    }                                                                               \
} while (0)

    const int nkt = 2*qb + 2;
    ISSUEKV(0, 0);
    cp_commit();
    ISSUEKV(1, 1);
    cp_commit();

    const int r   = lane & 7, blkid = lane >> 3;
    const int a_row = ((blkid & 1) << 3) + r;
    const int a_col = (blkid >> 1) << 3;
    const int b_row = ((blkid >> 1) << 3) + r;
    const int b_col = (blkid & 1) << 3;
    const int gr = lane >> 2;

    float oacc[16][4];
#pragma unroll
    for (int i = 0; i < 16; i++)
#pragma unroll
        for (int j = 0; j < 4; j++) oacc[i][j] = 0.f;
    float m0 = -1e30f, m1 = -1e30f, l0 = 0.f, l1 = 0.f;

    const int row0g = q0 + wid*16 + gr;
    const int row1g = row0g + 8;
    const int rowmin = q0 + wid*16;

    int stg = 0;
    for (int kt = 0; kt < nkt; kt++) {
        if (kt + 1 < nkt) {
            asm volatile("cp.async.wait_group 1;\n" ::: "memory");
        } else {
            asm volatile("cp.async.wait_group 0;\n" ::: "memory");
        }
        __syncthreads();
        if (kt + 2 < nkt) {
            int s2 = stg + 2; if (s2 >= 3) s2 -= 3;
            ISSUEKV(kt + 2, s2);
            cp_commit();
        }

        const int k0 = kt * BK;
        const uint32_t kb_s = sbase + (uint32_t)((QAREA + stg*STGKV) * 2);

        float sacc[8][4];
#pragma unroll
        for (int i = 0; i < 8; i++)
#pragma unroll
            for (int j = 0; j < 4; j++) sacc[i][j] = 0.f;

#pragma unroll
        for (int ks = 0; ks < 8; ks++) {
            uint32_t qa = sbase + (uint32_t)(((wid*16 + a_row)*FP + ks*16 + a_col) * 2);
            uint32_t qh[4], ql[4];
            ldsm4(qh, qa);
            ldsm4(ql, qa + QELE*2);
#pragma unroll
            for (int np = 0; np < 4; np++) {
                uint32_t ka = kb_s + (uint32_t)(((np*16 + b_row)*FP + ks*16 + b_col) * 2);
                uint32_t kh[4], kl[4];
                ldsm4(kh, ka);
                ldsm4(kl, ka + KELE*2);
                mma16816(sacc[2*np],   qh, &kh[0]);
                mma16816(sacc[2*np+1], qh, &kh[2]);
                mma16816(sacc[2*np],   qh, &kl[0]);
                mma16816(sacc[2*np+1], qh, &kl[2]);
                mma16816(sacc[2*np],   ql, &kh[0]);
                mma16816(sacc[2*np+1], ql, &kh[2]);
            }
        }

        // ---- causal mask (only near diagonal) + online softmax ----
        float mx0 = -1e30f, mx1 = -1e30f;
        if (k0 + 63 > rowmin) {
#pragma unroll
            for (int nt = 0; nt < 8; nt++) {
                int cg = k0 + nt*8 + (lane & 3)*2;
                if (cg     > row0g) sacc[nt][0] = -1e30f;
                if (cg + 1 > row0g) sacc[nt][1] = -1e30f;
                if (cg     > row1g) sacc[nt][2] = -1e30f;
                if (cg + 1 > row1g) sacc[nt][3] = -1e30f;
                mx0 = fmaxf(mx0, fmaxf(sacc[nt][0], sacc[nt][1]));
                mx1 = fmaxf(mx1, fmaxf(sacc[nt][2], sacc[nt][3]));
            }
        } else {
#pragma unroll
            for (int nt = 0; nt < 8; nt++) {
                mx0 = fmaxf(mx0, fmaxf(sacc[nt][0], sacc[nt][1]));
                mx1 = fmaxf(mx1, fmaxf(sacc[nt][2], sacc[nt][3]));
            }
        }
        mx0 = fmaxf(mx0, __shfl_xor_sync(0xffffffffu, mx0, 1));
        mx0 = fmaxf(mx0, __shfl_xor_sync(0xffffffffu, mx0, 2));
        mx1 = fmaxf(mx1, __shfl_xor_sync(0xffffffffu, mx1, 1));
        mx1 = fmaxf(mx1, __shfl_xor_sync(0xffffffffu, mx1, 2));

        float mn0 = fmaxf(m0, mx0), mn1 = fmaxf(m1, mx1);
        float sc0 = exp2f(m0 - mn0), sc1 = exp2f(m1 - mn1);
        m0 = mn0; m1 = mn1;

        float s0 = 0.f, s1 = 0.f;
#pragma unroll
        for (int nt = 0; nt < 8; nt++) {
            sacc[nt][0] = exp2f(sacc[nt][0] - m0);
            sacc[nt][1] = exp2f(sacc[nt][1] - m0);
            sacc[nt][2] = exp2f(sacc[nt][2] - m1);
            sacc[nt][3] = exp2f(sacc[nt][3] - m1);
            s0 += sacc[nt][0] + sacc[nt][1];
            s1 += sacc[nt][2] + sacc[nt][3];
        }
        s0 += __shfl_xor_sync(0xffffffffu, s0, 1);
        s0 += __shfl_xor_sync(0xffffffffu, s0, 2);
        s1 += __shfl_xor_sync(0xffffffffu, s1, 1);
        s1 += __shfl_xor_sync(0xffffffffu, s1, 2);
        l0 = l0*sc0 + s0;
        l1 = l1*sc1 + s1;

#pragma unroll
        for (int i = 0; i < 16; i++) {
            oacc[i][0] *= sc0; oacc[i][1] *= sc0;
            oacc[i][2] *= sc1; oacc[i][3] *= sc1;
        }

        // ---- O += P V (fp16 1-mma: P and V single planes) ----
        const int vrow = (lane & 7) + ((lane >> 3) & 1)*8;
        const int vcolb = ((lane >> 4) << 3);
#pragma unroll
        for (int kp = 0; kp < 4; kp++) {
            uint32_t ph[4];
#pragma unroll
            for (int half = 0; half < 2; half++) {
                ph[2*half]   = packh(sacc[2*kp+half][0], sacc[2*kp+half][1]);
                ph[2*half+1] = packh(sacc[2*kp+half][2], sacc[2*kp+half][3]);
            }
#pragma unroll
            for (int np = 0; np < 8; np++) {
                uint32_t va = kb_s + (uint32_t)((2*KELE + (kp*16 + vrow)*FP + np*16 + vcolb) * 2);
                uint32_t vh[4];
                ldsm4t(vh, va);
                mma16816h(oacc[2*np],   ph, &vh[0]);
                mma16816h(oacc[2*np+1], ph, &vh[2]);
            }
        }
        if (++stg == 3) stg = 0;
    }
#undef ISSUEKV

    // ---- epilogue: O /= l, write ctx fp16 single plane ----
    const float il0 = 1.f / l0, il1 = 1.f / l1;
    const size_t tok0 = (size_t)(b*TT + q0 + wid*16 + gr);
#pragma unroll
    for (int nt = 0; nt < 16; nt++) {
        int col = h*HD + nt*8 + (lane & 3)*2;
        *(uint32_t*)&ctxh[tok0*(HQ*HD) + col]     = packh(oacc[nt][0]*il0, oacc[nt][1]*il0);
        *(uint32_t*)&ctxh[(tok0+8)*(HQ*HD) + col] = packh(oacc[nt][2]*il1, oacc[nt][3]*il1);
    }
}

// ---------------- launch ------------------------------------------------------
extern "C" void kernel_launch(void* const* d_in, const int* in_sizes, int n_in,
                              void* d_out, int out_size)
{
    const float* x       = (const float*)d_in[0];
    const float* cosT    = (const float*)d_in[2];
    const float* sinT    = (const float*)d_in[3];
    const float* Wq      = (const float*)d_in[4];
    const float* Wk      = (const float*)d_in[5];
    const float* Wv      = (const float*)d_in[6];
    const float* Wo      = (const float*)d_in[7];
    const float* q_scale = (const float*)d_in[8];
    const float* k_scale = (const float*)d_in[9];
    float* out = (float*)d_out;

    __half *xh,*Wqh,*Wql,*Wkh,*Wkl,*Wvh,*Wvl,*Woh,*Wol,*ctxh,*Vh;
    bf16 *Qh,*Ql,*Kh,*Kl;
    cudaGetSymbolAddress((void**)&xh,   g_xh);
    cudaGetSymbolAddress((void**)&Wqh,  g_Wqh);  cudaGetSymbolAddress((void**)&Wql,  g_Wql);
    cudaGetSymbolAddress((void**)&Wkh,  g_Wkh);  cudaGetSymbolAddress((void**)&Wkl,  g_Wkl);
    cudaGetSymbolAddress((void**)&Wvh,  g_Wvh);  cudaGetSymbolAddress((void**)&Wvl,  g_Wvl);
    cudaGetSymbolAddress((void**)&Woh,  g_Woh);  cudaGetSymbolAddress((void**)&Wol,  g_Wol);
    cudaGetSymbolAddress((void**)&Qh,   g_Qh);   cudaGetSymbolAddress((void**)&Ql,   g_Ql);
    cudaGetSymbolAddress((void**)&Kh,   g_Kh);   cudaGetSymbolAddress((void**)&Kl,   g_Kl);
    cudaGetSymbolAddress((void**)&Vh,   g_Vh);
    cudaGetSymbolAddress((void**)&ctxh, g_ctxh);

    static bool attr_set = false;
    if (!attr_set) {
        cudaFuncSetAttribute(gemm_qkv,     cudaFuncAttributeMaxDynamicSharedMemorySize, GSMEM);
        cudaFuncSetAttribute(gemm_o,       cudaFuncAttributeMaxDynamicSharedMemorySize, GSMEM);
        cudaFuncSetAttribute(flash_kernel, cudaFuncAttributeMaxDynamicSharedMemorySize, FLASH_SMEM);
        attr_set = true;
    }

    // 0: all operand conversions in one launch
    split_all_kernel<<<20480, 256>>>(
        (const float4*)x, (const float4*)Wq, (const float4*)Wk,
        (const float4*)Wv, (const float4*)Wo,
        xh, Wqh, Wql, Wkh, Wkl, Wvh, Wvl, Woh, Wol);

    // 1: merged QKV projection (fp16 2-mma, 64x32 warp tiles) + fused epilogue
    gemm_qkv<<<dim3(32, MROWS/128), 256, GSMEM>>>(
        xh, Wqh, Wql, Wkh, Wkl, Wvh, Wvl,
        Qh, Ql, Kh, Kl, Vh, q_scale, k_scale, cosT, sinT);

    // 2: fused flash attention (QK bf16x3, PV fp16 1-mma)
    flash_kernel<<<dim3(TT/BQ, BB*HQ), 256, FLASH_SMEM>>>(Qh, Ql, Kh, Kl, Vh, ctxh);

    // 3: output projection (fp16 2-mma, 64x32 warp tiles, descale)
    gemm_o<<<dim3(DD/128, MROWS/128), 256, GSMEM>>>(ctxh, Woh, Wol, out, DD);
}

// round 13
// speedup vs baseline: 3.5920x; 1.1245x over previous
#include <cuda_runtime.h>
#include <cuda_bf16.h>
#include <cuda_fp16.h>
#include <cstdint>
#include <cstddef>

// Problem constants
#define BB 2
#define TT 2048
#define DD 2048
#define HQ 16
#define HKV 8
#define HD 128
#define MROWS (BB*TT)   // 4096

typedef __nv_bfloat16 bf16;

// log2(e)/sqrt(128)
#define QSCALE 0.12752551164384637f
#define WSCALE 256.0f
#define INV256 0.00390625f

// ---------------- scratch (static device globals) ---------------------------
__device__ __half g_xh [(size_t)MROWS*DD];                      // single plane
__device__ __half g_Wqh[(size_t)HQ*HD*DD],  g_Wql[(size_t)HQ*HD*DD];
__device__ __half g_Wkh[(size_t)HKV*HD*DD], g_Wkl[(size_t)HKV*HD*DD];
__device__ __half g_Wvh[(size_t)HKV*HD*DD], g_Wvl[(size_t)HKV*HD*DD];
__device__ __half g_Woh[(size_t)DD*HQ*HD];                      // single plane
__device__ bf16 g_Qh [(size_t)BB*HQ*TT*HD],  g_Ql [(size_t)BB*HQ*TT*HD];
__device__ bf16 g_Kh [(size_t)BB*HKV*TT*HD], g_Kl [(size_t)BB*HKV*TT*HD];
__device__ __half g_Vh [(size_t)MROWS*HKV*HD];                  // single plane
__device__ __half g_ctxh[(size_t)MROWS*HQ*HD];                  // single plane

// ---------------- PTX helpers ------------------------------------------------
__device__ __forceinline__ void ldsm4(uint32_t* r, uint32_t a) {
    asm volatile("ldmatrix.sync.aligned.m8n8.x4.shared.b16 {%0,%1,%2,%3}, [%4];\n"
        : "=r"(r[0]), "=r"(r[1]), "=r"(r[2]), "=r"(r[3]) : "r"(a));
}
__device__ __forceinline__ void ldsm4t(uint32_t* r, uint32_t a) {
    asm volatile("ldmatrix.sync.aligned.m8n8.x4.trans.shared.b16 {%0,%1,%2,%3}, [%4];\n"
        : "=r"(r[0]), "=r"(r[1]), "=r"(r[2]), "=r"(r[3]) : "r"(a));
}
__device__ __forceinline__ void mma16816(float* c, const uint32_t* a, const uint32_t* b) {
    asm volatile("mma.sync.aligned.m16n8k16.row.col.f32.bf16.bf16.f32 "
        "{%0,%1,%2,%3}, {%4,%5,%6,%7}, {%8,%9}, {%0,%1,%2,%3};\n"
        : "+f"(c[0]), "+f"(c[1]), "+f"(c[2]), "+f"(c[3])
        : "r"(a[0]), "r"(a[1]), "r"(a[2]), "r"(a[3]), "r"(b[0]), "r"(b[1]));
}
__device__ __forceinline__ void mma16816h(float* c, const uint32_t* a, const uint32_t* b) {
    asm volatile("mma.sync.aligned.m16n8k16.row.col.f32.f16.f16.f32 "
        "{%0,%1,%2,%3}, {%4,%5,%6,%7}, {%8,%9}, {%0,%1,%2,%3};\n"
        : "+f"(c[0]), "+f"(c[1]), "+f"(c[2]), "+f"(c[3])
        : "r"(a[0]), "r"(a[1]), "r"(a[2]), "r"(a[3]), "r"(b[0]), "r"(b[1]));
}
__device__ __forceinline__ void cp_async16(uint32_t dst, const void* src) {
    asm volatile("cp.async.cg.shared.global [%0], [%1], 16;\n" :: "r"(dst), "l"(src));
}
__device__ __forceinline__ void cp_commit() {
    asm volatile("cp.async.commit_group;\n" ::: "memory");
}
__device__ __forceinline__ uint32_t packbf(float a, float b) {
    __nv_bfloat162 t = __floats2bfloat162_rn(a, b);
    return *(uint32_t*)&t;
}
__device__ __forceinline__ uint32_t packh(float a, float b) {
    __half2 t = __floats2half2_rn(a, b);
    return *(uint32_t*)&t;
}
__device__ __forceinline__ void split2(float a, float b, uint32_t& h, uint32_t& l) {
    bf16 ha = __float2bfloat16(a), hb = __float2bfloat16(b);
    h = ((uint32_t)__bfloat16_as_ushort(hb) << 16) | (uint32_t)__bfloat16_as_ushort(ha);
    l = packbf(a - __bfloat162float(ha), b - __bfloat162float(hb));
}
__device__ __forceinline__ void split2h(float a, float b, uint32_t& h, uint32_t& l) {
    __half ha = __float2half_rn(a), hb = __float2half_rn(b);
    h = ((uint32_t)__half_as_ushort(hb) << 16) | (uint32_t)__half_as_ushort(ha);
    l = packh(a - __half2float(ha), b - __half2float(hb));
}

// ---------------- fused operand conversion (single launch) -------------------
// blocks [0,8192): x; [8192,12288): Wq; [12288,14336): Wk; [14336,16384): Wv;
// [16384,20480): Wo (single plane).
__global__ __launch_bounds__(256) void split_all_kernel(
    const float4* __restrict__ x,  const float4* __restrict__ Wq,
    const float4* __restrict__ Wk, const float4* __restrict__ Wv,
    const float4* __restrict__ Wo,
    __half* __restrict__ xh,
    __half* __restrict__ Wqh, __half* __restrict__ Wql,
    __half* __restrict__ Wkh, __half* __restrict__ Wkl,
    __half* __restrict__ Wvh, __half* __restrict__ Wvl,
    __half* __restrict__ Woh)
{
    int blk = blockIdx.x;
    if (blk < 8192) {
        int i = blk*256 + threadIdx.x;
        float4 v = x[i];
        *(uint2*)(xh + (size_t)i*4) = make_uint2(packh(v.x, v.y), packh(v.z, v.w));
        return;
    }
    blk -= 8192;
    if (blk >= 8192) {   // Wo single plane
        int i = (blk - 8192)*256 + threadIdx.x;
        float4 v = Wo[i];
        *(uint2*)(Woh + (size_t)i*4) =
            make_uint2(packh(v.x*WSCALE, v.y*WSCALE), packh(v.z*WSCALE, v.w*WSCALE));
        return;
    }
    const float4* in; __half *hi, *lo;
    if (blk < 4096)      {                in = Wq; hi = Wqh; lo = Wql; }
    else if (blk < 6144) { blk -= 4096;   in = Wk; hi = Wkh; lo = Wkl; }
    else                 { blk -= 6144;   in = Wv; hi = Wvh; lo = Wvl; }
    int i = blk*256 + threadIdx.x;
    float4 v = in[i];
    uint32_t h0, l0, h1, l1;
    split2h(v.x*WSCALE, v.y*WSCALE, h0, l0);
    split2h(v.z*WSCALE, v.w*WSCALE, h1, l1);
    *(uint2*)(hi + (size_t)i*4) = make_uint2(h0, h1);
    *(uint2*)(lo + (size_t)i*4) = make_uint2(l0, l1);
}

// ---------------- GEMM core macros (fp16, 64x32 warp tiles, 3-stage) ---------
#define BKC 32
#define PAD 40
#define ARR (128*PAD)
#define STG3 (3*ARR)
#define GSMEM (3*STG3*2)        // 92160 bytes (2-plane B)
#define STG2 (2*ARR)
#define GSMEM1 (3*STG2*2)       // 61440 bytes (1-plane B)

#define GEMM_PROLOGUE()                                                         \
    const int tid  = threadIdx.x;                                               \
    const int lane = tid & 31, wid = tid >> 5;                                  \
    const int wm = (wid & 1) * 64;                                              \
    const int wn = (wid >> 1) * 32;                                             \
    const int m0 = tid >> 2;                                                    \
    const int c0 = (tid & 3) * 8;                                               \
    const int r_   = lane & 7, blk_ = lane >> 3;                                \
    const int a_row = ((blk_ & 1) << 3) + r_;                                   \
    const int a_col = (blk_ >> 1) << 3;                                         \
    const int b_row = ((blk_ >> 1) << 3) + r_;                                  \
    const int b_col = (blk_ & 1) << 3;                                          \
    float acc[4][4][4];                                                         \
    _Pragma("unroll") for (int i = 0; i < 4; i++)                               \
    _Pragma("unroll") for (int j = 0; j < 4; j++)                               \
    _Pragma("unroll") for (int k = 0; k < 4; k++) acc[i][j][k] = 0.f;

// ---- 2-plane B variant (QKV) ----
#define ISSUE(it, stage) do {                                                   \
    const int k0_ = (it) * BKC;                                                 \
    uint32_t sst_ = sbase + (uint32_t)(stage) * (STG3 * 2);                     \
    _Pragma("unroll")                                                           \
    for (int hh_ = 0; hh_ < 2; hh_++) {                                         \
        int m_ = m0 + hh_ * 64;                                                 \
        cp_async16(sst_ + (uint32_t)((m_*PAD + c0) * 2),                        \
                   gA + (size_t)(row0 + m_) * K + k0_ + c0);                    \
        cp_async16(sst_ + (uint32_t)((ARR + m_*PAD + c0) * 2),                  \
                   gB0 + (size_t)(col0 + m_) * K + k0_ + c0);                   \
        cp_async16(sst_ + (uint32_t)((2*ARR + m_*PAD + c0) * 2),                \
                   gB1 + (size_t)(col0 + m_) * K + k0_ + c0);                   \
    }                                                                           \
} while (0)

#define GEMM_MAINLOOP()                                                         \
    ISSUE(0, 0);                                                                \
    cp_commit();                                                                \
    ISSUE(1, 1);                                                                \
    cp_commit();                                                                \
    int stg = 0;                                                                \
    for (int it = 0; it < niter; it++) {                                        \
        if (it + 1 < niter) {                                                   \
            asm volatile("cp.async.wait_group 1;\n" ::: "memory");              \
        } else {                                                                \
            asm volatile("cp.async.wait_group 0;\n" ::: "memory");              \
        }                                                                       \
        __syncthreads();                                                        \
        if (it + 2 < niter) {                                                   \
            int s2 = stg + 2; if (s2 >= 3) s2 -= 3;                             \
            ISSUE(it + 2, s2);                                                  \
            cp_commit();                                                        \
        }                                                                       \
        const uint32_t sst = sbase + (uint32_t)stg * (STG3 * 2);                \
        _Pragma("unroll")                                                       \
        for (int ks = 0; ks < 2; ks++) {                                        \
            const int kofs = ks * 16;                                           \
            uint32_t a_[4][4], bh_[2][4], bl_[2][4];                            \
            _Pragma("unroll")                                                   \
            for (int mt = 0; mt < 4; mt++)                                      \
                ldsm4(a_[mt], sst + (uint32_t)(((wm + mt*16 + a_row)*PAD + kofs + a_col) * 2)); \
            _Pragma("unroll")                                                   \
            for (int p = 0; p < 2; p++) {                                       \
                uint32_t addr = sst + (uint32_t)((ARR + (wn + p*16 + b_row)*PAD + kofs + b_col) * 2); \
                ldsm4(bh_[p], addr);                                            \
                ldsm4(bl_[p], addr + ARR * 2);                                  \
            }                                                                   \
            _Pragma("unroll")                                                   \
            for (int mt = 0; mt < 4; mt++)                                      \
            _Pragma("unroll")                                                   \
                for (int p = 0; p < 2; p++) {                                   \
                    mma16816h(acc[mt][2*p],   a_[mt], &bh_[p][0]);              \
                    mma16816h(acc[mt][2*p+1], a_[mt], &bh_[p][2]);              \
                    mma16816h(acc[mt][2*p],   a_[mt], &bl_[p][0]);              \
                    mma16816h(acc[mt][2*p+1], a_[mt], &bl_[p][2]);              \
                }                                                               \
        }                                                                       \
        if (++stg == 3) stg = 0;                                                \
    }

// ---- 1-plane B variant (O projection) ----
#define ISSUE1(it, stage) do {                                                  \
    const int k0_ = (it) * BKC;                                                 \
    uint32_t sst_ = sbase + (uint32_t)(stage) * (STG2 * 2);                     \
    _Pragma("unroll")                                                           \
    for (int hh_ = 0; hh_ < 2; hh_++) {                                         \
        int m_ = m0 + hh_ * 64;                                                 \
        cp_async16(sst_ + (uint32_t)((m_*PAD + c0) * 2),                        \
                   gA + (size_t)(row0 + m_) * K + k0_ + c0);                    \
        cp_async16(sst_ + (uint32_t)((ARR + m_*PAD + c0) * 2),                  \
                   gB0 + (size_t)(col0 + m_) * K + k0_ + c0);                   \
    }                                                                           \
} while (0)

#define GEMM_MAINLOOP1()                                                        \
    ISSUE1(0, 0);                                                               \
    cp_commit();                                                                \
    ISSUE1(1, 1);                                                               \
    cp_commit();                                                                \
    int stg = 0;                                                                \
    for (int it = 0; it < niter; it++) {                                        \
        if (it + 1 < niter) {                                                   \
            asm volatile("cp.async.wait_group 1;\n" ::: "memory");              \
        } else {                                                                \
            asm volatile("cp.async.wait_group 0;\n" ::: "memory");              \
        }                                                                       \
        __syncthreads();                                                        \
        if (it + 2 < niter) {                                                   \
            int s2 = stg + 2; if (s2 >= 3) s2 -= 3;                             \
            ISSUE1(it + 2, s2);                                                 \
            cp_commit();                                                        \
        }                                                                       \
        const uint32_t sst = sbase + (uint32_t)stg * (STG2 * 2);                \
        _Pragma("unroll")                                                       \
        for (int ks = 0; ks < 2; ks++) {                                        \
            const int kofs = ks * 16;                                           \
            uint32_t a_[4][4], bh_[2][4];                                       \
            _Pragma("unroll")                                                   \
            for (int mt = 0; mt < 4; mt++)                                      \
                ldsm4(a_[mt], sst + (uint32_t)(((wm + mt*16 + a_row)*PAD + kofs + a_col) * 2)); \
            _Pragma("unroll")                                                   \
            for (int p = 0; p < 2; p++)                                         \
                ldsm4(bh_[p], sst + (uint32_t)((ARR + (wn + p*16 + b_row)*PAD + kofs + b_col) * 2)); \
            _Pragma("unroll")                                                   \
            for (int mt = 0; mt < 4; mt++)                                      \
            _Pragma("unroll")                                                   \
                for (int p = 0; p < 2; p++) {                                   \
                    mma16816h(acc[mt][2*p],   a_[mt], &bh_[p][0]);              \
                    mma16816h(acc[mt][2*p+1], a_[mt], &bh_[p][2]);              \
                }                                                               \
        }                                                                       \
        if (++stg == 3) stg = 0;                                                \
    }

// ---------------- merged QKV GEMM with fused norm/rope/split epilogue --------
__global__ __launch_bounds__(256, 2) void gemm_qkv(
    const __half* __restrict__ gA,
    const __half* __restrict__ Wqh_, const __half* __restrict__ Wql_,
    const __half* __restrict__ Wkh_, const __half* __restrict__ Wkl_,
    const __half* __restrict__ Wvh_, const __half* __restrict__ Wvl_,
    bf16* __restrict__ Qh, bf16* __restrict__ Ql,
    bf16* __restrict__ Kh, bf16* __restrict__ Kl,
    __half* __restrict__ Vh,
    const float* __restrict__ q_scale, const float* __restrict__ k_scale,
    const float* __restrict__ cosT, const float* __restrict__ sinT)
{
    extern __shared__ __half sm[];
    const uint32_t sbase = (uint32_t)__cvta_generic_to_shared(sm);
    const int bx = blockIdx.x;
    const int row0 = blockIdx.y * 128;
    const int K = DD;
    const int niter = K / BKC;

    int mode, hloc;
    const __half *gB0, *gB1;
    if (bx < 16)      { mode = 0; hloc = bx;      gB0 = Wqh_; gB1 = Wql_; }
    else if (bx < 24) { mode = 1; hloc = bx - 16; gB0 = Wkh_; gB1 = Wkl_; }
    else              { mode = 2; hloc = bx - 24; gB0 = Wvh_; gB1 = Wvl_; }
    const int col0 = hloc * 128;

    GEMM_PROLOGUE();
    GEMM_MAINLOOP();

    // ---- stage fp32 tile into smem (reuse pipeline smem) ----
    __syncthreads();
    float* sf = (float*)sm;                 // 128 x 132 floats = 67584 B <= 92160
    const int gr = lane >> 2, gc = (lane & 3) * 2;
#pragma unroll
    for (int mt = 0; mt < 4; mt++)
#pragma unroll
        for (int nt = 0; nt < 4; nt++) {
            int row = wm + mt*16 + gr;
            int col = wn + nt*8 + gc;
            *(float2*)&sf[(size_t)row*132 + col]     = make_float2(acc[mt][nt][0], acc[mt][nt][1]);
            *(float2*)&sf[(size_t)(row+8)*132 + col] = make_float2(acc[mt][nt][2], acc[mt][nt][3]);
        }
    __syncthreads();

    const float* scv = (mode == 0) ? q_scale : k_scale;
    const float smul = (mode == 0) ? QSCALE : 1.0f;
    const int   Hn   = (mode == 0) ? HQ : HKV;
    bf16* outh = (mode == 0) ? Qh : Kh;
    bf16* outl = (mode == 0) ? Ql : Kl;

    float4 sc4 = make_float4(1.f,1.f,1.f,1.f);
    if (mode < 2) sc4 = *(const float4*)&scv[lane*4];

    for (int rr = 0; rr < 16; rr++) {
        const int row  = wid*16 + rr;
        const int gtok = row0 + row;
        const int b = gtok >> 11, t = gtok & (TT-1);
        float4 v = *(float4*)&sf[(size_t)row*132 + lane*4];
        v.x *= INV256; v.y *= INV256; v.z *= INV256; v.w *= INV256;   // weight descale
        if (mode < 2) {
            float ss = v.x*v.x + v.y*v.y + v.z*v.z + v.w*v.w;
#pragma unroll
            for (int ofs = 16; ofs > 0; ofs >>= 1)
                ss += __shfl_xor_sync(0xffffffffu, ss, ofs);
            float inv = rsqrtf(ss*(1.0f/HD) + 1e-6f);
            v.x *= inv*sc4.x; v.y *= inv*sc4.y; v.z *= inv*sc4.z; v.w *= inv*sc4.w;
            float px = __shfl_xor_sync(0xffffffffu, v.x, 16);
            float py = __shfl_xor_sync(0xffffffffu, v.y, 16);
            float pz = __shfl_xor_sync(0xffffffffu, v.z, 16);
            float pw = __shfl_xor_sync(0xffffffffu, v.w, 16);
            float s = (lane < 16) ? -1.f : 1.f;
            float4 cs = *(const float4*)&cosT[(size_t)t*HD + lane*4];
            float4 sn = *(const float4*)&sinT[(size_t)t*HD + lane*4];
            float4 o;
            o.x = (v.x*cs.x + s*px*sn.x) * smul;
            o.y = (v.y*cs.y + s*py*sn.y) * smul;
            o.z = (v.z*cs.z + s*pz*sn.z) * smul;
            o.w = (v.w*cs.w + s*pw*sn.w) * smul;
            uint32_t H0, L0, H1, L1;
            split2(o.x, o.y, H0, L0);
            split2(o.z, o.w, H1, L1);
            size_t off = (((size_t)(b*Hn + hloc))*TT + t)*HD + lane*4;
            *(uint2*)&outh[off] = make_uint2(H0, H1);
            *(uint2*)&outl[off] = make_uint2(L0, L1);
        } else {
            size_t off = (size_t)gtok*(HKV*HD) + hloc*HD + lane*4;
            *(uint2*)&Vh[off] = make_uint2(packh(v.x, v.y), packh(v.z, v.w));
        }
    }
}

// ---------------- O-projection GEMM (1-plane weights, fp32 epilogue) ---------
__global__ __launch_bounds__(256, 2) void gemm_o(
    const __half* __restrict__ gA,
    const __half* __restrict__ gB0,
    float* __restrict__ C, int N)
{
    extern __shared__ __half sm[];
    const uint32_t sbase = (uint32_t)__cvta_generic_to_shared(sm);
    const int row0 = blockIdx.y * 128, col0 = blockIdx.x * 128;
    const int K = DD;
    const int niter = K / BKC;

    GEMM_PROLOGUE();
    GEMM_MAINLOOP1();

    const int gr = lane >> 2, gc = (lane & 3) * 2;
#pragma unroll
    for (int mt = 0; mt < 4; mt++)
#pragma unroll
        for (int nt = 0; nt < 4; nt++) {
            int row = row0 + wm + mt*16 + gr;
            int col = col0 + wn + nt*8 + gc;
            *(float2*)&C[(size_t)row*N + col]     = make_float2(acc[mt][nt][0]*INV256, acc[mt][nt][1]*INV256);
            *(float2*)&C[(size_t)(row+8)*N + col] = make_float2(acc[mt][nt][2]*INV256, acc[mt][nt][3]*INV256);
        }
}

// ---------------- fused flash attention -------------------------------------
// QK^T: bf16x3 (accuracy-critical). PV: fp16 1-mma (P and V single planes).
// 3-stage KV pipeline, single barrier per tile.
#define BQ 128
#define BK 64
#define FP 136
#define QELE (BQ*FP)
#define KELE (BK*FP)
#define QAREA (2*QELE)
#define STGKV (3*KELE)
#define FLASH_SMEM ((QAREA + 3*STGKV) * 2)   // 226304 bytes

__global__ __launch_bounds__(256) void flash_kernel(
    const bf16* __restrict__ Qh, const bf16* __restrict__ Ql,
    const bf16* __restrict__ Kh, const bf16* __restrict__ Kl,
    const __half* __restrict__ Vh,
    __half* __restrict__ ctxh)
{
    extern __shared__ bf16 smf[];
    const int tid = threadIdx.x, lane = tid & 31, wid = tid >> 5;
    const int qb = gridDim.x - 1 - blockIdx.x;
    const int bh = blockIdx.y;
    const int b = bh >> 4, h = bh & 15, kv = h >> 1;
    const int q0 = qb * BQ;
    const uint32_t sbase = (uint32_t)__cvta_generic_to_shared(smf);

    const bf16* Qhg = Qh + ((size_t)(b*HQ  + h )*TT + q0)*HD;
    const bf16* Qlg = Ql + ((size_t)(b*HQ  + h )*TT + q0)*HD;
    const bf16* Khg = Kh + ((size_t)(b*HKV + kv)*TT)*HD;
    const bf16* Klg = Kl + ((size_t)(b*HKV + kv)*TT)*HD;
    const __half* Vhg = Vh + (size_t)b*TT*(HKV*HD) + kv*HD;

#pragma unroll
    for (int i = 0; i < 8; i++) {
        int c = tid + i*256;
        int row = c >> 4, col = (c & 15) * 8;
        cp_async16(sbase + (uint32_t)((row*FP + col) * 2),        Qhg + (size_t)row*HD + col);
        cp_async16(sbase + (uint32_t)((QELE + row*FP + col) * 2), Qlg + (size_t)row*HD + col);
    }

#define ISSUEKV(kt, stage) do {                                                     \
    const int k0_ = (kt) * BK;                                                      \
    const uint32_t kb_ = sbase + (uint32_t)((QAREA + (stage)*STGKV) * 2);           \
    _Pragma("unroll")                                                               \
    for (int i_ = 0; i_ < 4; i_++) {                                                \
        int c_ = tid + i_*256;                                                      \
        int row_ = c_ >> 4, col_ = (c_ & 15) * 8;                                   \
        uint32_t so_ = (uint32_t)((row_*FP + col_) * 2);                            \
        cp_async16(kb_ + so_,            Khg + (size_t)(k0_+row_)*HD + col_);       \
        cp_async16(kb_ + KELE*2 + so_,   Klg + (size_t)(k0_+row_)*HD + col_);       \
        cp_async16(kb_ + 2*KELE*2 + so_, Vhg + (size_t)(k0_+row_)*(HKV*HD) + col_); \
    }                                                                               \
} while (0)

    const int nkt = 2*qb + 2;
    ISSUEKV(0, 0);
    cp_commit();
    ISSUEKV(1, 1);
    cp_commit();

    const int r   = lane & 7, blkid = lane >> 3;
    const int a_row = ((blkid & 1) << 3) + r;
    const int a_col = (blkid >> 1) << 3;
    const int b_row = ((blkid >> 1) << 3) + r;
    const int b_col = (blkid & 1) << 3;
    const int gr = lane >> 2;

    float oacc[16][4];
#pragma unroll
    for (int i = 0; i < 16; i++)
#pragma unroll
        for (int j = 0; j < 4; j++) oacc[i][j] = 0.f;
    float m0 = -1e30f, m1 = -1e30f, l0 = 0.f, l1 = 0.f;

    const int row0g = q0 + wid*16 + gr;
    const int row1g = row0g + 8;
    const int rowmin = q0 + wid*16;

    int stg = 0;
    for (int kt = 0; kt < nkt; kt++) {
        if (kt + 1 < nkt) {
            asm volatile("cp.async.wait_group 1;\n" ::: "memory");
        } else {
            asm volatile("cp.async.wait_group 0;\n" ::: "memory");
        }
        __syncthreads();
        if (kt + 2 < nkt) {
            int s2 = stg + 2; if (s2 >= 3) s2 -= 3;
            ISSUEKV(kt + 2, s2);
            cp_commit();
        }

        const int k0 = kt * BK;
        const uint32_t kb_s = sbase + (uint32_t)((QAREA + stg*STGKV) * 2);

        float sacc[8][4];
#pragma unroll
        for (int i = 0; i < 8; i++)
#pragma unroll
            for (int j = 0; j < 4; j++) sacc[i][j] = 0.f;

#pragma unroll
        for (int ks = 0; ks < 8; ks++) {
            uint32_t qa = sbase + (uint32_t)(((wid*16 + a_row)*FP + ks*16 + a_col) * 2);
            uint32_t qh[4], ql[4];
            ldsm4(qh, qa);
            ldsm4(ql, qa + QELE*2);
#pragma unroll
            for (int np = 0; np < 4; np++) {
                uint32_t ka = kb_s + (uint32_t)(((np*16 + b_row)*FP + ks*16 + b_col) * 2);
                uint32_t kh[4], kl[4];
                ldsm4(kh, ka);
                ldsm4(kl, ka + KELE*2);
                mma16816(sacc[2*np],   qh, &kh[0]);
                mma16816(sacc[2*np+1], qh, &kh[2]);
                mma16816(sacc[2*np],   qh, &kl[0]);
                mma16816(sacc[2*np+1], qh, &kl[2]);
                mma16816(sacc[2*np],   ql, &kh[0]);
                mma16816(sacc[2*np+1], ql, &kh[2]);
            }
        }

        // ---- causal mask (only near diagonal) + online softmax ----
        float mx0 = -1e30f, mx1 = -1e30f;
        if (k0 + 63 > rowmin) {
#pragma unroll
            for (int nt = 0; nt < 8; nt++) {
                int cg = k0 + nt*8 + (lane & 3)*2;
                if (cg     > row0g) sacc[nt][0] = -1e30f;
                if (cg + 1 > row0g) sacc[nt][1] = -1e30f;
                if (cg     > row1g) sacc[nt][2] = -1e30f;
                if (cg + 1 > row1g) sacc[nt][3] = -1e30f;
                mx0 = fmaxf(mx0, fmaxf(sacc[nt][0], sacc[nt][1]));
                mx1 = fmaxf(mx1, fmaxf(sacc[nt][2], sacc[nt][3]));
            }
        } else {
#pragma unroll
            for (int nt = 0; nt < 8; nt++) {
                mx0 = fmaxf(mx0, fmaxf(sacc[nt][0], sacc[nt][1]));
                mx1 = fmaxf(mx1, fmaxf(sacc[nt][2], sacc[nt][3]));
            }
        }
        mx0 = fmaxf(mx0, __shfl_xor_sync(0xffffffffu, mx0, 1));
        mx0 = fmaxf(mx0, __shfl_xor_sync(0xffffffffu, mx0, 2));
        mx1 = fmaxf(mx1, __shfl_xor_sync(0xffffffffu, mx1, 1));
        mx1 = fmaxf(mx1, __shfl_xor_sync(0xffffffffu, mx1, 2));

        float mn0 = fmaxf(m0, mx0), mn1 = fmaxf(m1, mx1);
        float sc0 = exp2f(m0 - mn0), sc1 = exp2f(m1 - mn1);
        m0 = mn0; m1 = mn1;

        float s0 = 0.f, s1 = 0.f;
#pragma unroll
        for (int nt = 0; nt < 8; nt++) {
            sacc[nt][0] = exp2f(sacc[nt][0] - m0);
            sacc[nt][1] = exp2f(sacc[nt][1] - m0);
            sacc[nt][2] = exp2f(sacc[nt][2] - m1);
            sacc[nt][3] = exp2f(sacc[nt][3] - m1);
            s0 += sacc[nt][0] + sacc[nt][1];
            s1 += sacc[nt][2] + sacc[nt][3];
        }
        s0 += __shfl_xor_sync(0xffffffffu, s0, 1);
        s0 += __shfl_xor_sync(0xffffffffu, s0, 2);
        s1 += __shfl_xor_sync(0xffffffffu, s1, 1);
        s1 += __shfl_xor_sync(0xffffffffu, s1, 2);
        l0 = l0*sc0 + s0;
        l1 = l1*sc1 + s1;

#pragma unroll
        for (int i = 0; i < 16; i++) {
            oacc[i][0] *= sc0; oacc[i][1] *= sc0;
            oacc[i][2] *= sc1; oacc[i][3] *= sc1;
        }

        // ---- O += P V (fp16 1-mma: P and V single planes) ----
        const int vrow = (lane & 7) + ((lane >> 3) & 1)*8;
        const int vcolb = ((lane >> 4) << 3);
#pragma unroll
        for (int kp = 0; kp < 4; kp++) {
            uint32_t ph[4];
#pragma unroll
            for (int half = 0; half < 2; half++) {
                ph[2*half]   = packh(sacc[2*kp+half][0], sacc[2*kp+half][1]);
                ph[2*half+1] = packh(sacc[2*kp+half][2], sacc[2*kp+half][3]);
            }
#pragma unroll
            for (int np = 0; np < 8; np++) {
                uint32_t va = kb_s + (uint32_t)((2*KELE + (kp*16 + vrow)*FP + np*16 + vcolb) * 2);
                uint32_t vh[4];
                ldsm4t(vh, va);
                mma16816h(oacc[2*np],   ph, &vh[0]);
                mma16816h(oacc[2*np+1], ph, &vh[2]);
            }
        }
        if (++stg == 3) stg = 0;
    }
#undef ISSUEKV

    // ---- epilogue: O /= l, write ctx fp16 single plane ----
    const float il0 = 1.f / l0, il1 = 1.f / l1;
    const size_t tok0 = (size_t)(b*TT + q0 + wid*16 + gr);
#pragma unroll
    for (int nt = 0; nt < 16; nt++) {
        int col = h*HD + nt*8 + (lane & 3)*2;
        *(uint32_t*)&ctxh[tok0*(HQ*HD) + col]     = packh(oacc[nt][0]*il0, oacc[nt][1]*il0);
        *(uint32_t*)&ctxh[(tok0+8)*(HQ*HD) + col] = packh(oacc[nt][2]*il1, oacc[nt][3]*il1);
    }
}

// ---------------- launch ------------------------------------------------------
extern "C" void kernel_launch(void* const* d_in, const int* in_sizes, int n_in,
                              void* d_out, int out_size)
{
    const float* x       = (const float*)d_in[0];
    const float* cosT    = (const float*)d_in[2];
    const float* sinT    = (const float*)d_in[3];
    const float* Wq      = (const float*)d_in[4];
    const float* Wk      = (const float*)d_in[5];
    const float* Wv      = (const float*)d_in[6];
    const float* Wo      = (const float*)d_in[7];
    const float* q_scale = (const float*)d_in[8];
    const float* k_scale = (const float*)d_in[9];
    float* out = (float*)d_out;

    __half *xh,*Wqh,*Wql,*Wkh,*Wkl,*Wvh,*Wvl,*Woh,*ctxh,*Vh;
    bf16 *Qh,*Ql,*Kh,*Kl;
    cudaGetSymbolAddress((void**)&xh,   g_xh);
    cudaGetSymbolAddress((void**)&Wqh,  g_Wqh);  cudaGetSymbolAddress((void**)&Wql,  g_Wql);
    cudaGetSymbolAddress((void**)&Wkh,  g_Wkh);  cudaGetSymbolAddress((void**)&Wkl,  g_Wkl);
    cudaGetSymbolAddress((void**)&Wvh,  g_Wvh);  cudaGetSymbolAddress((void**)&Wvl,  g_Wvl);
    cudaGetSymbolAddress((void**)&Woh,  g_Woh);
    cudaGetSymbolAddress((void**)&Qh,   g_Qh);   cudaGetSymbolAddress((void**)&Ql,   g_Ql);
    cudaGetSymbolAddress((void**)&Kh,   g_Kh);   cudaGetSymbolAddress((void**)&Kl,   g_Kl);
    cudaGetSymbolAddress((void**)&Vh,   g_Vh);
    cudaGetSymbolAddress((void**)&ctxh, g_ctxh);

    static bool attr_set = false;
    if (!attr_set) {
        cudaFuncSetAttribute(gemm_qkv,     cudaFuncAttributeMaxDynamicSharedMemorySize, GSMEM);
        cudaFuncSetAttribute(gemm_o,       cudaFuncAttributeMaxDynamicSharedMemorySize, GSMEM1);
        cudaFuncSetAttribute(flash_kernel, cudaFuncAttributeMaxDynamicSharedMemorySize, FLASH_SMEM);
        attr_set = true;
    }

    // 0: all operand conversions in one launch
    split_all_kernel<<<20480, 256>>>(
        (const float4*)x, (const float4*)Wq, (const float4*)Wk,
        (const float4*)Wv, (const float4*)Wo,
        xh, Wqh, Wql, Wkh, Wkl, Wvh, Wvl, Woh);

    // 1: merged QKV projection (fp16 2-mma) + fused norm/rope/split epilogue
    gemm_qkv<<<dim3(32, MROWS/128), 256, GSMEM>>>(
        xh, Wqh, Wql, Wkh, Wkl, Wvh, Wvl,
        Qh, Ql, Kh, Kl, Vh, q_scale, k_scale, cosT, sinT);

    // 2: fused flash attention (QK bf16x3, PV fp16 1-mma)
    flash_kernel<<<dim3(TT/BQ, BB*HQ), 256, FLASH_SMEM>>>(Qh, Ql, Kh, Kl, Vh, ctxh);

    // 3: output projection (fp16 1-mma, descale)
    gemm_o<<<dim3(DD/128, MROWS/128), 256, GSMEM1>>>(ctxh, Woh, out, DD);
}

// round 14
// speedup vs baseline: 4.5425x; 1.2646x over previous
#include <cuda_runtime.h>
#include <cuda_bf16.h>
#include <cuda_fp16.h>
#include <cstdint>
#include <cstddef>

// Problem constants
#define BB 2
#define TT 2048
#define DD 2048
#define HQ 16
#define HKV 8
#define HD 128
#define MROWS (BB*TT)   // 4096

typedef __nv_bfloat16 bf16;

// log2(e)/sqrt(128)
#define QSCALE 0.12752551164384637f
#define WSCALE 256.0f
#define INV256 0.00390625f

// ---------------- scratch (static device globals) ---------------------------
__device__ __half g_xh [(size_t)MROWS*DD];                      // single plane
__device__ __half g_Wqh[(size_t)HQ*HD*DD];                      // single plane
__device__ __half g_Wkh[(size_t)HKV*HD*DD];                     // single plane
__device__ __half g_Wvh[(size_t)HKV*HD*DD];                     // single plane
__device__ __half g_Woh[(size_t)DD*HQ*HD];                      // single plane
__device__ bf16 g_Qh [(size_t)BB*HQ*TT*HD],  g_Ql [(size_t)BB*HQ*TT*HD];
__device__ bf16 g_Kh [(size_t)BB*HKV*TT*HD], g_Kl [(size_t)BB*HKV*TT*HD];
__device__ __half g_Vh [(size_t)MROWS*HKV*HD];                  // single plane
__device__ __half g_ctxh[(size_t)MROWS*HQ*HD];                  // single plane

// ---------------- PTX helpers ------------------------------------------------
__device__ __forceinline__ void ldsm4(uint32_t* r, uint32_t a) {
    asm volatile("ldmatrix.sync.aligned.m8n8.x4.shared.b16 {%0,%1,%2,%3}, [%4];\n"
        : "=r"(r[0]), "=r"(r[1]), "=r"(r[2]), "=r"(r[3]) : "r"(a));
}
__device__ __forceinline__ void ldsm4t(uint32_t* r, uint32_t a) {
    asm volatile("ldmatrix.sync.aligned.m8n8.x4.trans.shared.b16 {%0,%1,%2,%3}, [%4];\n"
        : "=r"(r[0]), "=r"(r[1]), "=r"(r[2]), "=r"(r[3]) : "r"(a));
}
__device__ __forceinline__ void mma16816(float* c, const uint32_t* a, const uint32_t* b) {
    asm volatile("mma.sync.aligned.m16n8k16.row.col.f32.bf16.bf16.f32 "
        "{%0,%1,%2,%3}, {%4,%5,%6,%7}, {%8,%9}, {%0,%1,%2,%3};\n"
        : "+f"(c[0]), "+f"(c[1]), "+f"(c[2]), "+f"(c[3])
        : "r"(a[0]), "r"(a[1]), "r"(a[2]), "r"(a[3]), "r"(b[0]), "r"(b[1]));
}
__device__ __forceinline__ void mma16816h(float* c, const uint32_t* a, const uint32_t* b) {
    asm volatile("mma.sync.aligned.m16n8k16.row.col.f32.f16.f16.f32 "
        "{%0,%1,%2,%3}, {%4,%5,%6,%7}, {%8,%9}, {%0,%1,%2,%3};\n"
        : "+f"(c[0]), "+f"(c[1]), "+f"(c[2]), "+f"(c[3])
        : "r"(a[0]), "r"(a[1]), "r"(a[2]), "r"(a[3]), "r"(b[0]), "r"(b[1]));
}
__device__ __forceinline__ void cp_async16(uint32_t dst, const void* src) {
    asm volatile("cp.async.cg.shared.global [%0], [%1], 16;\n" :: "r"(dst), "l"(src));
}
__device__ __forceinline__ void cp_commit() {
    asm volatile("cp.async.commit_group;\n" ::: "memory");
}
__device__ __forceinline__ uint32_t packbf(float a, float b) {
    __nv_bfloat162 t = __floats2bfloat162_rn(a, b);
    return *(uint32_t*)&t;
}
__device__ __forceinline__ uint32_t packh(float a, float b) {
    __half2 t = __floats2half2_rn(a, b);
    return *(uint32_t*)&t;
}
__device__ __forceinline__ void split2(float a, float b, uint32_t& h, uint32_t& l) {
    bf16 ha = __float2bfloat16(a), hb = __float2bfloat16(b);
    h = ((uint32_t)__bfloat16_as_ushort(hb) << 16) | (uint32_t)__bfloat16_as_ushort(ha);
    l = packbf(a - __bfloat162float(ha), b - __bfloat162float(hb));
}

// ---------------- fused operand conversion (single launch) -------------------
// blocks [0,8192): x; [8192,12288): Wq; [12288,14336): Wk; [14336,16384): Wv;
// [16384,20480): Wo.  All single fp16 plane (weights x256).
__global__ __launch_bounds__(256) void split_all_kernel(
    const float4* __restrict__ x,  const float4* __restrict__ Wq,
    const float4* __restrict__ Wk, const float4* __restrict__ Wv,
    const float4* __restrict__ Wo,
    __half* __restrict__ xh,
    __half* __restrict__ Wqh, __half* __restrict__ Wkh,
    __half* __restrict__ Wvh, __half* __restrict__ Woh)
{
    int blk = blockIdx.x;
    if (blk < 8192) {
        int i = blk*256 + threadIdx.x;
        float4 v = x[i];
        *(uint2*)(xh + (size_t)i*4) = make_uint2(packh(v.x, v.y), packh(v.z, v.w));
        return;
    }
    blk -= 8192;
    const float4* in; __half* out;
    if (blk < 4096)      {                in = Wq; out = Wqh; }
    else if (blk < 6144) { blk -= 4096;   in = Wk; out = Wkh; }
    else if (blk < 8192) { blk -= 6144;   in = Wv; out = Wvh; }
    else                 { blk -= 8192;   in = Wo; out = Woh; }
    int i = blk*256 + threadIdx.x;
    float4 v = in[i];
    *(uint2*)(out + (size_t)i*4) =
        make_uint2(packh(v.x*WSCALE, v.y*WSCALE), packh(v.z*WSCALE, v.w*WSCALE));
}

// ---------------- GEMM core macros (fp16 1-mma, 64x32 warp tiles, 3-stage) ---
#define BKC 32
#define PAD 40
#define ARR (128*PAD)
#define STG2 (2*ARR)
#define GSMEM1 (3*STG2*2)       // 61440 bytes

#define GEMM_PROLOGUE()                                                         \
    const int tid  = threadIdx.x;                                               \
    const int lane = tid & 31, wid = tid >> 5;                                  \
    const int wm = (wid & 1) * 64;                                              \
    const int wn = (wid >> 1) * 32;                                             \
    const int m0 = tid >> 2;                                                    \
    const int c0 = (tid & 3) * 8;                                               \
    const int r_   = lane & 7, blk_ = lane >> 3;                                \
    const int a_row = ((blk_ & 1) << 3) + r_;                                   \
    const int a_col = (blk_ >> 1) << 3;                                         \
    const int b_row = ((blk_ >> 1) << 3) + r_;                                  \
    const int b_col = (blk_ & 1) << 3;                                          \
    float acc[4][4][4];                                                         \
    _Pragma("unroll") for (int i = 0; i < 4; i++)                               \
    _Pragma("unroll") for (int j = 0; j < 4; j++)                               \
    _Pragma("unroll") for (int k = 0; k < 4; k++) acc[i][j][k] = 0.f;

#define ISSUE1(it, stage) do {                                                  \
    const int k0_ = (it) * BKC;                                                 \
    uint32_t sst_ = sbase + (uint32_t)(stage) * (STG2 * 2);                     \
    _Pragma("unroll")                                                           \
    for (int hh_ = 0; hh_ < 2; hh_++) {                                         \
        int m_ = m0 + hh_ * 64;                                                 \
        cp_async16(sst_ + (uint32_t)((m_*PAD + c0) * 2),                        \
                   gA + (size_t)(row0 + m_) * K + k0_ + c0);                    \
        cp_async16(sst_ + (uint32_t)((ARR + m_*PAD + c0) * 2),                  \
                   gB0 + (size_t)(col0 + m_) * K + k0_ + c0);                   \
    }                                                                           \
} while (0)

#define GEMM_MAINLOOP1()                                                        \
    ISSUE1(0, 0);                                                               \
    cp_commit();                                                                \
    ISSUE1(1, 1);                                                               \
    cp_commit();                                                                \
    int stg = 0;                                                                \
    for (int it = 0; it < niter; it++) {                                        \
        if (it + 1 < niter) {                                                   \
            asm volatile("cp.async.wait_group 1;\n" ::: "memory");              \
        } else {                                                                \
            asm volatile("cp.async.wait_group 0;\n" ::: "memory");              \
        }                                                                       \
        __syncthreads();                                                        \
        if (it + 2 < niter) {                                                   \
            int s2 = stg + 2; if (s2 >= 3) s2 -= 3;                             \
            ISSUE1(it + 2, s2);                                                 \
            cp_commit();                                                        \
        }                                                                       \
        const uint32_t sst = sbase + (uint32_t)stg * (STG2 * 2);                \
        _Pragma("unroll")                                                       \
        for (int ks = 0; ks < 2; ks++) {                                        \
            const int kofs = ks * 16;                                           \
            uint32_t a_[4][4], bh_[2][4];                                       \
            _Pragma("unroll")                                                   \
            for (int mt = 0; mt < 4; mt++)                                      \
                ldsm4(a_[mt], sst + (uint32_t)(((wm + mt*16 + a_row)*PAD + kofs + a_col) * 2)); \
            _Pragma("unroll")                                                   \
            for (int p = 0; p < 2; p++)                                         \
                ldsm4(bh_[p], sst + (uint32_t)((ARR + (wn + p*16 + b_row)*PAD + kofs + b_col) * 2)); \
            _Pragma("unroll")                                                   \
            for (int mt = 0; mt < 4; mt++)                                      \
            _Pragma("unroll")                                                   \
                for (int p = 0; p < 2; p++) {                                   \
                    mma16816h(acc[mt][2*p],   a_[mt], &bh_[p][0]);              \
                    mma16816h(acc[mt][2*p+1], a_[mt], &bh_[p][2]);              \
                }                                                               \
        }                                                                       \
        if (++stg == 3) stg = 0;                                                \
    }

// ---------------- merged QKV GEMM with fused norm/rope/split epilogue --------
__global__ __launch_bounds__(256, 2) void gemm_qkv(
    const __half* __restrict__ gA,
    const __half* __restrict__ Wqh_, const __half* __restrict__ Wkh_,
    const __half* __restrict__ Wvh_,
    bf16* __restrict__ Qh, bf16* __restrict__ Ql,
    bf16* __restrict__ Kh, bf16* __restrict__ Kl,
    __half* __restrict__ Vh,
    const float* __restrict__ q_scale, const float* __restrict__ k_scale,
    const float* __restrict__ cosT, const float* __restrict__ sinT)
{
    extern __shared__ __half sm[];
    const uint32_t sbase = (uint32_t)__cvta_generic_to_shared(sm);
    const int bx = blockIdx.x;
    const int row0 = blockIdx.y * 128;
    const int K = DD;
    const int niter = K / BKC;

    int mode, hloc;
    const __half* gB0;
    if (bx < 16)      { mode = 0; hloc = bx;      gB0 = Wqh_; }
    else if (bx < 24) { mode = 1; hloc = bx - 16; gB0 = Wkh_; }
    else              { mode = 2; hloc = bx - 24; gB0 = Wvh_; }
    const int col0 = hloc * 128;

    GEMM_PROLOGUE();
    GEMM_MAINLOOP1();

    // ---- stage fp32 tile into smem (reuse pipeline smem) ----
    __syncthreads();
    float* sf = (float*)sm;                 // 128 x 132 floats = 67584 B > 61440!
    // NOTE: GSMEM1 is 61440 < 67584; bump dynamic smem to the max of both.
    const int gr = lane >> 2, gc = (lane & 3) * 2;
#pragma unroll
    for (int mt = 0; mt < 4; mt++)
#pragma unroll
        for (int nt = 0; nt < 4; nt++) {
            int row = wm + mt*16 + gr;
            int col = wn + nt*8 + gc;
            *(float2*)&sf[(size_t)row*132 + col]     = make_float2(acc[mt][nt][0], acc[mt][nt][1]);
            *(float2*)&sf[(size_t)(row+8)*132 + col] = make_float2(acc[mt][nt][2], acc[mt][nt][3]);
        }
    __syncthreads();

    const float* scv = (mode == 0) ? q_scale : k_scale;
    const float smul = (mode == 0) ? QSCALE : 1.0f;
    const int   Hn   = (mode == 0) ? HQ : HKV;
    bf16* outh = (mode == 0) ? Qh : Kh;
    bf16* outl = (mode == 0) ? Ql : Kl;

    float4 sc4 = make_float4(1.f,1.f,1.f,1.f);
    if (mode < 2) sc4 = *(const float4*)&scv[lane*4];

    for (int rr = 0; rr < 16; rr++) {
        const int row  = wid*16 + rr;
        const int gtok = row0 + row;
        const int b = gtok >> 11, t = gtok & (TT-1);
        float4 v = *(float4*)&sf[(size_t)row*132 + lane*4];
        v.x *= INV256; v.y *= INV256; v.z *= INV256; v.w *= INV256;   // weight descale
        if (mode < 2) {
            float ss = v.x*v.x + v.y*v.y + v.z*v.z + v.w*v.w;
#pragma unroll
            for (int ofs = 16; ofs > 0; ofs >>= 1)
                ss += __shfl_xor_sync(0xffffffffu, ss, ofs);
            float inv = rsqrtf(ss*(1.0f/HD) + 1e-6f);
            v.x *= inv*sc4.x; v.y *= inv*sc4.y; v.z *= inv*sc4.z; v.w *= inv*sc4.w;
            float px = __shfl_xor_sync(0xffffffffu, v.x, 16);
            float py = __shfl_xor_sync(0xffffffffu, v.y, 16);
            float pz = __shfl_xor_sync(0xffffffffu, v.z, 16);
            float pw = __shfl_xor_sync(0xffffffffu, v.w, 16);
            float s = (lane < 16) ? -1.f : 1.f;
            float4 cs = *(const float4*)&cosT[(size_t)t*HD + lane*4];
            float4 sn = *(const float4*)&sinT[(size_t)t*HD + lane*4];
            float4 o;
            o.x = (v.x*cs.x + s*px*sn.x) * smul;
            o.y = (v.y*cs.y + s*py*sn.y) * smul;
            o.z = (v.z*cs.z + s*pz*sn.z) * smul;
            o.w = (v.w*cs.w + s*pw*sn.w) * smul;
            uint32_t H0, L0, H1, L1;
            split2(o.x, o.y, H0, L0);
            split2(o.z, o.w, H1, L1);
            size_t off = (((size_t)(b*Hn + hloc))*TT + t)*HD + lane*4;
            *(uint2*)&outh[off] = make_uint2(H0, H1);
            *(uint2*)&outl[off] = make_uint2(L0, L1);
        } else {
            size_t off = (size_t)gtok*(HKV*HD) + hloc*HD + lane*4;
            *(uint2*)&Vh[off] = make_uint2(packh(v.x, v.y), packh(v.z, v.w));
        }
    }
}

// ---------------- O-projection GEMM (1-plane weights, fp32 epilogue) ---------
__global__ __launch_bounds__(256, 2) void gemm_o(
    const __half* __restrict__ gA,
    const __half* __restrict__ gB0,
    float* __restrict__ C, int N)
{
    extern __shared__ __half sm[];
    const uint32_t sbase = (uint32_t)__cvta_generic_to_shared(sm);
    const int row0 = blockIdx.y * 128, col0 = blockIdx.x * 128;
    const int K = DD;
    const int niter = K / BKC;

    GEMM_PROLOGUE();
    GEMM_MAINLOOP1();

    const int gr = lane >> 2, gc = (lane & 3) * 2;
#pragma unroll
    for (int mt = 0; mt < 4; mt++)
#pragma unroll
        for (int nt = 0; nt < 4; nt++) {
            int row = row0 + wm + mt*16 + gr;
            int col = col0 + wn + nt*8 + gc;
            *(float2*)&C[(size_t)row*N + col]     = make_float2(acc[mt][nt][0]*INV256, acc[mt][nt][1]*INV256);
            *(float2*)&C[(size_t)(row+8)*N + col] = make_float2(acc[mt][nt][2]*INV256, acc[mt][nt][3]*INV256);
        }
}

// ---------------- fused flash attention -------------------------------------
// QK^T: bf16x3 (accuracy-critical). PV: fp16 1-mma (P and V single planes).
// 3-stage KV pipeline, single barrier per tile.
#define BQ 128
#define BK 64
#define FP 136
#define QELE (BQ*FP)
#define KELE (BK*FP)
#define QAREA (2*QELE)
#define STGKV (3*KELE)
#define FLASH_SMEM ((QAREA + 3*STGKV) * 2)   // 226304 bytes

__global__ __launch_bounds__(256) void flash_kernel(
    const bf16* __restrict__ Qh, const bf16* __restrict__ Ql,
    const bf16* __restrict__ Kh, const bf16* __restrict__ Kl,
    const __half* __restrict__ Vh,
    __half* __restrict__ ctxh)
{
    extern __shared__ bf16 smf[];
    const int tid = threadIdx.x, lane = tid & 31, wid = tid >> 5;
    const int qb = gridDim.x - 1 - blockIdx.x;
    const int bh = blockIdx.y;
    const int b = bh >> 4, h = bh & 15, kv = h >> 1;
    const int q0 = qb * BQ;
    const uint32_t sbase = (uint32_t)__cvta_generic_to_shared(smf);

    const bf16* Qhg = Qh + ((size_t)(b*HQ  + h )*TT + q0)*HD;
    const bf16* Qlg = Ql + ((size_t)(b*HQ  + h )*TT + q0)*HD;
    const bf16* Khg = Kh + ((size_t)(b*HKV + kv)*TT)*HD;
    const bf16* Klg = Kl + ((size_t)(b*HKV + kv)*TT)*HD;
    const __half* Vhg = Vh + (size_t)b*TT*(HKV*HD) + kv*HD;

#pragma unroll
    for (int i = 0; i < 8; i++) {
        int c = tid + i*256;
        int row = c >> 4, col = (c & 15) * 8;
        cp_async16(sbase + (uint32_t)((row*FP + col) * 2),        Qhg + (size_t)row*HD + col);
        cp_async16(sbase + (uint32_t)((QELE + row*FP + col) * 2), Qlg + (size_t)row*HD + col);
    }

#define ISSUEKV(kt, stage) do {                                                     \
    const int k0_ = (kt) * BK;                                                      \
    const uint32_t kb_ = sbase + (uint32_t)((QAREA + (stage)*STGKV) * 2);           \
    _Pragma("unroll")                                                               \
    for (int i_ = 0; i_ < 4; i_++) {                                                \
        int c_ = tid + i_*256;                                                      \
        int row_ = c_ >> 4, col_ = (c_ & 15) * 8;                                   \
        uint32_t so_ = (uint32_t)((row_*FP + col_) * 2);                            \
        cp_async16(kb_ + so_,            Khg + (size_t)(k0_+row_)*HD + col_);       \
        cp_async16(kb_ + KELE*2 + so_,   Klg + (size_t)(k0_+row_)*HD + col_);       \
        cp_async16(kb_ + 2*KELE*2 + so_, Vhg + (size_t)(k0_+row_)*(HKV*HD) + col_); \
    }                                                                               \
} while (0)

    const int nkt = 2*qb + 2;
    ISSUEKV(0, 0);
    cp_commit();
    ISSUEKV(1, 1);
    cp_commit();

    const int r   = lane & 7, blkid = lane >> 3;
    const int a_row = ((blkid & 1) << 3) + r;
    const int a_col = (blkid >> 1) << 3;
    const int b_row = ((blkid >> 1) << 3) + r;
    const int b_col = (blkid & 1) << 3;
    const int gr = lane >> 2;

    float oacc[16][4];
#pragma unroll
    for (int i = 0; i < 16; i++)
#pragma unroll
        for (int j = 0; j < 4; j++) oacc[i][j] = 0.f;
    float m0 = -1e30f, m1 = -1e30f, l0 = 0.f, l1 = 0.f;

    const int row0g = q0 + wid*16 + gr;
    const int row1g = row0g + 8;
    const int rowmin = q0 + wid*16;

    int stg = 0;
    for (int kt = 0; kt < nkt; kt++) {
        if (kt + 1 < nkt) {
            asm volatile("cp.async.wait_group 1;\n" ::: "memory");
        } else {
            asm volatile("cp.async.wait_group 0;\n" ::: "memory");
        }
        __syncthreads();
        if (kt + 2 < nkt) {
            int s2 = stg + 2; if (s2 >= 3) s2 -= 3;
            ISSUEKV(kt + 2, s2);
            cp_commit();
        }

        const int k0 = kt * BK;
        const uint32_t kb_s = sbase + (uint32_t)((QAREA + stg*STGKV) * 2);

        float sacc[8][4];
#pragma unroll
        for (int i = 0; i < 8; i++)
#pragma unroll
            for (int j = 0; j < 4; j++) sacc[i][j] = 0.f;

#pragma unroll
        for (int ks = 0; ks < 8; ks++) {
            uint32_t qa = sbase + (uint32_t)(((wid*16 + a_row)*FP + ks*16 + a_col) * 2);
            uint32_t qh[4], ql[4];
            ldsm4(qh, qa);
            ldsm4(ql, qa + QELE*2);
#pragma unroll
            for (int np = 0; np < 4; np++) {
                uint32_t ka = kb_s + (uint32_t)(((np*16 + b_row)*FP + ks*16 + b_col) * 2);
                uint32_t kh[4], kl[4];
                ldsm4(kh, ka);
                ldsm4(kl, ka + KELE*2);
                mma16816(sacc[2*np],   qh, &kh[0]);
                mma16816(sacc[2*np+1], qh, &kh[2]);
                mma16816(sacc[2*np],   qh, &kl[0]);
                mma16816(sacc[2*np+1], qh, &kl[2]);
                mma16816(sacc[2*np],   ql, &kh[0]);
                mma16816(sacc[2*np+1], ql, &kh[2]);
            }
        }

        // ---- causal mask (only near diagonal) + online softmax ----
        float mx0 = -1e30f, mx1 = -1e30f;
        if (k0 + 63 > rowmin) {
#pragma unroll
            for (int nt = 0; nt < 8; nt++) {
                int cg = k0 + nt*8 + (lane & 3)*2;
                if (cg     > row0g) sacc[nt][0] = -1e30f;
                if (cg + 1 > row0g) sacc[nt][1] = -1e30f;
                if (cg     > row1g) sacc[nt][2] = -1e30f;
                if (cg + 1 > row1g) sacc[nt][3] = -1e30f;
                mx0 = fmaxf(mx0, fmaxf(sacc[nt][0], sacc[nt][1]));
                mx1 = fmaxf(mx1, fmaxf(sacc[nt][2], sacc[nt][3]));
            }
        } else {
#pragma unroll
            for (int nt = 0; nt < 8; nt++) {
                mx0 = fmaxf(mx0, fmaxf(sacc[nt][0], sacc[nt][1]));
                mx1 = fmaxf(mx1, fmaxf(sacc[nt][2], sacc[nt][3]));
            }
        }
        mx0 = fmaxf(mx0, __shfl_xor_sync(0xffffffffu, mx0, 1));
        mx0 = fmaxf(mx0, __shfl_xor_sync(0xffffffffu, mx0, 2));
        mx1 = fmaxf(mx1, __shfl_xor_sync(0xffffffffu, mx1, 1));
        mx1 = fmaxf(mx1, __shfl_xor_sync(0xffffffffu, mx1, 2));

        float mn0 = fmaxf(m0, mx0), mn1 = fmaxf(m1, mx1);
        float sc0 = exp2f(m0 - mn0), sc1 = exp2f(m1 - mn1);
        m0 = mn0; m1 = mn1;

        float s0 = 0.f, s1 = 0.f;
#pragma unroll
        for (int nt = 0; nt < 8; nt++) {
            sacc[nt][0] = exp2f(sacc[nt][0] - m0);
            sacc[nt][1] = exp2f(sacc[nt][1] - m0);
            sacc[nt][2] = exp2f(sacc[nt][2] - m1);
            sacc[nt][3] = exp2f(sacc[nt][3] - m1);
            s0 += sacc[nt][0] + sacc[nt][1];
            s1 += sacc[nt][2] + sacc[nt][3];
        }
        s0 += __shfl_xor_sync(0xffffffffu, s0, 1);
        s0 += __shfl_xor_sync(0xffffffffu, s0, 2);
        s1 += __shfl_xor_sync(0xffffffffu, s1, 1);
        s1 += __shfl_xor_sync(0xffffffffu, s1, 2);
        l0 = l0*sc0 + s0;
        l1 = l1*sc1 + s1;

#pragma unroll
        for (int i = 0; i < 16; i++) {
            oacc[i][0] *= sc0; oacc[i][1] *= sc0;
            oacc[i][2] *= sc1; oacc[i][3] *= sc1;
        }

        // ---- O += P V (fp16 1-mma: P and V single planes) ----
        const int vrow = (lane & 7) + ((lane >> 3) & 1)*8;
        const int vcolb = ((lane >> 4) << 3);
#pragma unroll
        for (int kp = 0; kp < 4; kp++) {
            uint32_t ph[4];
#pragma unroll
            for (int half = 0; half < 2; half++) {
                ph[2*half]   = packh(sacc[2*kp+half][0], sacc[2*kp+half][1]);
                ph[2*half+1] = packh(sacc[2*kp+half][2], sacc[2*kp+half][3]);
            }
#pragma unroll
            for (int np = 0; np < 8; np++) {
                uint32_t va = kb_s + (uint32_t)((2*KELE + (kp*16 + vrow)*FP + np*16 + vcolb) * 2);
                uint32_t vh[4];
                ldsm4t(vh, va);
                mma16816h(oacc[2*np],   ph, &vh[0]);
                mma16816h(oacc[2*np+1], ph, &vh[2]);
            }
        }
        if (++stg == 3) stg = 0;
    }
#undef ISSUEKV

    // ---- epilogue: O /= l, write ctx fp16 single plane ----
    const float il0 = 1.f / l0, il1 = 1.f / l1;
    const size_t tok0 = (size_t)(b*TT + q0 + wid*16 + gr);
#pragma unroll
    for (int nt = 0; nt < 16; nt++) {
        int col = h*HD + nt*8 + (lane & 3)*2;
        *(uint32_t*)&ctxh[tok0*(HQ*HD) + col]     = packh(oacc[nt][0]*il0, oacc[nt][1]*il0);
        *(uint32_t*)&ctxh[(tok0+8)*(HQ*HD) + col] = packh(oacc[nt][2]*il1, oacc[nt][3]*il1);
    }
}

// ---------------- launch ------------------------------------------------------
extern "C" void kernel_launch(void* const* d_in, const int* in_sizes, int n_in,
                              void* d_out, int out_size)
{
    const float* x       = (const float*)d_in[0];
    const float* cosT    = (const float*)d_in[2];
    const float* sinT    = (const float*)d_in[3];
    const float* Wq      = (const float*)d_in[4];
    const float* Wk      = (const float*)d_in[5];
    const float* Wv      = (const float*)d_in[6];
    const float* Wo      = (const float*)d_in[7];
    const float* q_scale = (const float*)d_in[8];
    const float* k_scale = (const float*)d_in[9];
    float* out = (float*)d_out;

    __half *xh,*Wqh,*Wkh,*Wvh,*Woh,*ctxh,*Vh;
    bf16 *Qh,*Ql,*Kh,*Kl;
    cudaGetSymbolAddress((void**)&xh,   g_xh);
    cudaGetSymbolAddress((void**)&Wqh,  g_Wqh);
    cudaGetSymbolAddress((void**)&Wkh,  g_Wkh);
    cudaGetSymbolAddress((void**)&Wvh,  g_Wvh);
    cudaGetSymbolAddress((void**)&Woh,  g_Woh);
    cudaGetSymbolAddress((void**)&Qh,   g_Qh);   cudaGetSymbolAddress((void**)&Ql,   g_Ql);
    cudaGetSymbolAddress((void**)&Kh,   g_Kh);   cudaGetSymbolAddress((void**)&Kl,   g_Kl);
    cudaGetSymbolAddress((void**)&Vh,   g_Vh);
    cudaGetSymbolAddress((void**)&ctxh, g_ctxh);

    // gemm_qkv needs max(3-stage pipeline = 61440, fp32 epilogue staging = 67584)
    const int QKV_SMEM = 67584;

    static bool attr_set = false;
    if (!attr_set) {
        cudaFuncSetAttribute(gemm_qkv,     cudaFuncAttributeMaxDynamicSharedMemorySize, QKV_SMEM);
        cudaFuncSetAttribute(gemm_o,       cudaFuncAttributeMaxDynamicSharedMemorySize, GSMEM1);
        cudaFuncSetAttribute(flash_kernel, cudaFuncAttributeMaxDynamicSharedMemorySize, FLASH_SMEM);
        attr_set = true;
    }

    // 0: all operand conversions in one launch
    split_all_kernel<<<20480, 256>>>(
        (const float4*)x, (const float4*)Wq, (const float4*)Wk,
        (const float4*)Wv, (const float4*)Wo,
        xh, Wqh, Wkh, Wvh, Woh);

    // 1: merged QKV projection (fp16 1-mma) + fused norm/rope/split epilogue
    gemm_qkv<<<dim3(32, MROWS/128), 256, QKV_SMEM>>>(
        xh, Wqh, Wkh, Wvh,
        Qh, Ql, Kh, Kl, Vh, q_scale, k_scale, cosT, sinT);

    // 2: fused flash attention (QK bf16x3, PV fp16 1-mma)
    flash_kernel<<<dim3(TT/BQ, BB*HQ), 256, FLASH_SMEM>>>(Qh, Ql, Kh, Kl, Vh, ctxh);

    // 3: output projection (fp16 1-mma, descale)
    gemm_o<<<dim3(DD/128, MROWS/128), 256, GSMEM1>>>(ctxh, Woh, out, DD);
}

// round 15
// speedup vs baseline: 4.8638x; 1.0707x over previous
#include <cuda_runtime.h>
#include <cuda_bf16.h>
#include <cuda_fp16.h>
#include <cstdint>
#include <cstddef>

// Problem constants
#define BB 2
#define TT 2048
#define DD 2048
#define HQ 16
#define HKV 8
#define HD 128
#define MROWS (BB*TT)   // 4096

typedef __nv_bfloat16 bf16;

// log2(e)/sqrt(128)
#define QSCALE 0.12752551164384637f
#define WSCALE 256.0f
#define INV256 0.00390625f

// ---------------- scratch (static device globals) ---------------------------
__device__ __half g_xh [(size_t)MROWS*DD];                      // single plane
__device__ __half g_Wqh[(size_t)HQ*HD*DD];                      // single plane
__device__ __half g_Wkh[(size_t)HKV*HD*DD];                     // single plane
__device__ __half g_Wvh[(size_t)HKV*HD*DD];                     // single plane
__device__ __half g_Woh[(size_t)DD*HQ*HD];                      // single plane
__device__ bf16 g_Qh [(size_t)BB*HQ*TT*HD],  g_Ql [(size_t)BB*HQ*TT*HD];
__device__ bf16 g_Kh [(size_t)BB*HKV*TT*HD], g_Kl [(size_t)BB*HKV*TT*HD];
__device__ __half g_Vh [(size_t)MROWS*HKV*HD];                  // single plane
__device__ __half g_ctxh[(size_t)MROWS*HQ*HD];                  // single plane

// ---------------- PTX helpers ------------------------------------------------
__device__ __forceinline__ void ldsm4(uint32_t* r, uint32_t a) {
    asm volatile("ldmatrix.sync.aligned.m8n8.x4.shared.b16 {%0,%1,%2,%3}, [%4];\n"
        : "=r"(r[0]), "=r"(r[1]), "=r"(r[2]), "=r"(r[3]) : "r"(a));
}
__device__ __forceinline__ void ldsm4t(uint32_t* r, uint32_t a) {
    asm volatile("ldmatrix.sync.aligned.m8n8.x4.trans.shared.b16 {%0,%1,%2,%3}, [%4];\n"
        : "=r"(r[0]), "=r"(r[1]), "=r"(r[2]), "=r"(r[3]) : "r"(a));
}
__device__ __forceinline__ void mma16816(float* c, const uint32_t* a, const uint32_t* b) {
    asm volatile("mma.sync.aligned.m16n8k16.row.col.f32.bf16.bf16.f32 "
        "{%0,%1,%2,%3}, {%4,%5,%6,%7}, {%8,%9}, {%0,%1,%2,%3};\n"
        : "+f"(c[0]), "+f"(c[1]), "+f"(c[2]), "+f"(c[3])
        : "r"(a[0]), "r"(a[1]), "r"(a[2]), "r"(a[3]), "r"(b[0]), "r"(b[1]));
}
__device__ __forceinline__ void mma16816h(float* c, const uint32_t* a, const uint32_t* b) {
    asm volatile("mma.sync.aligned.m16n8k16.row.col.f32.f16.f16.f32 "
        "{%0,%1,%2,%3}, {%4,%5,%6,%7}, {%8,%9}, {%0,%1,%2,%3};\n"
        : "+f"(c[0]), "+f"(c[1]), "+f"(c[2]), "+f"(c[3])
        : "r"(a[0]), "r"(a[1]), "r"(a[2]), "r"(a[3]), "r"(b[0]), "r"(b[1]));
}
__device__ __forceinline__ void cp_async16(uint32_t dst, const void* src) {
    asm volatile("cp.async.cg.shared.global [%0], [%1], 16;\n" :: "r"(dst), "l"(src));
}
__device__ __forceinline__ void cp_commit() {
    asm volatile("cp.async.commit_group;\n" ::: "memory");
}
__device__ __forceinline__ uint32_t packbf(float a, float b) {
    __nv_bfloat162 t = __floats2bfloat162_rn(a, b);
    return *(uint32_t*)&t;
}
__device__ __forceinline__ uint32_t packh(float a, float b) {
    __half2 t = __floats2half2_rn(a, b);
    return *(uint32_t*)&t;
}
__device__ __forceinline__ void split2(float a, float b, uint32_t& h, uint32_t& l) {
    bf16 ha = __float2bfloat16(a), hb = __float2bfloat16(b);
    h = ((uint32_t)__bfloat16_as_ushort(hb) << 16) | (uint32_t)__bfloat16_as_ushort(ha);
    l = packbf(a - __bfloat162float(ha), b - __bfloat162float(hb));
}

// ---------------- fused operand conversion (single launch) -------------------
__global__ __launch_bounds__(256) void split_all_kernel(
    const float4* __restrict__ x,  const float4* __restrict__ Wq,
    const float4* __restrict__ Wk, const float4* __restrict__ Wv,
    const float4* __restrict__ Wo,
    __half* __restrict__ xh,
    __half* __restrict__ Wqh, __half* __restrict__ Wkh,
    __half* __restrict__ Wvh, __half* __restrict__ Woh)
{
    int blk = blockIdx.x;
    if (blk < 8192) {
        int i = blk*256 + threadIdx.x;
        float4 v = x[i];
        *(uint2*)(xh + (size_t)i*4) = make_uint2(packh(v.x, v.y), packh(v.z, v.w));
        return;
    }
    blk -= 8192;
    const float4* in; __half* out;
    if (blk < 4096)      {                in = Wq; out = Wqh; }
    else if (blk < 6144) { blk -= 4096;   in = Wk; out = Wkh; }
    else if (blk < 8192) { blk -= 6144;   in = Wv; out = Wvh; }
    else                 { blk -= 8192;   in = Wo; out = Woh; }
    int i = blk*256 + threadIdx.x;
    float4 v = in[i];
    *(uint2*)(out + (size_t)i*4) =
        make_uint2(packh(v.x*WSCALE, v.y*WSCALE), packh(v.z*WSCALE, v.w*WSCALE));
}

// ---------------- GEMM core macros (fp16 1-mma, BK=64, 3-stage) --------------
#define BKC 64
#define PAD 72
#define ARR (128*PAD)           // 9216 fp16
#define STG2 (2*ARR)            // 18432 fp16 = 36864 B / stage
#define GSMEM1 (3*STG2*2)       // 110592 bytes

#define GEMM_PROLOGUE()                                                         \
    const int tid  = threadIdx.x;                                               \
    const int lane = tid & 31, wid = tid >> 5;                                  \
    const int wm = (wid & 1) * 64;                                              \
    const int wn = (wid >> 1) * 32;                                             \
    const int mrow = tid >> 3;                                                  \
    const int ccol = (tid & 7) * 8;                                             \
    const int r_   = lane & 7, blk_ = lane >> 3;                                \
    const int a_row = ((blk_ & 1) << 3) + r_;                                   \
    const int a_col = (blk_ >> 1) << 3;                                         \
    const int b_row = ((blk_ >> 1) << 3) + r_;                                  \
    const int b_col = (blk_ & 1) << 3;                                          \
    float acc[4][4][4];                                                         \
    _Pragma("unroll") for (int i = 0; i < 4; i++)                               \
    _Pragma("unroll") for (int j = 0; j < 4; j++)                               \
    _Pragma("unroll") for (int k = 0; k < 4; k++) acc[i][j][k] = 0.f;

#define ISSUE1(it, stage) do {                                                  \
    const int k0_ = (it) * BKC;                                                 \
    uint32_t sst_ = sbase + (uint32_t)(stage) * (STG2 * 2);                     \
    _Pragma("unroll")                                                           \
    for (int rg_ = 0; rg_ < 4; rg_++) {                                         \
        int m_ = mrow + rg_ * 32;                                               \
        cp_async16(sst_ + (uint32_t)((m_*PAD + ccol) * 2),                      \
                   gA + (size_t)(row0 + m_) * K + k0_ + ccol);                  \
        cp_async16(sst_ + (uint32_t)((ARR + m_*PAD + ccol) * 2),                \
                   gB0 + (size_t)(col0 + m_) * K + k0_ + ccol);                 \
    }                                                                           \
} while (0)

#define GEMM_MAINLOOP1()                                                        \
    ISSUE1(0, 0);                                                               \
    cp_commit();                                                                \
    ISSUE1(1, 1);                                                               \
    cp_commit();                                                                \
    int stg = 0;                                                                \
    for (int it = 0; it < niter; it++) {                                        \
        if (it + 1 < niter) {                                                   \
            asm volatile("cp.async.wait_group 1;\n" ::: "memory");              \
        } else {                                                                \
            asm volatile("cp.async.wait_group 0;\n" ::: "memory");              \
        }                                                                       \
        __syncthreads();                                                        \
        if (it + 2 < niter) {                                                   \
            int s2 = stg + 2; if (s2 >= 3) s2 -= 3;                             \
            ISSUE1(it + 2, s2);                                                 \
            cp_commit();                                                        \
        }                                                                       \
        const uint32_t sst = sbase + (uint32_t)stg * (STG2 * 2);                \
        _Pragma("unroll")                                                       \
        for (int ks = 0; ks < 4; ks++) {                                        \
            const int kofs = ks * 16;                                           \
            uint32_t a_[4][4], bh_[2][4];                                       \
            _Pragma("unroll")                                                   \
            for (int mt = 0; mt < 4; mt++)                                      \
                ldsm4(a_[mt], sst + (uint32_t)(((wm + mt*16 + a_row)*PAD + kofs + a_col) * 2)); \
            _Pragma("unroll")                                                   \
            for (int p = 0; p < 2; p++)                                         \
                ldsm4(bh_[p], sst + (uint32_t)((ARR + (wn + p*16 + b_row)*PAD + kofs + b_col) * 2)); \
            _Pragma("unroll")                                                   \
            for (int mt = 0; mt < 4; mt++)                                      \
            _Pragma("unroll")                                                   \
                for (int p = 0; p < 2; p++) {                                   \
                    mma16816h(acc[mt][2*p],   a_[mt], &bh_[p][0]);              \
                    mma16816h(acc[mt][2*p+1], a_[mt], &bh_[p][2]);              \
                }                                                               \
        }                                                                       \
        if (++stg == 3) stg = 0;                                                \
    }

// ---------------- merged QKV GEMM with fused norm/rope/split epilogue --------
__global__ __launch_bounds__(256, 2) void gemm_qkv(
    const __half* __restrict__ gA,
    const __half* __restrict__ Wqh_, const __half* __restrict__ Wkh_,
    const __half* __restrict__ Wvh_,
    bf16* __restrict__ Qh, bf16* __restrict__ Ql,
    bf16* __restrict__ Kh, bf16* __restrict__ Kl,
    __half* __restrict__ Vh,
    const float* __restrict__ q_scale, const float* __restrict__ k_scale,
    const float* __restrict__ cosT, const float* __restrict__ sinT)
{
    extern __shared__ __half sm[];
    const uint32_t sbase = (uint32_t)__cvta_generic_to_shared(sm);
    const int bx = blockIdx.x;
    const int row0 = blockIdx.y * 128;
    const int K = DD;
    const int niter = K / BKC;

    int mode, hloc;
    const __half* gB0;
    if (bx < 16)      { mode = 0; hloc = bx;      gB0 = Wqh_; }
    else if (bx < 24) { mode = 1; hloc = bx - 16; gB0 = Wkh_; }
    else              { mode = 2; hloc = bx - 24; gB0 = Wvh_; }
    const int col0 = hloc * 128;

    GEMM_PROLOGUE();
    GEMM_MAINLOOP1();

    // ---- stage fp32 tile into smem (reuse pipeline smem) ----
    __syncthreads();
    float* sf = (float*)sm;                 // 128 x 132 floats = 67584 B <= 110592
    const int gr = lane >> 2, gc = (lane & 3) * 2;
#pragma unroll
    for (int mt = 0; mt < 4; mt++)
#pragma unroll
        for (int nt = 0; nt < 4; nt++) {
            int row = wm + mt*16 + gr;
            int col = wn + nt*8 + gc;
            *(float2*)&sf[(size_t)row*132 + col]     = make_float2(acc[mt][nt][0], acc[mt][nt][1]);
            *(float2*)&sf[(size_t)(row+8)*132 + col] = make_float2(acc[mt][nt][2], acc[mt][nt][3]);
        }
    __syncthreads();

    const float* scv = (mode == 0) ? q_scale : k_scale;
    const float smul = (mode == 0) ? QSCALE : 1.0f;
    const int   Hn   = (mode == 0) ? HQ : HKV;
    bf16* outh = (mode == 0) ? Qh : Kh;
    bf16* outl = (mode == 0) ? Ql : Kl;

    float4 sc4 = make_float4(1.f,1.f,1.f,1.f);
    if (mode < 2) sc4 = *(const float4*)&scv[lane*4];

    for (int rr = 0; rr < 16; rr++) {
        const int row  = wid*16 + rr;
        const int gtok = row0 + row;
        const int b = gtok >> 11, t = gtok & (TT-1);
        float4 v = *(float4*)&sf[(size_t)row*132 + lane*4];
        v.x *= INV256; v.y *= INV256; v.z *= INV256; v.w *= INV256;   // weight descale
        if (mode < 2) {
            float ss = v.x*v.x + v.y*v.y + v.z*v.z + v.w*v.w;
#pragma unroll
            for (int ofs = 16; ofs > 0; ofs >>= 1)
                ss += __shfl_xor_sync(0xffffffffu, ss, ofs);
            float inv = rsqrtf(ss*(1.0f/HD) + 1e-6f);
            v.x *= inv*sc4.x; v.y *= inv*sc4.y; v.z *= inv*sc4.z; v.w *= inv*sc4.w;
            float px = __shfl_xor_sync(0xffffffffu, v.x, 16);
            float py = __shfl_xor_sync(0xffffffffu, v.y, 16);
            float pz = __shfl_xor_sync(0xffffffffu, v.z, 16);
            float pw = __shfl_xor_sync(0xffffffffu, v.w, 16);
            float s = (lane < 16) ? -1.f : 1.f;
            float4 cs = *(const float4*)&cosT[(size_t)t*HD + lane*4];
            float4 sn = *(const float4*)&sinT[(size_t)t*HD + lane*4];
            float4 o;
            o.x = (v.x*cs.x + s*px*sn.x) * smul;
            o.y = (v.y*cs.y + s*py*sn.y) * smul;
            o.z = (v.z*cs.z + s*pz*sn.z) * smul;
            o.w = (v.w*cs.w + s*pw*sn.w) * smul;
            uint32_t H0, L0, H1, L1;
            split2(o.x, o.y, H0, L0);
            split2(o.z, o.w, H1, L1);
            size_t off = (((size_t)(b*Hn + hloc))*TT + t)*HD + lane*4;
            *(uint2*)&outh[off] = make_uint2(H0, H1);
            *(uint2*)&outl[off] = make_uint2(L0, L1);
        } else {
            size_t off = (size_t)gtok*(HKV*HD) + hloc*HD + lane*4;
            *(uint2*)&Vh[off] = make_uint2(packh(v.x, v.y), packh(v.z, v.w));
        }
    }
}

// ---------------- O-projection GEMM (1-plane weights, fp32 epilogue) ---------
__global__ __launch_bounds__(256, 2) void gemm_o(
    const __half* __restrict__ gA,
    const __half* __restrict__ gB0,
    float* __restrict__ C, int N)
{
    extern __shared__ __half sm[];
    const uint32_t sbase = (uint32_t)__cvta_generic_to_shared(sm);
    const int row0 = blockIdx.y * 128, col0 = blockIdx.x * 128;
    const int K = DD;
    const int niter = K / BKC;

    GEMM_PROLOGUE();
    GEMM_MAINLOOP1();

    const int gr = lane >> 2, gc = (lane & 3) * 2;
#pragma unroll
    for (int mt = 0; mt < 4; mt++)
#pragma unroll
        for (int nt = 0; nt < 4; nt++) {
            int row = row0 + wm + mt*16 + gr;
            int col = col0 + wn + nt*8 + gc;
            *(float2*)&C[(size_t)row*N + col]     = make_float2(acc[mt][nt][0]*INV256, acc[mt][nt][1]*INV256);
            *(float2*)&C[(size_t)(row+8)*N + col] = make_float2(acc[mt][nt][2]*INV256, acc[mt][nt][3]*INV256);
        }
}

// ---------------- fused flash attention -------------------------------------
// QK^T: bf16x3 (accuracy-critical). PV: fp16 1-mma (P and V single planes).
// 3-stage KV pipeline, single barrier per tile.
#define BQ 128
#define BK 64
#define FP 136
#define QELE (BQ*FP)
#define KELE (BK*FP)
#define QAREA (2*QELE)
#define STGKV (3*KELE)
#define FLASH_SMEM ((QAREA + 3*STGKV) * 2)   // 226304 bytes

__global__ __launch_bounds__(256) void flash_kernel(
    const bf16* __restrict__ Qh, const bf16* __restrict__ Ql,
    const bf16* __restrict__ Kh, const bf16* __restrict__ Kl,
    const __half* __restrict__ Vh,
    __half* __restrict__ ctxh)
{
    extern __shared__ bf16 smf[];
    const int tid = threadIdx.x, lane = tid & 31, wid = tid >> 5;
    const int qb = gridDim.x - 1 - blockIdx.x;
    const int bh = blockIdx.y;
    const int b = bh >> 4, h = bh & 15, kv = h >> 1;
    const int q0 = qb * BQ;
    const uint32_t sbase = (uint32_t)__cvta_generic_to_shared(smf);

    const bf16* Qhg = Qh + ((size_t)(b*HQ  + h )*TT + q0)*HD;
    const bf16* Qlg = Ql + ((size_t)(b*HQ  + h )*TT + q0)*HD;
    const bf16* Khg = Kh + ((size_t)(b*HKV + kv)*TT)*HD;
    const bf16* Klg = Kl + ((size_t)(b*HKV + kv)*TT)*HD;
    const __half* Vhg = Vh + (size_t)b*TT*(HKV*HD) + kv*HD;

#pragma unroll
    for (int i = 0; i < 8; i++) {
        int c = tid + i*256;
        int row = c >> 4, col = (c & 15) * 8;
        cp_async16(sbase + (uint32_t)((row*FP + col) * 2),        Qhg + (size_t)row*HD + col);
        cp_async16(sbase + (uint32_t)((QELE + row*FP + col) * 2), Qlg + (size_t)row*HD + col);
    }

#define ISSUEKV(kt, stage) do {                                                     \
    const int k0_ = (kt) * BK;                                                      \
    const uint32_t kb_ = sbase + (uint32_t)((QAREA + (stage)*STGKV) * 2);           \
    _Pragma("unroll")                                                               \
    for (int i_ = 0; i_ < 4; i_++) {                                                \
        int c_ = tid + i_*256;                                                      \
        int row_ = c_ >> 4, col_ = (c_ & 15) * 8;                                   \
        uint32_t so_ = (uint32_t)((row_*FP + col_) * 2);                            \
        cp_async16(kb_ + so_,            Khg + (size_t)(k0_+row_)*HD + col_);       \
        cp_async16(kb_ + KELE*2 + so_,   Klg + (size_t)(k0_+row_)*HD + col_);       \
        cp_async16(kb_ + 2*KELE*2 + so_, Vhg + (size_t)(k0_+row_)*(HKV*HD) + col_); \
    }                                                                               \
} while (0)

    const int nkt = 2*qb + 2;
    ISSUEKV(0, 0);
    cp_commit();
    ISSUEKV(1, 1);
    cp_commit();

    const int r   = lane & 7, blkid = lane >> 3;
    const int a_row = ((blkid & 1) << 3) + r;
    const int a_col = (blkid >> 1) << 3;
    const int b_row = ((blkid >> 1) << 3) + r;
    const int b_col = (blkid & 1) << 3;
    const int gr = lane >> 2;

    float oacc[16][4];
#pragma unroll
    for (int i = 0; i < 16; i++)
#pragma unroll
        for (int j = 0; j < 4; j++) oacc[i][j] = 0.f;
    float m0 = -1e30f, m1 = -1e30f, l0 = 0.f, l1 = 0.f;

    const int row0g = q0 + wid*16 + gr;
    const int row1g = row0g + 8;
    const int rowmin = q0 + wid*16;

    int stg = 0;
    for (int kt = 0; kt < nkt; kt++) {
        if (kt + 1 < nkt) {
            asm volatile("cp.async.wait_group 1;\n" ::: "memory");
        } else {
            asm volatile("cp.async.wait_group 0;\n" ::: "memory");
        }
        __syncthreads();
        if (kt + 2 < nkt) {
            int s2 = stg + 2; if (s2 >= 3) s2 -= 3;
            ISSUEKV(kt + 2, s2);
            cp_commit();
        }

        const int k0 = kt * BK;
        const uint32_t kb_s = sbase + (uint32_t)((QAREA + stg*STGKV) * 2);

        float sacc[8][4];
#pragma unroll
        for (int i = 0; i < 8; i++)
#pragma unroll
            for (int j = 0; j < 4; j++) sacc[i][j] = 0.f;

#pragma unroll
        for (int ks = 0; ks < 8; ks++) {
            uint32_t qa = sbase + (uint32_t)(((wid*16 + a_row)*FP + ks*16 + a_col) * 2);
            uint32_t qh[4], ql[4];
            ldsm4(qh, qa);
            ldsm4(ql, qa + QELE*2);
#pragma unroll
            for (int np = 0; np < 4; np++) {
                uint32_t ka = kb_s + (uint32_t)(((np*16 + b_row)*FP + ks*16 + b_col) * 2);
                uint32_t kh[4], kl[4];
                ldsm4(kh, ka);
                ldsm4(kl, ka + KELE*2);
                mma16816(sacc[2*np],   qh, &kh[0]);
                mma16816(sacc[2*np+1], qh, &kh[2]);
                mma16816(sacc[2*np],   qh, &kl[0]);
                mma16816(sacc[2*np+1], qh, &kl[2]);
                mma16816(sacc[2*np],   ql, &kh[0]);
                mma16816(sacc[2*np+1], ql, &kh[2]);
            }
        }

        // ---- causal mask (only near diagonal) + online softmax ----
        float mx0 = -1e30f, mx1 = -1e30f;
        if (k0 + 63 > rowmin) {
#pragma unroll
            for (int nt = 0; nt < 8; nt++) {
                int cg = k0 + nt*8 + (lane & 3)*2;
                if (cg     > row0g) sacc[nt][0] = -1e30f;
                if (cg + 1 > row0g) sacc[nt][1] = -1e30f;
                if (cg     > row1g) sacc[nt][2] = -1e30f;
                if (cg + 1 > row1g) sacc[nt][3] = -1e30f;
                mx0 = fmaxf(mx0, fmaxf(sacc[nt][0], sacc[nt][1]));
                mx1 = fmaxf(mx1, fmaxf(sacc[nt][2], sacc[nt][3]));
            }
        } else {
#pragma unroll
            for (int nt = 0; nt < 8; nt++) {
                mx0 = fmaxf(mx0, fmaxf(sacc[nt][0], sacc[nt][1]));
                mx1 = fmaxf(mx1, fmaxf(sacc[nt][2], sacc[nt][3]));
            }
        }
        mx0 = fmaxf(mx0, __shfl_xor_sync(0xffffffffu, mx0, 1));
        mx0 = fmaxf(mx0, __shfl_xor_sync(0xffffffffu, mx0, 2));
        mx1 = fmaxf(mx1, __shfl_xor_sync(0xffffffffu, mx1, 1));
        mx1 = fmaxf(mx1, __shfl_xor_sync(0xffffffffu, mx1, 2));

        float mn0 = fmaxf(m0, mx0), mn1 = fmaxf(m1, mx1);
        float sc0 = exp2f(m0 - mn0), sc1 = exp2f(m1 - mn1);
        m0 = mn0; m1 = mn1;

        float s0 = 0.f, s1 = 0.f;
#pragma unroll
        for (int nt = 0; nt < 8; nt++) {
            sacc[nt][0] = exp2f(sacc[nt][0] - m0);
            sacc[nt][1] = exp2f(sacc[nt][1] - m0);
            sacc[nt][2] = exp2f(sacc[nt][2] - m1);
            sacc[nt][3] = exp2f(sacc[nt][3] - m1);
            s0 += sacc[nt][0] + sacc[nt][1];
            s1 += sacc[nt][2] + sacc[nt][3];
        }
        s0 += __shfl_xor_sync(0xffffffffu, s0, 1);
        s0 += __shfl_xor_sync(0xffffffffu, s0, 2);
        s1 += __shfl_xor_sync(0xffffffffu, s1, 1);
        s1 += __shfl_xor_sync(0xffffffffu, s1, 2);
        l0 = l0*sc0 + s0;
        l1 = l1*sc1 + s1;

#pragma unroll
        for (int i = 0; i < 16; i++) {
            oacc[i][0] *= sc0; oacc[i][1] *= sc0;
            oacc[i][2] *= sc1; oacc[i][3] *= sc1;
        }

        // ---- O += P V (fp16 1-mma: P and V single planes) ----
        const int vrow = (lane & 7) + ((lane >> 3) & 1)*8;
        const int vcolb = ((lane >> 4) << 3);
#pragma unroll
        for (int kp = 0; kp < 4; kp++) {
            uint32_t ph[4];
#pragma unroll
            for (int half = 0; half < 2; half++) {
                ph[2*half]   = packh(sacc[2*kp+half][0], sacc[2*kp+half][1]);
                ph[2*half+1] = packh(sacc[2*kp+half][2], sacc[2*kp+half][3]);
            }
#pragma unroll
            for (int np = 0; np < 8; np++) {
                uint32_t va = kb_s + (uint32_t)((2*KELE + (kp*16 + vrow)*FP + np*16 + vcolb) * 2);
                uint32_t vh[4];
                ldsm4t(vh, va);
                mma16816h(oacc[2*np],   ph, &vh[0]);
                mma16816h(oacc[2*np+1], ph, &vh[2]);
            }
        }
        if (++stg == 3) stg = 0;
    }
#undef ISSUEKV

    // ---- epilogue: O /= l, write ctx fp16 single plane ----
    const float il0 = 1.f / l0, il1 = 1.f / l1;
    const size_t tok0 = (size_t)(b*TT + q0 + wid*16 + gr);
#pragma unroll
    for (int nt = 0; nt < 16; nt++) {
        int col = h*HD + nt*8 + (lane & 3)*2;
        *(uint32_t*)&ctxh[tok0*(HQ*HD) + col]     = packh(oacc[nt][0]*il0, oacc[nt][1]*il0);
        *(uint32_t*)&ctxh[(tok0+8)*(HQ*HD) + col] = packh(oacc[nt][2]*il1, oacc[nt][3]*il1);
    }
}

// ---------------- launch ------------------------------------------------------
extern "C" void kernel_launch(void* const* d_in, const int* in_sizes, int n_in,
                              void* d_out, int out_size)
{
    const float* x       = (const float*)d_in[0];
    const float* cosT    = (const float*)d_in[2];
    const float* sinT    = (const float*)d_in[3];
    const float* Wq      = (const float*)d_in[4];
    const float* Wk      = (const float*)d_in[5];
    const float* Wv      = (const float*)d_in[6];
    const float* Wo      = (const float*)d_in[7];
    const float* q_scale = (const float*)d_in[8];
    const float* k_scale = (const float*)d_in[9];
    float* out = (float*)d_out;

    __half *xh,*Wqh,*Wkh,*Wvh,*Woh,*ctxh,*Vh;
    bf16 *Qh,*Ql,*Kh,*Kl;
    cudaGetSymbolAddress((void**)&xh,   g_xh);
    cudaGetSymbolAddress((void**)&Wqh,  g_Wqh);
    cudaGetSymbolAddress((void**)&Wkh,  g_Wkh);
    cudaGetSymbolAddress((void**)&Wvh,  g_Wvh);
    cudaGetSymbolAddress((void**)&Woh,  g_Woh);
    cudaGetSymbolAddress((void**)&Qh,   g_Qh);   cudaGetSymbolAddress((void**)&Ql,   g_Ql);
    cudaGetSymbolAddress((void**)&Kh,   g_Kh);   cudaGetSymbolAddress((void**)&Kl,   g_Kl);
    cudaGetSymbolAddress((void**)&Vh,   g_Vh);
    cudaGetSymbolAddress((void**)&ctxh, g_ctxh);

    static bool attr_set = false;
    if (!attr_set) {
        cudaFuncSetAttribute(gemm_qkv,     cudaFuncAttributeMaxDynamicSharedMemorySize, GSMEM1);
        cudaFuncSetAttribute(gemm_o,       cudaFuncAttributeMaxDynamicSharedMemorySize, GSMEM1);
        cudaFuncSetAttribute(flash_kernel, cudaFuncAttributeMaxDynamicSharedMemorySize, FLASH_SMEM);
        attr_set = true;
    }

    // 0: all operand conversions in one launch
    split_all_kernel<<<20480, 256>>>(
        (const float4*)x, (const float4*)Wq, (const float4*)Wk,
        (const float4*)Wv, (const float4*)Wo,
        xh, Wqh, Wkh, Wvh, Woh);

    // 1: merged QKV projection (fp16 1-mma, BK=64) + fused norm/rope/split
    gemm_qkv<<<dim3(32, MROWS/128), 256, GSMEM1>>>(
        xh, Wqh, Wkh, Wvh,
        Qh, Ql, Kh, Kl, Vh, q_scale, k_scale, cosT, sinT);

    // 2: fused flash attention (QK bf16x3, PV fp16 1-mma)
    flash_kernel<<<dim3(TT/BQ, BB*HQ), 256, FLASH_SMEM>>>(Qh, Ql, Kh, Kl, Vh, ctxh);

    // 3: output projection (fp16 1-mma, BK=64, descale)
    gemm_o<<<dim3(DD/128, MROWS/128), 256, GSMEM1>>>(ctxh, Woh, out, DD);
}